// round 6
// baseline (speedup 1.0000x reference)
#include <cuda_runtime.h>
#include <cuda_bf16.h>
#include <cstdint>

// ---------------------------------------------------------------------------
// CausalSelfAttention on GB300 (sm_103 family target — no 'a' features).
// All matmuls via mma.sync.m16n8k16 bf16 with hi/lo error splitting.
// Stage 1: qkv GEMM, epilogue writes per-head bf16 hi/lo Q(scaled)/K/V
// Stage 2: causal flash attention, bf16 tiles via 2-stage cp.async ring
// Stage 3: out = y @ w_proj + b_proj (fp32 out)
// ---------------------------------------------------------------------------

#define B_ 4
#define T_ 2048
#define C_ 768
#define H_ 12
#define ROWS_ 8192
#define QKVC_ 2304
#define PHT_ (B_ * H_ * T_ * 64)   // per-head tensor elems

// ---------------- scratch ---------------------------------------------------
__device__ __align__(256) __nv_bfloat16  g_xhi[ROWS_ * C_];
__device__ __align__(256) __nv_bfloat16  g_xlo[ROWS_ * C_];
__device__ __align__(256) __nv_bfloat16  g_yhi[ROWS_ * C_];
__device__ __align__(256) __nv_bfloat16  g_ylo[ROWS_ * C_];
__device__ __align__(256) __nv_bfloat16  g_qhi[PHT_], g_qlo[PHT_];
__device__ __align__(256) __nv_bfloat16  g_khi[PHT_], g_klo[PHT_];
__device__ __align__(256) __nv_bfloat16  g_vhi[PHT_], g_vlo[PHT_];
__device__ __align__(256) __nv_bfloat16  g_wa_hi[QKVC_ * C_];
__device__ __align__(256) __nv_bfloat16  g_wa_lo[QKVC_ * C_];
__device__ __align__(256) __nv_bfloat16  g_wp_hi[C_ * C_];
__device__ __align__(256) __nv_bfloat16  g_wp_lo[C_ * C_];

// ---------------- helpers ---------------------------------------------------
__device__ __forceinline__ uint32_t smem_u32(const void* p) {
    uint32_t a;
    asm("{ .reg .u64 t; cvta.to.shared.u64 t, %1; cvt.u32.u64 %0, t; }"
        : "=r"(a) : "l"(p));
    return a;
}
#define SWZ(x) ((x) ^ (((x) >> 3) & 0x70))

__device__ __forceinline__ void cpa16(uint32_t dst, const void* src) {
    asm volatile("cp.async.cg.shared.global [%0], [%1], 16;" :: "r"(dst), "l"(src));
}
__device__ __forceinline__ void cpa_commit() { asm volatile("cp.async.commit_group;"); }

__device__ __forceinline__ void ldsm_x4(uint32_t& r0, uint32_t& r1, uint32_t& r2,
                                        uint32_t& r3, uint32_t addr) {
    asm volatile("ldmatrix.sync.aligned.m8n8.x4.shared.b16 {%0,%1,%2,%3}, [%4];"
                 : "=r"(r0), "=r"(r1), "=r"(r2), "=r"(r3) : "r"(addr));
}
__device__ __forceinline__ void ldsm_x2(uint32_t& r0, uint32_t& r1, uint32_t addr) {
    asm volatile("ldmatrix.sync.aligned.m8n8.x2.shared.b16 {%0,%1}, [%2];"
                 : "=r"(r0), "=r"(r1) : "r"(addr));
}
__device__ __forceinline__ void ldsm_x2t(uint32_t& r0, uint32_t& r1, uint32_t addr) {
    asm volatile("ldmatrix.sync.aligned.m8n8.x2.trans.shared.b16 {%0,%1}, [%2];"
                 : "=r"(r0), "=r"(r1) : "r"(addr));
}
__device__ __forceinline__ void mma_bf16(float* c, const uint32_t* a,
                                         uint32_t b0, uint32_t b1) {
    asm volatile("mma.sync.aligned.m16n8k16.row.col.f32.bf16.bf16.f32 "
                 "{%0,%1,%2,%3}, {%4,%5,%6,%7}, {%8,%9}, {%0,%1,%2,%3};"
                 : "+f"(c[0]), "+f"(c[1]), "+f"(c[2]), "+f"(c[3])
                 : "r"(a[0]), "r"(a[1]), "r"(a[2]), "r"(a[3]), "r"(b0), "r"(b1));
}

__device__ __forceinline__ void split2(float a, float b, uint32_t& h, uint32_t& l) {
    __nv_bfloat16 ha = __float2bfloat16(a), hb = __float2bfloat16(b);
    __nv_bfloat16 la = __float2bfloat16(a - __bfloat162float(ha));
    __nv_bfloat16 lb = __float2bfloat16(b - __bfloat162float(hb));
    __nv_bfloat162 hh(ha, hb), ll(la, lb);
    h = *(uint32_t*)&hh;
    l = *(uint32_t*)&ll;
}

// ---------------------------------------------------------------------------
// Conversion kernels
// ---------------------------------------------------------------------------
__global__ void split_rows_kernel(const float* __restrict__ in,
                                  __nv_bfloat16* __restrict__ hi,
                                  __nv_bfloat16* __restrict__ lo, int n4)
{
    int i = blockIdx.x * blockDim.x + threadIdx.x;
    if (i >= n4) return;
    float4 v = ((const float4*)in)[i];
    uint32_t h0, l0, h1, l1;
    split2(v.x, v.y, h0, l0);
    split2(v.z, v.w, h1, l1);
    uint32_t* hp = (uint32_t*)(hi + 4 * (size_t)i);
    uint32_t* lp = (uint32_t*)(lo + 4 * (size_t)i);
    hp[0] = h0; hp[1] = h1;
    lp[0] = l0; lp[1] = l1;
}

__global__ void split_transpose_kernel(const float* __restrict__ w,
                                       __nv_bfloat16* __restrict__ hiT,
                                       __nv_bfloat16* __restrict__ loT, int K, int N)
{
    __shared__ float t[32][33];
    const int n0 = blockIdx.x * 32, k0 = blockIdx.y * 32;
    const int tx = threadIdx.x, ty = threadIdx.y;
#pragma unroll
    for (int j = 0; j < 4; j++)
        t[ty + j * 8][tx] = w[(size_t)(k0 + ty + j * 8) * N + n0 + tx];
    __syncthreads();
#pragma unroll
    for (int j = 0; j < 4; j++) {
        const int n = ty + j * 8;
        float v = t[tx][n];
        __nv_bfloat16 h = __float2bfloat16(v);
        __nv_bfloat16 l = __float2bfloat16(v - __bfloat162float(h));
        hiT[(size_t)(n0 + n) * K + k0 + tx] = h;
        loT[(size_t)(n0 + n) * K + k0 + tx] = l;
    }
}

// ---------------------------------------------------------------------------
// GEMM: 128x128 tile, BK=64, 8 warps, 3-stage cp.async, SW128 smem.
// MODE 0: fp32 out + bias.  MODE 1: qkv split epilogue -> per-head bf16 hi/lo.
// ---------------------------------------------------------------------------
#define G_STAGE 65536
#define G_SMEM  (3 * G_STAGE)

__device__ __forceinline__ void gemm_load_chunk(
    uint32_t sb, const __nv_bfloat16* Ahi, const __nv_bfloat16* Alo,
    const __nv_bfloat16* Bhi, const __nv_bfloat16* Blo,
    int rowBase, int colBase, int K, int kc, int stage, int tid)
{
    const uint32_t base = sb + stage * G_STAGE;
    const int k0 = kc * 64;
    const __nv_bfloat16* srcs[4] = { Ahi, Alo, Bhi, Blo };
#pragma unroll
    for (int t = 0; t < 4; t++) {
        const __nv_bfloat16* src = srcs[t];
        const int gb = (t < 2) ? rowBase : colBase;
        const uint32_t soff = base + t * 16384;
#pragma unroll
        for (int i = 0; i < 4; i++) {
            const int seg = tid + i * 256;
            const int r = seg >> 3, g = seg & 7;
            cpa16(soff + SWZ(r * 128 + g * 16),
                  src + (size_t)(gb + r) * K + k0 + g * 8);
        }
    }
    cpa_commit();
}

template <int MODE>
__global__ __launch_bounds__(256, 1)
void gemm_mma_kernel(const __nv_bfloat16* __restrict__ Ahi, const __nv_bfloat16* __restrict__ Alo,
                     const __nv_bfloat16* __restrict__ Bhi, const __nv_bfloat16* __restrict__ Blo,
                     const float* __restrict__ bias, float* __restrict__ Cm,
                     __nv_bfloat16* __restrict__ qh_, __nv_bfloat16* __restrict__ ql_,
                     __nv_bfloat16* __restrict__ kh_, __nv_bfloat16* __restrict__ kl_,
                     __nv_bfloat16* __restrict__ vh_, __nv_bfloat16* __restrict__ vl_,
                     int M, int N, int K)
{
    extern __shared__ char smem[];
    const uint32_t sb = smem_u32(smem);
    const int tid = threadIdx.x, wid = tid >> 5, lane = tid & 31;
    const int wm = wid >> 2, wn = wid & 3;
    const int rowBase = blockIdx.y * 128, colBase = blockIdx.x * 128;
    const int NK = K / 64;

    float c[4][4][4];
#pragma unroll
    for (int i = 0; i < 4; i++)
#pragma unroll
        for (int j = 0; j < 4; j++)
#pragma unroll
            for (int k = 0; k < 4; k++) c[i][j][k] = 0.f;

    gemm_load_chunk(sb, Ahi, Alo, Bhi, Blo, rowBase, colBase, K, 0, 0, tid);
    gemm_load_chunk(sb, Ahi, Alo, Bhi, Blo, rowBase, colBase, K, 1, 1, tid);
    gemm_load_chunk(sb, Ahi, Alo, Bhi, Blo, rowBase, colBase, K, 2, 2, tid);

    const int aRow = wm * 64 + (lane & 15);
    const uint32_t aSegOff = ((lane >> 4) & 1) * 16;
    const int bRowL = wn * 32 + (lane & 7);
    const uint32_t bSegOff = ((lane >> 3) & 1) * 16;

    for (int kc = 0; kc < NK; kc++) {
        asm volatile("cp.async.wait_group 2;" ::: "memory");
        __syncthreads();
        const uint32_t st = sb + (kc % 3) * G_STAGE;
#pragma unroll
        for (int ks = 0; ks < 4; ks++) {
            uint32_t bh[4][2], bl[4][2];
#pragma unroll
            for (int nj = 0; nj < 4; nj++) {
                const uint32_t boff = SWZ((uint32_t)(bRowL + nj * 8) * 128 + ks * 32 + bSegOff);
                ldsm_x2(bh[nj][0], bh[nj][1], st + 32768 + boff);
                ldsm_x2(bl[nj][0], bl[nj][1], st + 49152 + boff);
            }
#pragma unroll
            for (int mi = 0; mi < 4; mi++) {
                uint32_t ah[4], al[4];
                const uint32_t aoff = SWZ((uint32_t)(aRow + mi * 16) * 128 + ks * 32 + aSegOff);
                ldsm_x4(ah[0], ah[1], ah[2], ah[3], st + aoff);
                ldsm_x4(al[0], al[1], al[2], al[3], st + 16384 + aoff);
#pragma unroll
                for (int nj = 0; nj < 4; nj++) {
                    mma_bf16(c[mi][nj], ah, bh[nj][0], bh[nj][1]);
                    mma_bf16(c[mi][nj], al, bh[nj][0], bh[nj][1]);
                    mma_bf16(c[mi][nj], ah, bl[nj][0], bl[nj][1]);
                }
            }
        }
        __syncthreads();
        if (kc + 3 < NK)
            gemm_load_chunk(sb, Ahi, Alo, Bhi, Blo, rowBase, colBase, K,
                            kc + 3, kc % 3, tid);
    }

    const int g = lane >> 2, q2 = (lane & 3) * 2;
#pragma unroll
    for (int mi = 0; mi < 4; mi++) {
        const int row0 = rowBase + wm * 64 + mi * 16 + g;
#pragma unroll
        for (int nj = 0; nj < 4; nj++) {
            const int col = colBase + wn * 32 + nj * 8 + q2;
            const float bx = bias[col], by = bias[col + 1];
            if (MODE == 0) {
                float2 v0 = make_float2(c[mi][nj][0] + bx, c[mi][nj][1] + by);
                float2 v1 = make_float2(c[mi][nj][2] + bx, c[mi][nj][3] + by);
                *(float2*)(Cm + (size_t)row0 * N + col) = v0;
                *(float2*)(Cm + (size_t)(row0 + 8) * N + col) = v1;
            } else {
                const int sec = col / 768;
                const int cid = col - sec * 768;
                const int hh = cid >> 6, d = cid & 63;
                const float sc = (sec == 0) ? 0.125f : 1.0f;
                const int bb = row0 >> 11, t = row0 & 2047;
                const size_t off0 = (((size_t)bb * H_ + hh) * T_ + t) * 64 + d;
                uint32_t h0, l0, h1, l1;
                split2((c[mi][nj][0] + bx) * sc, (c[mi][nj][1] + by) * sc, h0, l0);
                split2((c[mi][nj][2] + bx) * sc, (c[mi][nj][3] + by) * sc, h1, l1);
                __nv_bfloat16 *dh, *dl;
                if (sec == 0)      { dh = qh_; dl = ql_; }
                else if (sec == 1) { dh = kh_; dl = kl_; }
                else               { dh = vh_; dl = vl_; }
                *(uint32_t*)(dh + off0) = h0;
                *(uint32_t*)(dl + off0) = l0;
                *(uint32_t*)(dh + off0 + 512) = h1;   // row0+8 -> +8*64
                *(uint32_t*)(dl + off0 + 512) = l1;
            }
        }
    }
}

// ---------------------------------------------------------------------------
// Flash attention v2: bf16 per-head inputs, 2-stage cp.async ping-pong.
// CTA: 128 q-rows, 8 warps (16 q-rows each), k-tile 64.
// smem: Qhi|Qlo (32K) + 2 x (Khi|Klo|Vhi|Vlo 32K) = 96K.
// ---------------------------------------------------------------------------
#define SM_QHI 0
#define SM_QLO 16384
#define SM_ST  32768      // stage base; stride 32768
#define A_SMEM 98304

__device__ __forceinline__ void attn_load_kv(
    uint32_t sb, const __nv_bfloat16* khi, const __nv_bfloat16* klo,
    const __nv_bfloat16* vhi, const __nv_bfloat16* vlo,
    size_t hb, int kBase, int stage, int tid)
{
    const uint32_t st = sb + SM_ST + stage * 32768;
#pragma unroll
    for (int i = 0; i < 2; i++) {
        const int seg = tid + i * 256;
        const int r = seg >> 3, gsg = seg & 7;
        const size_t goff = hb + (size_t)(kBase + r) * 64 + gsg * 8;
        const uint32_t soff = SWZ((uint32_t)r * 128 + gsg * 16);
        cpa16(st + soff,         khi + goff);
        cpa16(st + 8192 + soff,  klo + goff);
        cpa16(st + 16384 + soff, vhi + goff);
        cpa16(st + 24576 + soff, vlo + goff);
    }
    cpa_commit();
}

__global__ __launch_bounds__(256, 1)
void attn_mma_kernel(const __nv_bfloat16* __restrict__ qhi, const __nv_bfloat16* __restrict__ qlo,
                     const __nv_bfloat16* __restrict__ khi, const __nv_bfloat16* __restrict__ klo,
                     const __nv_bfloat16* __restrict__ vhi, const __nv_bfloat16* __restrict__ vlo,
                     __nv_bfloat16* __restrict__ yhi, __nv_bfloat16* __restrict__ ylo)
{
    extern __shared__ char smem[];
    const uint32_t sb = smem_u32(smem);
    const int qt = (int)gridDim.x - 1 - (int)blockIdx.x;
    const int bh = blockIdx.y;
    const int b = bh / H_, h = bh % H_;
    const int tid = threadIdx.x, wid = tid >> 5, lane = tid & 31;
    const int qBase = qt * 128;
    const size_t hb = (size_t)bh * T_ * 64;

    // Q tile loads (bf16, swizzled)
#pragma unroll
    for (int i = 0; i < 4; i++) {
        const int seg = tid + i * 256;
        const int r = seg >> 3, gsg = seg & 7;
        const size_t goff = hb + (size_t)(qBase + r) * 64 + gsg * 8;
        const uint32_t soff = SWZ((uint32_t)r * 128 + gsg * 16);
        cpa16(sb + SM_QHI + soff, qhi + goff);
        cpa16(sb + SM_QLO + soff, qlo + goff);
    }
    cpa_commit();
    attn_load_kv(sb, khi, klo, vhi, vlo, hb, 0, 0, tid);
    asm volatile("cp.async.wait_group 0;" ::: "memory");
    __syncthreads();

    // Q fragments (register resident)
    uint32_t qh[4][4], ql[4][4];
    {
        const int aRow = wid * 16 + (lane & 15);
        const uint32_t aSeg = ((lane >> 4) & 1) * 16;
#pragma unroll
        for (int ks = 0; ks < 4; ks++) {
            const uint32_t aoff = SWZ((uint32_t)aRow * 128 + ks * 32 + aSeg);
            ldsm_x4(qh[ks][0], qh[ks][1], qh[ks][2], qh[ks][3], sb + SM_QHI + aoff);
            ldsm_x4(ql[ks][0], ql[ks][1], ql[ks][2], ql[ks][3], sb + SM_QLO + aoff);
        }
    }

    float o[8][4];
#pragma unroll
    for (int d = 0; d < 8; d++)
#pragma unroll
        for (int k = 0; k < 4; k++) o[d][k] = 0.f;
    float m0 = -1e30f, m1 = -1e30f, l0s = 0.f, l1s = 0.f;

    const int g = lane >> 2, q2 = (lane & 3) * 2;
    const int row0 = qBase + wid * 16 + g;
    const int rowWarpMax = qBase + wid * 16 + 15;
    const int ktMax = 2 * qt + 1;

    const int bRowL = lane & 7;
    const uint32_t bSeg = ((lane >> 3) & 1) * 16;
    const int vRowL = lane & 15;

    for (int kt = 0; kt <= ktMax; kt++) {
        const int kBase = kt * 64;
        if (kt < ktMax) {
            attn_load_kv(sb, khi, klo, vhi, vlo, hb, kBase + 64, (kt + 1) & 1, tid);
            asm volatile("cp.async.wait_group 1;" ::: "memory");
        } else {
            asm volatile("cp.async.wait_group 0;" ::: "memory");
        }
        __syncthreads();

        if (kBase <= rowWarpMax) {
            const uint32_t st = sb + SM_ST + (kt & 1) * 32768;

            // ---- S = Q K^T ----
            float sc[8][4];
#pragma unroll
            for (int nj = 0; nj < 8; nj++)
#pragma unroll
                for (int k = 0; k < 4; k++) sc[nj][k] = 0.f;
#pragma unroll
            for (int nj = 0; nj < 8; nj++) {
#pragma unroll
                for (int ks = 0; ks < 4; ks++) {
                    const uint32_t boff = SWZ((uint32_t)(nj * 8 + bRowL) * 128 + ks * 32 + bSeg);
                    uint32_t k0, k1;
                    ldsm_x2(k0, k1, st + boff);
                    mma_bf16(sc[nj], qh[ks], k0, k1);
                    mma_bf16(sc[nj], ql[ks], k0, k1);
                    ldsm_x2(k0, k1, st + 8192 + boff);
                    mma_bf16(sc[nj], qh[ks], k0, k1);
                }
            }

            // ---- causal mask ----
            if (kBase + 63 > qBase + wid * 16) {
#pragma unroll
                for (int nj = 0; nj < 8; nj++) {
                    const int col = kBase + nj * 8 + q2;
                    if (col > row0)         sc[nj][0] = -1e30f;
                    if (col + 1 > row0)     sc[nj][1] = -1e30f;
                    if (col > row0 + 8)     sc[nj][2] = -1e30f;
                    if (col + 1 > row0 + 8) sc[nj][3] = -1e30f;
                }
            }

            // ---- online softmax ----
            float mx0 = -1e30f, mx1 = -1e30f;
#pragma unroll
            for (int nj = 0; nj < 8; nj++) {
                mx0 = fmaxf(mx0, fmaxf(sc[nj][0], sc[nj][1]));
                mx1 = fmaxf(mx1, fmaxf(sc[nj][2], sc[nj][3]));
            }
            mx0 = fmaxf(mx0, __shfl_xor_sync(0xffffffffu, mx0, 1));
            mx0 = fmaxf(mx0, __shfl_xor_sync(0xffffffffu, mx0, 2));
            mx1 = fmaxf(mx1, __shfl_xor_sync(0xffffffffu, mx1, 1));
            mx1 = fmaxf(mx1, __shfl_xor_sync(0xffffffffu, mx1, 2));
            const float mn0 = fmaxf(m0, mx0), mn1 = fmaxf(m1, mx1);
            const float al0 = __expf(m0 - mn0), al1 = __expf(m1 - mn1);
            m0 = mn0; m1 = mn1;
            float s0 = 0.f, s1 = 0.f;
#pragma unroll
            for (int nj = 0; nj < 8; nj++) {
                sc[nj][0] = __expf(sc[nj][0] - mn0);
                sc[nj][1] = __expf(sc[nj][1] - mn0);
                sc[nj][2] = __expf(sc[nj][2] - mn1);
                sc[nj][3] = __expf(sc[nj][3] - mn1);
                s0 += sc[nj][0] + sc[nj][1];
                s1 += sc[nj][2] + sc[nj][3];
            }
            s0 += __shfl_xor_sync(0xffffffffu, s0, 1);
            s0 += __shfl_xor_sync(0xffffffffu, s0, 2);
            s1 += __shfl_xor_sync(0xffffffffu, s1, 1);
            s1 += __shfl_xor_sync(0xffffffffu, s1, 2);
            l0s = l0s * al0 + s0;
            l1s = l1s * al1 + s1;

            // ---- P fragments (register remap, split) ----
            uint32_t ph[4][4], pl[4][4];
#pragma unroll
            for (int ks = 0; ks < 4; ks++) {
                split2(sc[2 * ks][0],     sc[2 * ks][1],     ph[ks][0], pl[ks][0]);
                split2(sc[2 * ks][2],     sc[2 * ks][3],     ph[ks][1], pl[ks][1]);
                split2(sc[2 * ks + 1][0], sc[2 * ks + 1][1], ph[ks][2], pl[ks][2]);
                split2(sc[2 * ks + 1][2], sc[2 * ks + 1][3], ph[ks][3], pl[ks][3]);
            }

            // ---- rescale O, accumulate P V ----
#pragma unroll
            for (int dj = 0; dj < 8; dj++) {
                o[dj][0] *= al0; o[dj][1] *= al0;
                o[dj][2] *= al1; o[dj][3] *= al1;
#pragma unroll
                for (int ks = 0; ks < 4; ks++) {
                    const uint32_t voff = SWZ((uint32_t)(ks * 16 + vRowL) * 128 + dj * 16);
                    uint32_t v0, v1;
                    ldsm_x2t(v0, v1, st + 16384 + voff);
                    mma_bf16(o[dj], ph[ks], v0, v1);
                    mma_bf16(o[dj], pl[ks], v0, v1);
                    ldsm_x2t(v0, v1, st + 24576 + voff);
                    mma_bf16(o[dj], ph[ks], v0, v1);
                }
            }
        }
        __syncthreads();
    }

    // ---- epilogue: O/l -> bf16 hi/lo (row-major [b*T+t][C] for stage 3) ----
    const float inv0 = 1.0f / l0s, inv1 = 1.0f / l1s;
#pragma unroll
    for (int dj = 0; dj < 8; dj++) {
        uint32_t h0, l0, h1, l1;
        split2(o[dj][0] * inv0, o[dj][1] * inv0, h0, l0);
        split2(o[dj][2] * inv1, o[dj][3] * inv1, h1, l1);
        const size_t r0 = ((size_t)b * T_ + row0) * C_ + h * 64 + dj * 8 + q2;
        const size_t r1 = r0 + 8 * C_;
        *(uint32_t*)(yhi + r0) = h0;
        *(uint32_t*)(ylo + r0) = l0;
        *(uint32_t*)(yhi + r1) = h1;
        *(uint32_t*)(ylo + r1) = l1;
    }
}

// ---------------------------------------------------------------------------
extern "C" void kernel_launch(void* const* d_in, const int* in_sizes, int n_in,
                              void* d_out, int out_size)
{
    const float* x      = (const float*)d_in[0];
    const float* w_attn = (const float*)d_in[1];
    const float* b_attn = (const float*)d_in[2];
    const float* w_proj = (const float*)d_in[3];
    const float* b_proj = (const float*)d_in[4];
    float* out = (float*)d_out;

    __nv_bfloat16 *xhi, *xlo, *yhi, *ylo, *wah, *wal, *wph, *wpl;
    __nv_bfloat16 *qh, *ql, *kh, *kl, *vh, *vl;
    cudaGetSymbolAddress((void**)&xhi, g_xhi);
    cudaGetSymbolAddress((void**)&xlo, g_xlo);
    cudaGetSymbolAddress((void**)&yhi, g_yhi);
    cudaGetSymbolAddress((void**)&ylo, g_ylo);
    cudaGetSymbolAddress((void**)&wah, g_wa_hi);
    cudaGetSymbolAddress((void**)&wal, g_wa_lo);
    cudaGetSymbolAddress((void**)&wph, g_wp_hi);
    cudaGetSymbolAddress((void**)&wpl, g_wp_lo);
    cudaGetSymbolAddress((void**)&qh, g_qhi);
    cudaGetSymbolAddress((void**)&ql, g_qlo);
    cudaGetSymbolAddress((void**)&kh, g_khi);
    cudaGetSymbolAddress((void**)&kl, g_klo);
    cudaGetSymbolAddress((void**)&vh, g_vhi);
    cudaGetSymbolAddress((void**)&vl, g_vlo);

    cudaFuncSetAttribute(gemm_mma_kernel<0>,
                         cudaFuncAttributeMaxDynamicSharedMemorySize, G_SMEM);
    cudaFuncSetAttribute(gemm_mma_kernel<1>,
                         cudaFuncAttributeMaxDynamicSharedMemorySize, G_SMEM);
    cudaFuncSetAttribute(attn_mma_kernel,
                         cudaFuncAttributeMaxDynamicSharedMemorySize, A_SMEM);

    // conversions
    {
        int n4 = ROWS_ * C_ / 4;
        split_rows_kernel<<<(n4 + 255) / 256, 256>>>(x, xhi, xlo, n4);
        dim3 bt(32, 8);
        split_transpose_kernel<<<dim3(QKVC_ / 32, C_ / 32), bt>>>(w_attn, wah, wal, C_, QKVC_);
        split_transpose_kernel<<<dim3(C_ / 32,    C_ / 32), bt>>>(w_proj, wph, wpl, C_, C_);
    }
    // Stage 1: qkv GEMM, split epilogue -> per-head Q/K/V bf16 hi/lo
    {
        dim3 grid(QKVC_ / 128, ROWS_ / 128);
        gemm_mma_kernel<1><<<grid, 256, G_SMEM>>>(xhi, xlo, wah, wal, b_attn,
                                                  nullptr, qh, ql, kh, kl, vh, vl,
                                                  ROWS_, QKVC_, C_);
    }
    // Stage 2: attention -> y (bf16 hi/lo)
    {
        dim3 grid(T_ / 128, B_ * H_);
        attn_mma_kernel<<<grid, 256, A_SMEM>>>(qh, ql, kh, kl, vh, vl, yhi, ylo);
    }
    // Stage 3: out = y @ w_proj + b_proj
    {
        dim3 grid(C_ / 128, ROWS_ / 128);
        gemm_mma_kernel<0><<<grid, 256, G_SMEM>>>(yhi, ylo, wph, wpl, b_proj, out,
                                                  nullptr, nullptr, nullptr, nullptr,
                                                  nullptr, nullptr, ROWS_, C_, C_);
    }
}

// round 7
// speedup vs baseline: 1.0462x; 1.0462x over previous
#include <cuda_runtime.h>
#include <cuda_bf16.h>
#include <cstdint>

// ---------------------------------------------------------------------------
// CausalSelfAttention on GB300 (sm_103 family target — no 'a' features).
// All matmuls via mma.sync.m16n8k16 bf16 with hi/lo error splitting.
// Stage 1: qkv GEMM, smem-staged epilogue -> per-head bf16 hi/lo Q*log2e/8,K,V
// Stage 2: causal flash attention (exp2 softmax), 2-stage cp.async ring
// Stage 3: out = y @ w_proj + b_proj (fp32 out)
// ---------------------------------------------------------------------------

#define B_ 4
#define T_ 2048
#define C_ 768
#define H_ 12
#define ROWS_ 8192
#define QKVC_ 2304
#define PHT_ (B_ * H_ * T_ * 64)

// ---------------- scratch ---------------------------------------------------
__device__ __align__(256) __nv_bfloat16  g_xhi[ROWS_ * C_];
__device__ __align__(256) __nv_bfloat16  g_xlo[ROWS_ * C_];
__device__ __align__(256) __nv_bfloat16  g_yhi[ROWS_ * C_];
__device__ __align__(256) __nv_bfloat16  g_ylo[ROWS_ * C_];
__device__ __align__(256) __nv_bfloat16  g_qhi[PHT_], g_qlo[PHT_];
__device__ __align__(256) __nv_bfloat16  g_khi[PHT_], g_klo[PHT_];
__device__ __align__(256) __nv_bfloat16  g_vhi[PHT_], g_vlo[PHT_];
__device__ __align__(256) __nv_bfloat16  g_wa_hi[QKVC_ * C_];
__device__ __align__(256) __nv_bfloat16  g_wa_lo[QKVC_ * C_];
__device__ __align__(256) __nv_bfloat16  g_wp_hi[C_ * C_];
__device__ __align__(256) __nv_bfloat16  g_wp_lo[C_ * C_];

// ---------------- helpers ---------------------------------------------------
__device__ __forceinline__ uint32_t smem_u32(const void* p) {
    uint32_t a;
    asm("{ .reg .u64 t; cvta.to.shared.u64 t, %1; cvt.u32.u64 %0, t; }"
        : "=r"(a) : "l"(p));
    return a;
}
#define SWZ(x) ((x) ^ (((x) >> 3) & 0x70))

__device__ __forceinline__ void cpa16(uint32_t dst, const void* src) {
    asm volatile("cp.async.cg.shared.global [%0], [%1], 16;" :: "r"(dst), "l"(src));
}
__device__ __forceinline__ void cpa_commit() { asm volatile("cp.async.commit_group;"); }

__device__ __forceinline__ void ldsm_x4(uint32_t& r0, uint32_t& r1, uint32_t& r2,
                                        uint32_t& r3, uint32_t addr) {
    asm volatile("ldmatrix.sync.aligned.m8n8.x4.shared.b16 {%0,%1,%2,%3}, [%4];"
                 : "=r"(r0), "=r"(r1), "=r"(r2), "=r"(r3) : "r"(addr));
}
__device__ __forceinline__ void ldsm_x2(uint32_t& r0, uint32_t& r1, uint32_t addr) {
    asm volatile("ldmatrix.sync.aligned.m8n8.x2.shared.b16 {%0,%1}, [%2];"
                 : "=r"(r0), "=r"(r1) : "r"(addr));
}
__device__ __forceinline__ void ldsm_x2t(uint32_t& r0, uint32_t& r1, uint32_t addr) {
    asm volatile("ldmatrix.sync.aligned.m8n8.x2.trans.shared.b16 {%0,%1}, [%2];"
                 : "=r"(r0), "=r"(r1) : "r"(addr));
}
__device__ __forceinline__ void mma_bf16(float* c, const uint32_t* a,
                                         uint32_t b0, uint32_t b1) {
    asm volatile("mma.sync.aligned.m16n8k16.row.col.f32.bf16.bf16.f32 "
                 "{%0,%1,%2,%3}, {%4,%5,%6,%7}, {%8,%9}, {%0,%1,%2,%3};"
                 : "+f"(c[0]), "+f"(c[1]), "+f"(c[2]), "+f"(c[3])
                 : "r"(a[0]), "r"(a[1]), "r"(a[2]), "r"(a[3]), "r"(b0), "r"(b1));
}

// round-nearest split (conversion kernels)
__device__ __forceinline__ void split2(float a, float b, uint32_t& h, uint32_t& l) {
    __nv_bfloat16 ha = __float2bfloat16(a), hb = __float2bfloat16(b);
    __nv_bfloat16 la = __float2bfloat16(a - __bfloat162float(ha));
    __nv_bfloat16 lb = __float2bfloat16(b - __bfloat162float(hb));
    __nv_bfloat162 hh(ha, hb), ll(la, lb);
    h = *(uint32_t*)&hh;
    l = *(uint32_t*)&ll;
}

// cheap truncation split: hi = trunc-to-bf16 via PRMT, lo = rn(residual)
__device__ __forceinline__ void split2t(float a, float b, uint32_t& h, uint32_t& l) {
    const uint32_t ua = __float_as_uint(a), ub = __float_as_uint(b);
    h = __byte_perm(ua, ub, 0x7632);                 // [b_hi16 : a_hi16]
    const float ra = a - __uint_as_float(ua & 0xffff0000u);
    const float rb = b - __uint_as_float(ub & 0xffff0000u);
    asm("cvt.rn.bf16x2.f32 %0, %1, %2;" : "=r"(l) : "f"(rb), "f"(ra));
}

// ---------------------------------------------------------------------------
// Conversion kernels
// ---------------------------------------------------------------------------
__global__ void split_rows_kernel(const float* __restrict__ in,
                                  __nv_bfloat16* __restrict__ hi,
                                  __nv_bfloat16* __restrict__ lo, int n4)
{
    int i = blockIdx.x * blockDim.x + threadIdx.x;
    if (i >= n4) return;
    float4 v = ((const float4*)in)[i];
    uint32_t h0, l0, h1, l1;
    split2(v.x, v.y, h0, l0);
    split2(v.z, v.w, h1, l1);
    uint32_t* hp = (uint32_t*)(hi + 4 * (size_t)i);
    uint32_t* lp = (uint32_t*)(lo + 4 * (size_t)i);
    hp[0] = h0; hp[1] = h1;
    lp[0] = l0; lp[1] = l1;
}

__global__ void split_transpose_kernel(const float* __restrict__ w,
                                       __nv_bfloat16* __restrict__ hiT,
                                       __nv_bfloat16* __restrict__ loT, int K, int N)
{
    __shared__ float t[32][33];
    const int n0 = blockIdx.x * 32, k0 = blockIdx.y * 32;
    const int tx = threadIdx.x, ty = threadIdx.y;
#pragma unroll
    for (int j = 0; j < 4; j++)
        t[ty + j * 8][tx] = w[(size_t)(k0 + ty + j * 8) * N + n0 + tx];
    __syncthreads();
#pragma unroll
    for (int j = 0; j < 4; j++) {
        const int n = ty + j * 8;
        float v = t[tx][n];
        __nv_bfloat16 h = __float2bfloat16(v);
        __nv_bfloat16 l = __float2bfloat16(v - __bfloat162float(h));
        hiT[(size_t)(n0 + n) * K + k0 + tx] = h;
        loT[(size_t)(n0 + n) * K + k0 + tx] = l;
    }
}

// ---------------------------------------------------------------------------
// GEMM: 128x128 tile, BK=64, 8 warps, 3-stage cp.async, SW128 smem.
// MODE 0: fp32 out + bias.
// MODE 1: qkv epilogue, smem-staged -> per-head bf16 hi/lo, Q scaled.
// ---------------------------------------------------------------------------
#define G_STAGE 65536
#define G_SMEM  (3 * G_STAGE)
#define EPI_STRIDE 136            // bf16 elems per staged row (16B aligned, bank-shifted)

__device__ __forceinline__ void gemm_load_chunk(
    uint32_t sb, const __nv_bfloat16* Ahi, const __nv_bfloat16* Alo,
    const __nv_bfloat16* Bhi, const __nv_bfloat16* Blo,
    int rowBase, int colBase, int K, int kc, int stage, int tid)
{
    const uint32_t base = sb + stage * G_STAGE;
    const int k0 = kc * 64;
    const __nv_bfloat16* srcs[4] = { Ahi, Alo, Bhi, Blo };
#pragma unroll
    for (int t = 0; t < 4; t++) {
        const __nv_bfloat16* src = srcs[t];
        const int gb = (t < 2) ? rowBase : colBase;
        const uint32_t soff = base + t * 16384;
#pragma unroll
        for (int i = 0; i < 4; i++) {
            const int seg = tid + i * 256;
            const int r = seg >> 3, g = seg & 7;
            cpa16(soff + SWZ(r * 128 + g * 16),
                  src + (size_t)(gb + r) * K + k0 + g * 8);
        }
    }
    cpa_commit();
}

template <int MODE>
__global__ __launch_bounds__(256, 1)
void gemm_mma_kernel(const __nv_bfloat16* __restrict__ Ahi, const __nv_bfloat16* __restrict__ Alo,
                     const __nv_bfloat16* __restrict__ Bhi, const __nv_bfloat16* __restrict__ Blo,
                     const float* __restrict__ bias, float* __restrict__ Cm,
                     __nv_bfloat16* __restrict__ qh_, __nv_bfloat16* __restrict__ ql_,
                     __nv_bfloat16* __restrict__ kh_, __nv_bfloat16* __restrict__ kl_,
                     __nv_bfloat16* __restrict__ vh_, __nv_bfloat16* __restrict__ vl_,
                     int M, int N, int K)
{
    extern __shared__ char smem[];
    const uint32_t sb = smem_u32(smem);
    const int tid = threadIdx.x, wid = tid >> 5, lane = tid & 31;
    const int wm = wid >> 2, wn = wid & 3;
    const int rowBase = blockIdx.y * 128, colBase = blockIdx.x * 128;
    const int NK = K / 64;

    float c[4][4][4];
#pragma unroll
    for (int i = 0; i < 4; i++)
#pragma unroll
        for (int j = 0; j < 4; j++)
#pragma unroll
            for (int k = 0; k < 4; k++) c[i][j][k] = 0.f;

    gemm_load_chunk(sb, Ahi, Alo, Bhi, Blo, rowBase, colBase, K, 0, 0, tid);
    gemm_load_chunk(sb, Ahi, Alo, Bhi, Blo, rowBase, colBase, K, 1, 1, tid);
    gemm_load_chunk(sb, Ahi, Alo, Bhi, Blo, rowBase, colBase, K, 2, 2, tid);

    const int aRow = wm * 64 + (lane & 15);
    const uint32_t aSegOff = ((lane >> 4) & 1) * 16;
    const int bRowL = wn * 32 + (lane & 7);
    const uint32_t bSegOff = ((lane >> 3) & 1) * 16;

    for (int kc = 0; kc < NK; kc++) {
        if (kc + 1 >= NK)      asm volatile("cp.async.wait_group 0;" ::: "memory");
        else if (kc + 2 >= NK) asm volatile("cp.async.wait_group 1;" ::: "memory");
        else                   asm volatile("cp.async.wait_group 2;" ::: "memory");
        __syncthreads();
        const uint32_t st = sb + (kc % 3) * G_STAGE;
#pragma unroll
        for (int ks = 0; ks < 4; ks++) {
            uint32_t bh[4][2], bl[4][2];
#pragma unroll
            for (int nj = 0; nj < 4; nj++) {
                const uint32_t boff = SWZ((uint32_t)(bRowL + nj * 8) * 128 + ks * 32 + bSegOff);
                ldsm_x2(bh[nj][0], bh[nj][1], st + 32768 + boff);
                ldsm_x2(bl[nj][0], bl[nj][1], st + 49152 + boff);
            }
#pragma unroll
            for (int mi = 0; mi < 4; mi++) {
                uint32_t ah[4], al[4];
                const uint32_t aoff = SWZ((uint32_t)(aRow + mi * 16) * 128 + ks * 32 + aSegOff);
                ldsm_x4(ah[0], ah[1], ah[2], ah[3], st + aoff);
                ldsm_x4(al[0], al[1], al[2], al[3], st + 16384 + aoff);
#pragma unroll
                for (int nj = 0; nj < 4; nj++) {
                    mma_bf16(c[mi][nj], ah, bh[nj][0], bh[nj][1]);
                    mma_bf16(c[mi][nj], al, bh[nj][0], bh[nj][1]);
                    mma_bf16(c[mi][nj], ah, bl[nj][0], bl[nj][1]);
                }
            }
        }
        __syncthreads();
        if (kc + 3 < NK)
            gemm_load_chunk(sb, Ahi, Alo, Bhi, Blo, rowBase, colBase, K,
                            kc + 3, kc % 3, tid);
    }

    const int g = lane >> 2, q2 = (lane & 3) * 2;
    if (MODE == 0) {
#pragma unroll
        for (int mi = 0; mi < 4; mi++) {
            const int row0 = rowBase + wm * 64 + mi * 16 + g;
#pragma unroll
            for (int nj = 0; nj < 4; nj++) {
                const int col = colBase + wn * 32 + nj * 8 + q2;
                const float bx = bias[col], by = bias[col + 1];
                float2 v0 = make_float2(c[mi][nj][0] + bx, c[mi][nj][1] + by);
                float2 v1 = make_float2(c[mi][nj][2] + bx, c[mi][nj][3] + by);
                *(float2*)(Cm + (size_t)row0 * N + col) = v0;
                *(float2*)(Cm + (size_t)(row0 + 8) * N + col) = v1;
            }
        }
    } else {
        // --- smem-staged per-head epilogue (mainloop smem is free now) ---
        const int sec = colBase / 768;                 // 0=Q 1=K 2=V (uniform)
        const int cid0 = colBase % 768;
        // Q pre-scaled by (1/8)*log2(e) so attention softmax runs in exp2 domain
        const float scl = (sec == 0) ? 0.18033688f : 1.0f;
        const uint32_t hbuf = sb, lbuf = sb + 128 * EPI_STRIDE * 2;
#pragma unroll
        for (int mi = 0; mi < 4; mi++) {
            const int rl = wm * 64 + mi * 16 + g;
#pragma unroll
            for (int nj = 0; nj < 4; nj++) {
                const int col = wn * 32 + nj * 8 + q2;
                const float bx = bias[colBase + col], by = bias[colBase + col + 1];
                uint32_t h0, l0, h1, l1;
                split2t((c[mi][nj][0] + bx) * scl, (c[mi][nj][1] + by) * scl, h0, l0);
                split2t((c[mi][nj][2] + bx) * scl, (c[mi][nj][3] + by) * scl, h1, l1);
                const uint32_t o0 = (uint32_t)(rl * EPI_STRIDE + col) * 2;
                const uint32_t o1 = o0 + 8 * EPI_STRIDE * 2;
                *(uint32_t*)(smem + (hbuf - sb) + o0) = h0;
                *(uint32_t*)(smem + (lbuf - sb) + o0) = l0;
                *(uint32_t*)(smem + (hbuf - sb) + o1) = h1;
                *(uint32_t*)(smem + (lbuf - sb) + o1) = l1;
            }
        }
        __syncthreads();
        __nv_bfloat16 *dh, *dl;
        if (sec == 0)      { dh = qh_; dl = ql_; }
        else if (sec == 1) { dh = kh_; dl = kl_; }
        else               { dh = vh_; dl = vl_; }
#pragma unroll
        for (int i = 0; i < 8; i++) {
            const int seg = tid + i * 256;
            const int r = seg >> 4, colb = (seg & 15) * 8;
            const int hh = (cid0 + colb) >> 6, d = (cid0 + colb) & 63;
            const int grow = rowBase + r;
            const int bb = grow >> 11, t = grow & 2047;
            const size_t off = (((size_t)bb * H_ + hh) * T_ + t) * 64 + d;
            const uint32_t so = (uint32_t)(r * EPI_STRIDE + colb) * 2;
            *(uint4*)(dh + off) = *(uint4*)(smem + so);
            *(uint4*)(dl + off) = *(uint4*)(smem + (128 * EPI_STRIDE * 2) + so);
        }
    }
}

// ---------------------------------------------------------------------------
// Flash attention: bf16 per-head inputs (Q pre-scaled, exp2 softmax),
// 2-stage cp.async ping-pong. 8 warps x 16 q-rows, k-tile 64.
// ---------------------------------------------------------------------------
#define SM_QHI 0
#define SM_QLO 16384
#define SM_ST  32768
#define A_SMEM 98304

__device__ __forceinline__ void attn_load_kv(
    uint32_t sb, const __nv_bfloat16* khi, const __nv_bfloat16* klo,
    const __nv_bfloat16* vhi, const __nv_bfloat16* vlo,
    size_t hb, int kBase, int stage, int tid)
{
    const uint32_t st = sb + SM_ST + stage * 32768;
#pragma unroll
    for (int i = 0; i < 2; i++) {
        const int seg = tid + i * 256;
        const int r = seg >> 3, gsg = seg & 7;
        const size_t goff = hb + (size_t)(kBase + r) * 64 + gsg * 8;
        const uint32_t soff = SWZ((uint32_t)r * 128 + gsg * 16);
        cpa16(st + soff,         khi + goff);
        cpa16(st + 8192 + soff,  klo + goff);
        cpa16(st + 16384 + soff, vhi + goff);
        cpa16(st + 24576 + soff, vlo + goff);
    }
    cpa_commit();
}

__global__ __launch_bounds__(256, 1)
void attn_mma_kernel(const __nv_bfloat16* __restrict__ qhi, const __nv_bfloat16* __restrict__ qlo,
                     const __nv_bfloat16* __restrict__ khi, const __nv_bfloat16* __restrict__ klo,
                     const __nv_bfloat16* __restrict__ vhi, const __nv_bfloat16* __restrict__ vlo,
                     __nv_bfloat16* __restrict__ yhi, __nv_bfloat16* __restrict__ ylo)
{
    extern __shared__ char smem[];
    const uint32_t sb = smem_u32(smem);
    const int qt = (int)gridDim.x - 1 - (int)blockIdx.x;
    const int bh = blockIdx.y;
    const int b = bh / H_, h = bh % H_;
    const int tid = threadIdx.x, wid = tid >> 5, lane = tid & 31;
    const int qBase = qt * 128;
    const size_t hb = (size_t)bh * T_ * 64;

#pragma unroll
    for (int i = 0; i < 4; i++) {
        const int seg = tid + i * 256;
        const int r = seg >> 3, gsg = seg & 7;
        const size_t goff = hb + (size_t)(qBase + r) * 64 + gsg * 8;
        const uint32_t soff = SWZ((uint32_t)r * 128 + gsg * 16);
        cpa16(sb + SM_QHI + soff, qhi + goff);
        cpa16(sb + SM_QLO + soff, qlo + goff);
    }
    cpa_commit();
    attn_load_kv(sb, khi, klo, vhi, vlo, hb, 0, 0, tid);
    asm volatile("cp.async.wait_group 0;" ::: "memory");
    __syncthreads();

    uint32_t qh[4][4], ql[4][4];
    {
        const int aRow = wid * 16 + (lane & 15);
        const uint32_t aSeg = ((lane >> 4) & 1) * 16;
#pragma unroll
        for (int ks = 0; ks < 4; ks++) {
            const uint32_t aoff = SWZ((uint32_t)aRow * 128 + ks * 32 + aSeg);
            ldsm_x4(qh[ks][0], qh[ks][1], qh[ks][2], qh[ks][3], sb + SM_QHI + aoff);
            ldsm_x4(ql[ks][0], ql[ks][1], ql[ks][2], ql[ks][3], sb + SM_QLO + aoff);
        }
    }

    float o[8][4];
#pragma unroll
    for (int d = 0; d < 8; d++)
#pragma unroll
        for (int k = 0; k < 4; k++) o[d][k] = 0.f;
    float m0 = -1e30f, m1 = -1e30f, l0s = 0.f, l1s = 0.f;

    const int g = lane >> 2, q2 = (lane & 3) * 2;
    const int row0 = qBase + wid * 16 + g;
    const int rowWarpMax = qBase + wid * 16 + 15;
    const int ktMax = 2 * qt + 1;

    const int bRowL = lane & 7;
    const uint32_t bSeg = ((lane >> 3) & 1) * 16;
    const int vRowL = lane & 15;

    for (int kt = 0; kt <= ktMax; kt++) {
        const int kBase = kt * 64;
        if (kt < ktMax) {
            attn_load_kv(sb, khi, klo, vhi, vlo, hb, kBase + 64, (kt + 1) & 1, tid);
            asm volatile("cp.async.wait_group 1;" ::: "memory");
        } else {
            asm volatile("cp.async.wait_group 0;" ::: "memory");
        }
        __syncthreads();

        if (kBase <= rowWarpMax) {
            const uint32_t st = sb + SM_ST + (kt & 1) * 32768;

            // ---- S = Q K^T (logits already in log2 domain) ----
            float sc[8][4];
#pragma unroll
            for (int nj = 0; nj < 8; nj++)
#pragma unroll
                for (int k = 0; k < 4; k++) sc[nj][k] = 0.f;
#pragma unroll
            for (int nj = 0; nj < 8; nj++) {
#pragma unroll
                for (int ks = 0; ks < 4; ks++) {
                    const uint32_t boff = SWZ((uint32_t)(nj * 8 + bRowL) * 128 + ks * 32 + bSeg);
                    uint32_t k0, k1;
                    ldsm_x2(k0, k1, st + boff);
                    mma_bf16(sc[nj], qh[ks], k0, k1);
                    mma_bf16(sc[nj], ql[ks], k0, k1);
                    ldsm_x2(k0, k1, st + 8192 + boff);
                    mma_bf16(sc[nj], qh[ks], k0, k1);
                }
            }

            if (kBase + 63 > qBase + wid * 16) {
#pragma unroll
                for (int nj = 0; nj < 8; nj++) {
                    const int col = kBase + nj * 8 + q2;
                    if (col > row0)         sc[nj][0] = -1e30f;
                    if (col + 1 > row0)     sc[nj][1] = -1e30f;
                    if (col > row0 + 8)     sc[nj][2] = -1e30f;
                    if (col + 1 > row0 + 8) sc[nj][3] = -1e30f;
                }
            }

            // ---- online softmax (base 2) ----
            float mx0 = -1e30f, mx1 = -1e30f;
#pragma unroll
            for (int nj = 0; nj < 8; nj++) {
                mx0 = fmaxf(mx0, fmaxf(sc[nj][0], sc[nj][1]));
                mx1 = fmaxf(mx1, fmaxf(sc[nj][2], sc[nj][3]));
            }
            mx0 = fmaxf(mx0, __shfl_xor_sync(0xffffffffu, mx0, 1));
            mx0 = fmaxf(mx0, __shfl_xor_sync(0xffffffffu, mx0, 2));
            mx1 = fmaxf(mx1, __shfl_xor_sync(0xffffffffu, mx1, 1));
            mx1 = fmaxf(mx1, __shfl_xor_sync(0xffffffffu, mx1, 2));
            const float mn0 = fmaxf(m0, mx0), mn1 = fmaxf(m1, mx1);
            const float al0 = exp2f(m0 - mn0), al1 = exp2f(m1 - mn1);
            m0 = mn0; m1 = mn1;
            float s0 = 0.f, s1 = 0.f;
#pragma unroll
            for (int nj = 0; nj < 8; nj++) {
                sc[nj][0] = exp2f(sc[nj][0] - mn0);
                sc[nj][1] = exp2f(sc[nj][1] - mn0);
                sc[nj][2] = exp2f(sc[nj][2] - mn1);
                sc[nj][3] = exp2f(sc[nj][3] - mn1);
                s0 += sc[nj][0] + sc[nj][1];
                s1 += sc[nj][2] + sc[nj][3];
            }
            s0 += __shfl_xor_sync(0xffffffffu, s0, 1);
            s0 += __shfl_xor_sync(0xffffffffu, s0, 2);
            s1 += __shfl_xor_sync(0xffffffffu, s1, 1);
            s1 += __shfl_xor_sync(0xffffffffu, s1, 2);
            l0s = l0s * al0 + s0;
            l1s = l1s * al1 + s1;

            // ---- P fragments (cheap truncation split) ----
            uint32_t ph[4][4], pl[4][4];
#pragma unroll
            for (int ks = 0; ks < 4; ks++) {
                split2t(sc[2 * ks][0],     sc[2 * ks][1],     ph[ks][0], pl[ks][0]);
                split2t(sc[2 * ks][2],     sc[2 * ks][3],     ph[ks][1], pl[ks][1]);
                split2t(sc[2 * ks + 1][0], sc[2 * ks + 1][1], ph[ks][2], pl[ks][2]);
                split2t(sc[2 * ks + 1][2], sc[2 * ks + 1][3], ph[ks][3], pl[ks][3]);
            }

            // ---- rescale O, accumulate P V ----
#pragma unroll
            for (int dj = 0; dj < 8; dj++) {
                o[dj][0] *= al0; o[dj][1] *= al0;
                o[dj][2] *= al1; o[dj][3] *= al1;
#pragma unroll
                for (int ks = 0; ks < 4; ks++) {
                    const uint32_t voff = SWZ((uint32_t)(ks * 16 + vRowL) * 128 + dj * 16);
                    uint32_t v0, v1;
                    ldsm_x2t(v0, v1, st + 16384 + voff);
                    mma_bf16(o[dj], ph[ks], v0, v1);
                    mma_bf16(o[dj], pl[ks], v0, v1);
                    ldsm_x2t(v0, v1, st + 24576 + voff);
                    mma_bf16(o[dj], ph[ks], v0, v1);
                }
            }
        }
        __syncthreads();
    }

    const float inv0 = 1.0f / l0s, inv1 = 1.0f / l1s;
#pragma unroll
    for (int dj = 0; dj < 8; dj++) {
        uint32_t h0, l0, h1, l1;
        split2t(o[dj][0] * inv0, o[dj][1] * inv0, h0, l0);
        split2t(o[dj][2] * inv1, o[dj][3] * inv1, h1, l1);
        const size_t r0 = ((size_t)b * T_ + row0) * C_ + h * 64 + dj * 8 + q2;
        const size_t r1 = r0 + 8 * C_;
        *(uint32_t*)(yhi + r0) = h0;
        *(uint32_t*)(ylo + r0) = l0;
        *(uint32_t*)(yhi + r1) = h1;
        *(uint32_t*)(ylo + r1) = l1;
    }
}

// ---------------------------------------------------------------------------
extern "C" void kernel_launch(void* const* d_in, const int* in_sizes, int n_in,
                              void* d_out, int out_size)
{
    const float* x      = (const float*)d_in[0];
    const float* w_attn = (const float*)d_in[1];
    const float* b_attn = (const float*)d_in[2];
    const float* w_proj = (const float*)d_in[3];
    const float* b_proj = (const float*)d_in[4];
    float* out = (float*)d_out;

    __nv_bfloat16 *xhi, *xlo, *yhi, *ylo, *wah, *wal, *wph, *wpl;
    __nv_bfloat16 *qh, *ql, *kh, *kl, *vh, *vl;
    cudaGetSymbolAddress((void**)&xhi, g_xhi);
    cudaGetSymbolAddress((void**)&xlo, g_xlo);
    cudaGetSymbolAddress((void**)&yhi, g_yhi);
    cudaGetSymbolAddress((void**)&ylo, g_ylo);
    cudaGetSymbolAddress((void**)&wah, g_wa_hi);
    cudaGetSymbolAddress((void**)&wal, g_wa_lo);
    cudaGetSymbolAddress((void**)&wph, g_wp_hi);
    cudaGetSymbolAddress((void**)&wpl, g_wp_lo);
    cudaGetSymbolAddress((void**)&qh, g_qhi);
    cudaGetSymbolAddress((void**)&ql, g_qlo);
    cudaGetSymbolAddress((void**)&kh, g_khi);
    cudaGetSymbolAddress((void**)&kl, g_klo);
    cudaGetSymbolAddress((void**)&vh, g_vhi);
    cudaGetSymbolAddress((void**)&vl, g_vlo);

    cudaFuncSetAttribute(gemm_mma_kernel<0>,
                         cudaFuncAttributeMaxDynamicSharedMemorySize, G_SMEM);
    cudaFuncSetAttribute(gemm_mma_kernel<1>,
                         cudaFuncAttributeMaxDynamicSharedMemorySize, G_SMEM);
    cudaFuncSetAttribute(attn_mma_kernel,
                         cudaFuncAttributeMaxDynamicSharedMemorySize, A_SMEM);

    {
        int n4 = ROWS_ * C_ / 4;
        split_rows_kernel<<<(n4 + 255) / 256, 256>>>(x, xhi, xlo, n4);
        dim3 bt(32, 8);
        split_transpose_kernel<<<dim3(QKVC_ / 32, C_ / 32), bt>>>(w_attn, wah, wal, C_, QKVC_);
        split_transpose_kernel<<<dim3(C_ / 32,    C_ / 32), bt>>>(w_proj, wph, wpl, C_, C_);
    }
    {
        dim3 grid(QKVC_ / 128, ROWS_ / 128);
        gemm_mma_kernel<1><<<grid, 256, G_SMEM>>>(xhi, xlo, wah, wal, b_attn,
                                                  nullptr, qh, ql, kh, kl, vh, vl,
                                                  ROWS_, QKVC_, C_);
    }
    {
        dim3 grid(T_ / 128, B_ * H_);
        attn_mma_kernel<<<grid, 256, A_SMEM>>>(qh, ql, kh, kl, vh, vl, yhi, ylo);
    }
    {
        dim3 grid(C_ / 128, ROWS_ / 128);
        gemm_mma_kernel<0><<<grid, 256, G_SMEM>>>(yhi, ylo, wph, wpl, b_proj, out,
                                                  nullptr, nullptr, nullptr, nullptr,
                                                  nullptr, nullptr, ROWS_, C_, C_);
    }
}

// round 8
// speedup vs baseline: 1.4879x; 1.4222x over previous
#include <cuda_runtime.h>
#include <cuda_bf16.h>
#include <cstdint>

// ---------------------------------------------------------------------------
// CausalSelfAttention on GB300 (sm_103 family target — no 'a' features).
// All matmuls via mma.sync.m16n8k16 bf16 with hi/lo error splitting.
// Stage 1: qkv = x @ w_attn + b_attn  (clean GEMM, fp32 out)
// Stage 1b: qkv -> per-head bf16 hi/lo Q(*log2e/8)/K/V  (memory-bound split)
// Stage 2: causal flash attention, 3-stage cp.async ring,
//          softmax(kt) interleaved with S(kt+1) inside each warp
// Stage 3: out = y @ w_proj + b_proj
// ---------------------------------------------------------------------------

#define B_ 4
#define T_ 2048
#define C_ 768
#define H_ 12
#define ROWS_ 8192
#define QKVC_ 2304
#define PHT_ (B_ * H_ * T_ * 64)

// ---------------- scratch ---------------------------------------------------
__device__ __align__(256) float          g_qkv[ROWS_ * QKVC_];
__device__ __align__(256) __nv_bfloat16  g_xhi[ROWS_ * C_];
__device__ __align__(256) __nv_bfloat16  g_xlo[ROWS_ * C_];
__device__ __align__(256) __nv_bfloat16  g_yhi[ROWS_ * C_];
__device__ __align__(256) __nv_bfloat16  g_ylo[ROWS_ * C_];
__device__ __align__(256) __nv_bfloat16  g_qhi[PHT_], g_qlo[PHT_];
__device__ __align__(256) __nv_bfloat16  g_khi[PHT_], g_klo[PHT_];
__device__ __align__(256) __nv_bfloat16  g_vhi[PHT_], g_vlo[PHT_];
__device__ __align__(256) __nv_bfloat16  g_wa_hi[QKVC_ * C_];
__device__ __align__(256) __nv_bfloat16  g_wa_lo[QKVC_ * C_];
__device__ __align__(256) __nv_bfloat16  g_wp_hi[C_ * C_];
__device__ __align__(256) __nv_bfloat16  g_wp_lo[C_ * C_];

// ---------------- helpers ---------------------------------------------------
__device__ __forceinline__ uint32_t smem_u32(const void* p) {
    uint32_t a;
    asm("{ .reg .u64 t; cvta.to.shared.u64 t, %1; cvt.u32.u64 %0, t; }"
        : "=r"(a) : "l"(p));
    return a;
}
#define SWZ(x) ((x) ^ (((x) >> 3) & 0x70))

__device__ __forceinline__ void cpa16(uint32_t dst, const void* src) {
    asm volatile("cp.async.cg.shared.global [%0], [%1], 16;" :: "r"(dst), "l"(src));
}
__device__ __forceinline__ void cpa_commit() { asm volatile("cp.async.commit_group;"); }

__device__ __forceinline__ void ldsm_x4(uint32_t& r0, uint32_t& r1, uint32_t& r2,
                                        uint32_t& r3, uint32_t addr) {
    asm volatile("ldmatrix.sync.aligned.m8n8.x4.shared.b16 {%0,%1,%2,%3}, [%4];"
                 : "=r"(r0), "=r"(r1), "=r"(r2), "=r"(r3) : "r"(addr));
}
__device__ __forceinline__ void ldsm_x2(uint32_t& r0, uint32_t& r1, uint32_t addr) {
    asm volatile("ldmatrix.sync.aligned.m8n8.x2.shared.b16 {%0,%1}, [%2];"
                 : "=r"(r0), "=r"(r1) : "r"(addr));
}
__device__ __forceinline__ void ldsm_x2t(uint32_t& r0, uint32_t& r1, uint32_t addr) {
    asm volatile("ldmatrix.sync.aligned.m8n8.x2.trans.shared.b16 {%0,%1}, [%2];"
                 : "=r"(r0), "=r"(r1) : "r"(addr));
}
__device__ __forceinline__ void mma_bf16(float* c, const uint32_t* a,
                                         uint32_t b0, uint32_t b1) {
    asm volatile("mma.sync.aligned.m16n8k16.row.col.f32.bf16.bf16.f32 "
                 "{%0,%1,%2,%3}, {%4,%5,%6,%7}, {%8,%9}, {%0,%1,%2,%3};"
                 : "+f"(c[0]), "+f"(c[1]), "+f"(c[2]), "+f"(c[3])
                 : "r"(a[0]), "r"(a[1]), "r"(a[2]), "r"(a[3]), "r"(b0), "r"(b1));
}
__device__ __forceinline__ float ex2_(float x) {
    float r; asm("ex2.approx.f32 %0, %1;" : "=f"(r) : "f"(x)); return r;
}

// round-nearest split
__device__ __forceinline__ void split2(float a, float b, uint32_t& h, uint32_t& l) {
    __nv_bfloat16 ha = __float2bfloat16(a), hb = __float2bfloat16(b);
    __nv_bfloat16 la = __float2bfloat16(a - __bfloat162float(ha));
    __nv_bfloat16 lb = __float2bfloat16(b - __bfloat162float(hb));
    __nv_bfloat162 hh(ha, hb), ll(la, lb);
    h = *(uint32_t*)&hh;
    l = *(uint32_t*)&ll;
}
// cheap truncation split
__device__ __forceinline__ void split2t(float a, float b, uint32_t& h, uint32_t& l) {
    const uint32_t ua = __float_as_uint(a), ub = __float_as_uint(b);
    h = __byte_perm(ua, ub, 0x7632);
    const float ra = a - __uint_as_float(ua & 0xffff0000u);
    const float rb = b - __uint_as_float(ub & 0xffff0000u);
    asm("cvt.rn.bf16x2.f32 %0, %1, %2;" : "=r"(l) : "f"(rb), "f"(ra));
}

// ---------------------------------------------------------------------------
// Conversion kernels
// ---------------------------------------------------------------------------
__global__ void split_rows_kernel(const float* __restrict__ in,
                                  __nv_bfloat16* __restrict__ hi,
                                  __nv_bfloat16* __restrict__ lo, int n4)
{
    int i = blockIdx.x * blockDim.x + threadIdx.x;
    if (i >= n4) return;
    float4 v = ((const float4*)in)[i];
    uint32_t h0, l0, h1, l1;
    split2(v.x, v.y, h0, l0);
    split2(v.z, v.w, h1, l1);
    uint32_t* hp = (uint32_t*)(hi + 4 * (size_t)i);
    uint32_t* lp = (uint32_t*)(lo + 4 * (size_t)i);
    hp[0] = h0; hp[1] = h1;
    lp[0] = l0; lp[1] = l1;
}

__global__ void split_transpose_kernel(const float* __restrict__ w,
                                       __nv_bfloat16* __restrict__ hiT,
                                       __nv_bfloat16* __restrict__ loT, int K, int N)
{
    __shared__ float t[32][33];
    const int n0 = blockIdx.x * 32, k0 = blockIdx.y * 32;
    const int tx = threadIdx.x, ty = threadIdx.y;
#pragma unroll
    for (int j = 0; j < 4; j++)
        t[ty + j * 8][tx] = w[(size_t)(k0 + ty + j * 8) * N + n0 + tx];
    __syncthreads();
#pragma unroll
    for (int j = 0; j < 4; j++) {
        const int n = ty + j * 8;
        float v = t[tx][n];
        __nv_bfloat16 h = __float2bfloat16(v);
        __nv_bfloat16 l = __float2bfloat16(v - __bfloat162float(h));
        hiT[(size_t)(n0 + n) * K + k0 + tx] = h;
        loT[(size_t)(n0 + n) * K + k0 + tx] = l;
    }
}

// qkv fp32 [row][2304] -> per-head bf16 hi/lo Q(scaled)/K/V
__global__ void qkv_split_kernel(const float* __restrict__ qkv,
                                 __nv_bfloat16* __restrict__ qh, __nv_bfloat16* __restrict__ ql,
                                 __nv_bfloat16* __restrict__ kh, __nv_bfloat16* __restrict__ kl,
                                 __nv_bfloat16* __restrict__ vh, __nv_bfloat16* __restrict__ vl)
{
    const int i = blockIdx.x * blockDim.x + threadIdx.x;   // < ROWS_*576
    const int row = i / 576;
    const int c4 = (i - row * 576) * 4;
    float4 v = *(const float4*)(qkv + (size_t)row * QKVC_ + c4);
    const int sec = c4 / 768;
    const int cid = c4 - sec * 768;
    const int hh = cid >> 6, d = cid & 63;
    if (sec == 0) {   // fold (1/8)*log2(e) into Q for exp2-domain softmax
        const float s = 0.18033688f;
        v.x *= s; v.y *= s; v.z *= s; v.w *= s;
    }
    uint32_t h0, l0, h1, l1;
    split2(v.x, v.y, h0, l0);
    split2(v.z, v.w, h1, l1);
    const int b = row >> 11, t = row & 2047;
    const size_t off = (((size_t)b * H_ + hh) * T_ + t) * 64 + d;
    __nv_bfloat16 *dh, *dl;
    if (sec == 0)      { dh = qh; dl = ql; }
    else if (sec == 1) { dh = kh; dl = kl; }
    else               { dh = vh; dl = vl; }
    ((uint32_t*)(dh + off))[0] = h0; ((uint32_t*)(dh + off))[1] = h1;
    ((uint32_t*)(dl + off))[0] = l0; ((uint32_t*)(dl + off))[1] = l1;
}

// ---------------------------------------------------------------------------
// GEMM: C[M,N] = (Ahi+Alo)[M,K] @ (Bhi+Blo)[N,K]^T + bias  (fp32 out)
// 128x128 tile, BK=64, 8 warps, 3-stage cp.async, SW128 smem.
// ---------------------------------------------------------------------------
#define G_STAGE 65536
#define G_SMEM  (3 * G_STAGE)

__device__ __forceinline__ void gemm_load_chunk(
    uint32_t sb, const __nv_bfloat16* Ahi, const __nv_bfloat16* Alo,
    const __nv_bfloat16* Bhi, const __nv_bfloat16* Blo,
    int rowBase, int colBase, int K, int kc, int stage, int tid)
{
    const uint32_t base = sb + stage * G_STAGE;
    const int k0 = kc * 64;
    const __nv_bfloat16* srcs[4] = { Ahi, Alo, Bhi, Blo };
#pragma unroll
    for (int t = 0; t < 4; t++) {
        const __nv_bfloat16* src = srcs[t];
        const int gb = (t < 2) ? rowBase : colBase;
        const uint32_t soff = base + t * 16384;
#pragma unroll
        for (int i = 0; i < 4; i++) {
            const int seg = tid + i * 256;
            const int r = seg >> 3, g = seg & 7;
            cpa16(soff + SWZ(r * 128 + g * 16),
                  src + (size_t)(gb + r) * K + k0 + g * 8);
        }
    }
    cpa_commit();
}

__global__ __launch_bounds__(256, 1)
void gemm_mma_kernel(const __nv_bfloat16* __restrict__ Ahi, const __nv_bfloat16* __restrict__ Alo,
                     const __nv_bfloat16* __restrict__ Bhi, const __nv_bfloat16* __restrict__ Blo,
                     const float* __restrict__ bias, float* __restrict__ Cm,
                     int M, int N, int K)
{
    extern __shared__ char smem[];
    const uint32_t sb = smem_u32(smem);
    const int tid = threadIdx.x, wid = tid >> 5, lane = tid & 31;
    const int wm = wid >> 2, wn = wid & 3;
    const int rowBase = blockIdx.y * 128, colBase = blockIdx.x * 128;
    const int NK = K / 64;

    float c[4][4][4];
#pragma unroll
    for (int i = 0; i < 4; i++)
#pragma unroll
        for (int j = 0; j < 4; j++)
#pragma unroll
            for (int k = 0; k < 4; k++) c[i][j][k] = 0.f;

    gemm_load_chunk(sb, Ahi, Alo, Bhi, Blo, rowBase, colBase, K, 0, 0, tid);
    gemm_load_chunk(sb, Ahi, Alo, Bhi, Blo, rowBase, colBase, K, 1, 1, tid);
    gemm_load_chunk(sb, Ahi, Alo, Bhi, Blo, rowBase, colBase, K, 2, 2, tid);

    const int aRow = wm * 64 + (lane & 15);
    const uint32_t aSegOff = ((lane >> 4) & 1) * 16;
    const int bRowL = wn * 32 + (lane & 7);
    const uint32_t bSegOff = ((lane >> 3) & 1) * 16;

    for (int kc = 0; kc < NK; kc++) {
        if (kc + 1 >= NK)      asm volatile("cp.async.wait_group 0;" ::: "memory");
        else if (kc + 2 >= NK) asm volatile("cp.async.wait_group 1;" ::: "memory");
        else                   asm volatile("cp.async.wait_group 2;" ::: "memory");
        __syncthreads();
        const uint32_t st = sb + (kc % 3) * G_STAGE;
#pragma unroll
        for (int ks = 0; ks < 4; ks++) {
            uint32_t bh[4][2], bl[4][2];
#pragma unroll
            for (int nj = 0; nj < 4; nj++) {
                const uint32_t boff = SWZ((uint32_t)(bRowL + nj * 8) * 128 + ks * 32 + bSegOff);
                ldsm_x2(bh[nj][0], bh[nj][1], st + 32768 + boff);
                ldsm_x2(bl[nj][0], bl[nj][1], st + 49152 + boff);
            }
#pragma unroll
            for (int mi = 0; mi < 4; mi++) {
                uint32_t ah[4], al[4];
                const uint32_t aoff = SWZ((uint32_t)(aRow + mi * 16) * 128 + ks * 32 + aSegOff);
                ldsm_x4(ah[0], ah[1], ah[2], ah[3], st + aoff);
                ldsm_x4(al[0], al[1], al[2], al[3], st + 16384 + aoff);
#pragma unroll
                for (int nj = 0; nj < 4; nj++) {
                    mma_bf16(c[mi][nj], ah, bh[nj][0], bh[nj][1]);
                    mma_bf16(c[mi][nj], al, bh[nj][0], bh[nj][1]);
                    mma_bf16(c[mi][nj], ah, bl[nj][0], bl[nj][1]);
                }
            }
        }
        __syncthreads();
        if (kc + 3 < NK)
            gemm_load_chunk(sb, Ahi, Alo, Bhi, Blo, rowBase, colBase, K,
                            kc + 3, kc % 3, tid);
    }

    const int g = lane >> 2, q2 = (lane & 3) * 2;
#pragma unroll
    for (int mi = 0; mi < 4; mi++) {
        const int row0 = rowBase + wm * 64 + mi * 16 + g;
#pragma unroll
        for (int nj = 0; nj < 4; nj++) {
            const int col = colBase + wn * 32 + nj * 8 + q2;
            const float bx = bias[col], by = bias[col + 1];
            float2 v0 = make_float2(c[mi][nj][0] + bx, c[mi][nj][1] + by);
            float2 v1 = make_float2(c[mi][nj][2] + bx, c[mi][nj][3] + by);
            *(float2*)(Cm + (size_t)row0 * N + col) = v0;
            *(float2*)(Cm + (size_t)(row0 + 8) * N + col) = v1;
        }
    }
}

// ---------------------------------------------------------------------------
// Flash attention: 3-stage cp.async ring; per-warp software pipeline —
// S(kt+1) MMAs interleaved with softmax(kt), then PV(kt).
// 8 warps x 16 q-rows, k-tile 64. smem: Q 32K + 3x32K = 128K.
// ---------------------------------------------------------------------------
#define SM_QHI 0
#define SM_QLO 16384
#define SM_ST  32768
#define A_SMEM 131072

__device__ __forceinline__ void attn_load_kv(
    uint32_t sb, const __nv_bfloat16* khi, const __nv_bfloat16* klo,
    const __nv_bfloat16* vhi, const __nv_bfloat16* vlo,
    size_t hb, int kBase, int stage, int tid)
{
    const uint32_t st = sb + SM_ST + stage * 32768;
#pragma unroll
    for (int i = 0; i < 2; i++) {
        const int seg = tid + i * 256;
        const int r = seg >> 3, gsg = seg & 7;
        const size_t goff = hb + (size_t)(kBase + r) * 64 + gsg * 8;
        const uint32_t soff = SWZ((uint32_t)r * 128 + gsg * 16);
        cpa16(st + soff,         khi + goff);
        cpa16(st + 8192 + soff,  klo + goff);
        cpa16(st + 16384 + soff, vhi + goff);
        cpa16(st + 24576 + soff, vlo + goff);
    }
    cpa_commit();
}

__global__ __launch_bounds__(256, 1)
void attn_mma_kernel(const __nv_bfloat16* __restrict__ qhi, const __nv_bfloat16* __restrict__ qlo,
                     const __nv_bfloat16* __restrict__ khi, const __nv_bfloat16* __restrict__ klo,
                     const __nv_bfloat16* __restrict__ vhi, const __nv_bfloat16* __restrict__ vlo,
                     __nv_bfloat16* __restrict__ yhi, __nv_bfloat16* __restrict__ ylo)
{
    extern __shared__ char smem[];
    const uint32_t sb = smem_u32(smem);
    const int qt = (int)gridDim.x - 1 - (int)blockIdx.x;
    const int bh = blockIdx.y;
    const int b = bh / H_, h = bh % H_;
    const int tid = threadIdx.x, wid = tid >> 5, lane = tid & 31;
    const int qBase = qt * 128;
    const size_t hb = (size_t)bh * T_ * 64;
    const int ktMax = 2 * qt + 1;

    // ---- prologue loads: Q (group 0), KV tile 0 (g1), KV tile 1 (g2) ----
#pragma unroll
    for (int i = 0; i < 4; i++) {
        const int seg = tid + i * 256;
        const int r = seg >> 3, gsg = seg & 7;
        const size_t goff = hb + (size_t)(qBase + r) * 64 + gsg * 8;
        const uint32_t soff = SWZ((uint32_t)r * 128 + gsg * 16);
        cpa16(sb + SM_QHI + soff, qhi + goff);
        cpa16(sb + SM_QLO + soff, qlo + goff);
    }
    cpa_commit();
    attn_load_kv(sb, khi, klo, vhi, vlo, hb, 0,  0, tid);
    attn_load_kv(sb, khi, klo, vhi, vlo, hb, 64, 1, tid);
    asm volatile("cp.async.wait_group 1;" ::: "memory");   // Q + KV0 done
    __syncthreads();

    // ---- Q fragments ----
    uint32_t qh[4][4], ql[4][4];
    {
        const int aRow = wid * 16 + (lane & 15);
        const uint32_t aSeg = ((lane >> 4) & 1) * 16;
#pragma unroll
        for (int ks = 0; ks < 4; ks++) {
            const uint32_t aoff = SWZ((uint32_t)aRow * 128 + ks * 32 + aSeg);
            ldsm_x4(qh[ks][0], qh[ks][1], qh[ks][2], qh[ks][3], sb + SM_QHI + aoff);
            ldsm_x4(ql[ks][0], ql[ks][1], ql[ks][2], ql[ks][3], sb + SM_QLO + aoff);
        }
    }

    float o[8][4];
#pragma unroll
    for (int d = 0; d < 8; d++)
#pragma unroll
        for (int k = 0; k < 4; k++) o[d][k] = 0.f;
    float m0 = -1e30f, m1 = -1e30f, l0s = 0.f, l1s = 0.f;

    const int g = lane >> 2, q2 = (lane & 3) * 2;
    const int qRowMin = qBase + wid * 16;
    const int row0 = qRowMin + g;
    const int wktMax = (qRowMin + 15) >> 6;   // last k-tile this warp needs

    const int bRowL = lane & 7;
    const uint32_t bSeg = ((lane >> 3) & 1) * 16;
    const int vRowL = lane & 15;

    // ---- S(0) ----
    float sc[8][4];
    {
        const uint32_t st0 = sb + SM_ST;
#pragma unroll
        for (int nj = 0; nj < 8; nj++) {
#pragma unroll
            for (int k = 0; k < 4; k++) sc[nj][k] = 0.f;
#pragma unroll
            for (int ks = 0; ks < 4; ks++) {
                const uint32_t boff = SWZ((uint32_t)(nj * 8 + bRowL) * 128 + ks * 32 + bSeg);
                uint32_t k0, k1;
                ldsm_x2(k0, k1, st0 + boff);
                mma_bf16(sc[nj], qh[ks], k0, k1);
                mma_bf16(sc[nj], ql[ks], k0, k1);
                ldsm_x2(k0, k1, st0 + 8192 + boff);
                mma_bf16(sc[nj], qh[ks], k0, k1);
            }
        }
    }

    for (int kt = 0; kt <= ktMax; kt++) {
        const int kBase = kt * 64;
        // prefetch tile kt+2 into slot (kt+2)%3 (slot freed by end-of-prev-iter sync)
        if (kt + 2 <= ktMax) {
            attn_load_kv(sb, khi, klo, vhi, vlo, hb, (kt + 2) * 64, (kt + 2) % 3, tid);
            asm volatile("cp.async.wait_group 1;" ::: "memory");   // KV(kt+1) done
        } else {
            asm volatile("cp.async.wait_group 0;" ::: "memory");
        }
        __syncthreads();   // cross-thread visibility of KV(kt+1)

        const bool doP = (kt <= wktMax);
        const bool doS = (kt + 1 <= ktMax) && (kt + 1 <= wktMax);

        if (doP) {
            const uint32_t stP = sb + SM_ST + (kt % 3) * 32768;
            const uint32_t stS = sb + SM_ST + ((kt + 1) % 3) * 32768;

            // ---- mask current tile (diagonal region only) ----
            if (kBase + 63 > qRowMin) {
#pragma unroll
                for (int nj = 0; nj < 8; nj++) {
                    const int col = kBase + nj * 8 + q2;
                    if (col > row0)         sc[nj][0] = -1e30f;
                    if (col + 1 > row0)     sc[nj][1] = -1e30f;
                    if (col > row0 + 8)     sc[nj][2] = -1e30f;
                    if (col + 1 > row0 + 8) sc[nj][3] = -1e30f;
                }
            }

            // ---- row maxes ----
            float mx0 = -1e30f, mx1 = -1e30f;
#pragma unroll
            for (int nj = 0; nj < 8; nj++) {
                mx0 = fmaxf(mx0, fmaxf(sc[nj][0], sc[nj][1]));
                mx1 = fmaxf(mx1, fmaxf(sc[nj][2], sc[nj][3]));
            }
            mx0 = fmaxf(mx0, __shfl_xor_sync(0xffffffffu, mx0, 1));
            mx0 = fmaxf(mx0, __shfl_xor_sync(0xffffffffu, mx0, 2));
            mx1 = fmaxf(mx1, __shfl_xor_sync(0xffffffffu, mx1, 1));
            mx1 = fmaxf(mx1, __shfl_xor_sync(0xffffffffu, mx1, 2));
            const float mn0 = fmaxf(m0, mx0), mn1 = fmaxf(m1, mx1);
            const float al0 = ex2_(m0 - mn0), al1 = ex2_(m1 - mn1);
            m0 = mn0; m1 = mn1;

            float s0 = 0.f, s1 = 0.f;
            float sn[8][4];
            if (doS) {
                // ---- S(kt+1) MMAs interleaved with exp2 of softmax(kt) ----
#pragma unroll
                for (int nj = 0; nj < 8; nj++) {
#pragma unroll
                    for (int k = 0; k < 4; k++) sn[nj][k] = 0.f;
#pragma unroll
                    for (int ks = 0; ks < 4; ks++) {
                        const uint32_t boff = SWZ((uint32_t)(nj * 8 + bRowL) * 128 + ks * 32 + bSeg);
                        uint32_t k0, k1;
                        ldsm_x2(k0, k1, stS + boff);
                        mma_bf16(sn[nj], qh[ks], k0, k1);
                        mma_bf16(sn[nj], ql[ks], k0, k1);
                        ldsm_x2(k0, k1, stS + 8192 + boff);
                        mma_bf16(sn[nj], qh[ks], k0, k1);
                    }
                    sc[nj][0] = ex2_(sc[nj][0] - mn0);
                    sc[nj][1] = ex2_(sc[nj][1] - mn0);
                    sc[nj][2] = ex2_(sc[nj][2] - mn1);
                    sc[nj][3] = ex2_(sc[nj][3] - mn1);
                    s0 += sc[nj][0] + sc[nj][1];
                    s1 += sc[nj][2] + sc[nj][3];
                }
            } else {
#pragma unroll
                for (int nj = 0; nj < 8; nj++) {
                    sc[nj][0] = ex2_(sc[nj][0] - mn0);
                    sc[nj][1] = ex2_(sc[nj][1] - mn0);
                    sc[nj][2] = ex2_(sc[nj][2] - mn1);
                    sc[nj][3] = ex2_(sc[nj][3] - mn1);
                    s0 += sc[nj][0] + sc[nj][1];
                    s1 += sc[nj][2] + sc[nj][3];
                }
            }
            s0 += __shfl_xor_sync(0xffffffffu, s0, 1);
            s0 += __shfl_xor_sync(0xffffffffu, s0, 2);
            s1 += __shfl_xor_sync(0xffffffffu, s1, 1);
            s1 += __shfl_xor_sync(0xffffffffu, s1, 2);
            l0s = l0s * al0 + s0;
            l1s = l1s * al1 + s1;

            // ---- P fragments ----
            uint32_t ph[4][4], pl[4][4];
#pragma unroll
            for (int ks = 0; ks < 4; ks++) {
                split2t(sc[2 * ks][0],     sc[2 * ks][1],     ph[ks][0], pl[ks][0]);
                split2t(sc[2 * ks][2],     sc[2 * ks][3],     ph[ks][1], pl[ks][1]);
                split2t(sc[2 * ks + 1][0], sc[2 * ks + 1][1], ph[ks][2], pl[ks][2]);
                split2t(sc[2 * ks + 1][2], sc[2 * ks + 1][3], ph[ks][3], pl[ks][3]);
            }

            // ---- PV(kt) + O rescale ----
#pragma unroll
            for (int dj = 0; dj < 8; dj++) {
                o[dj][0] *= al0; o[dj][1] *= al0;
                o[dj][2] *= al1; o[dj][3] *= al1;
#pragma unroll
                for (int ks = 0; ks < 4; ks++) {
                    const uint32_t voff = SWZ((uint32_t)(ks * 16 + vRowL) * 128 + dj * 16);
                    uint32_t v0, v1;
                    ldsm_x2t(v0, v1, stP + 16384 + voff);
                    mma_bf16(o[dj], ph[ks], v0, v1);
                    mma_bf16(o[dj], pl[ks], v0, v1);
                    ldsm_x2t(v0, v1, stP + 24576 + voff);
                    mma_bf16(o[dj], ph[ks], v0, v1);
                }
            }

            // rotate pipeline
            if (doS) {
#pragma unroll
                for (int nj = 0; nj < 8; nj++)
#pragma unroll
                    for (int k = 0; k < 4; k++) sc[nj][k] = sn[nj][k];
            }
        }
        __syncthreads();   // protect ring slot reuse
    }

    // ---- epilogue: O/l -> bf16 hi/lo (row-major for stage 3) ----
    const float inv0 = 1.0f / l0s, inv1 = 1.0f / l1s;
#pragma unroll
    for (int dj = 0; dj < 8; dj++) {
        uint32_t h0, l0, h1, l1;
        split2t(o[dj][0] * inv0, o[dj][1] * inv0, h0, l0);
        split2t(o[dj][2] * inv1, o[dj][3] * inv1, h1, l1);
        const size_t r0 = ((size_t)b * T_ + row0) * C_ + h * 64 + dj * 8 + q2;
        const size_t r1 = r0 + 8 * C_;
        *(uint32_t*)(yhi + r0) = h0;
        *(uint32_t*)(ylo + r0) = l0;
        *(uint32_t*)(yhi + r1) = h1;
        *(uint32_t*)(ylo + r1) = l1;
    }
}

// ---------------------------------------------------------------------------
extern "C" void kernel_launch(void* const* d_in, const int* in_sizes, int n_in,
                              void* d_out, int out_size)
{
    const float* x      = (const float*)d_in[0];
    const float* w_attn = (const float*)d_in[1];
    const float* b_attn = (const float*)d_in[2];
    const float* w_proj = (const float*)d_in[3];
    const float* b_proj = (const float*)d_in[4];
    float* out = (float*)d_out;

    float* qkv;
    __nv_bfloat16 *xhi, *xlo, *yhi, *ylo, *wah, *wal, *wph, *wpl;
    __nv_bfloat16 *qh, *ql, *kh, *kl, *vh, *vl;
    cudaGetSymbolAddress((void**)&qkv, g_qkv);
    cudaGetSymbolAddress((void**)&xhi, g_xhi);
    cudaGetSymbolAddress((void**)&xlo, g_xlo);
    cudaGetSymbolAddress((void**)&yhi, g_yhi);
    cudaGetSymbolAddress((void**)&ylo, g_ylo);
    cudaGetSymbolAddress((void**)&wah, g_wa_hi);
    cudaGetSymbolAddress((void**)&wal, g_wa_lo);
    cudaGetSymbolAddress((void**)&wph, g_wp_hi);
    cudaGetSymbolAddress((void**)&wpl, g_wp_lo);
    cudaGetSymbolAddress((void**)&qh, g_qhi);
    cudaGetSymbolAddress((void**)&ql, g_qlo);
    cudaGetSymbolAddress((void**)&kh, g_khi);
    cudaGetSymbolAddress((void**)&kl, g_klo);
    cudaGetSymbolAddress((void**)&vh, g_vhi);
    cudaGetSymbolAddress((void**)&vl, g_vlo);

    cudaFuncSetAttribute(gemm_mma_kernel,
                         cudaFuncAttributeMaxDynamicSharedMemorySize, G_SMEM);
    cudaFuncSetAttribute(attn_mma_kernel,
                         cudaFuncAttributeMaxDynamicSharedMemorySize, A_SMEM);

    // input/weight conversions
    {
        int n4 = ROWS_ * C_ / 4;
        split_rows_kernel<<<(n4 + 255) / 256, 256>>>(x, xhi, xlo, n4);
        dim3 bt(32, 8);
        split_transpose_kernel<<<dim3(QKVC_ / 32, C_ / 32), bt>>>(w_attn, wah, wal, C_, QKVC_);
        split_transpose_kernel<<<dim3(C_ / 32,    C_ / 32), bt>>>(w_proj, wph, wpl, C_, C_);
    }
    // Stage 1: qkv = x @ w_attn + b_attn  (fp32)
    {
        dim3 grid(QKVC_ / 128, ROWS_ / 128);
        gemm_mma_kernel<<<grid, 256, G_SMEM>>>(xhi, xlo, wah, wal, b_attn, qkv,
                                               ROWS_, QKVC_, C_);
    }
    // Stage 1b: qkv -> per-head bf16 hi/lo
    {
        qkv_split_kernel<<<ROWS_ * 576 / 256, 256>>>(qkv, qh, ql, kh, kl, vh, vl);
    }
    // Stage 2: attention -> y (bf16 hi/lo)
    {
        dim3 grid(T_ / 128, B_ * H_);
        attn_mma_kernel<<<grid, 256, A_SMEM>>>(qh, ql, kh, kl, vh, vl, yhi, ylo);
    }
    // Stage 3: out = y @ w_proj + b_proj
    {
        dim3 grid(C_ / 128, ROWS_ / 128);
        gemm_mma_kernel<<<grid, 256, G_SMEM>>>(yhi, ylo, wph, wpl, b_proj, out,
                                               ROWS_, C_, C_);
    }
}

// round 9
// speedup vs baseline: 1.5811x; 1.0626x over previous
#include <cuda_runtime.h>
#include <cuda_bf16.h>
#include <cstdint>

// ---------------------------------------------------------------------------
// CausalSelfAttention on GB300 (sm_103 family target — no 'a' features).
// All matmuls via mma.sync.m16n8k16 bf16 with hi/lo error splitting.
// Stage 1: qkv GEMM -> row-major bf16 hi/lo (Q cols pre-scaled by log2e/8)
// Stage 2: causal flash attention reads strided row-major slices;
//          3-stage cp.async ring; S(kt+1) interleaved with softmax(kt)
// Stage 3: out = y @ w_proj + b_proj (fp32 out)
// ---------------------------------------------------------------------------

#define B_ 4
#define T_ 2048
#define C_ 768
#define H_ 12
#define ROWS_ 8192
#define QKVC_ 2304

// ---------------- scratch ---------------------------------------------------
__device__ __align__(256) __nv_bfloat16  g_qkvhi[ROWS_ * QKVC_];
__device__ __align__(256) __nv_bfloat16  g_qkvlo[ROWS_ * QKVC_];
__device__ __align__(256) __nv_bfloat16  g_xhi[ROWS_ * C_];
__device__ __align__(256) __nv_bfloat16  g_xlo[ROWS_ * C_];
__device__ __align__(256) __nv_bfloat16  g_yhi[ROWS_ * C_];
__device__ __align__(256) __nv_bfloat16  g_ylo[ROWS_ * C_];
__device__ __align__(256) __nv_bfloat16  g_wa_hi[QKVC_ * C_];
__device__ __align__(256) __nv_bfloat16  g_wa_lo[QKVC_ * C_];
__device__ __align__(256) __nv_bfloat16  g_wp_hi[C_ * C_];
__device__ __align__(256) __nv_bfloat16  g_wp_lo[C_ * C_];

// ---------------- helpers ---------------------------------------------------
__device__ __forceinline__ uint32_t smem_u32(const void* p) {
    uint32_t a;
    asm("{ .reg .u64 t; cvta.to.shared.u64 t, %1; cvt.u32.u64 %0, t; }"
        : "=r"(a) : "l"(p));
    return a;
}
#define SWZ(x) ((x) ^ (((x) >> 3) & 0x70))

__device__ __forceinline__ void cpa16(uint32_t dst, const void* src) {
    asm volatile("cp.async.cg.shared.global [%0], [%1], 16;" :: "r"(dst), "l"(src));
}
__device__ __forceinline__ void cpa_commit() { asm volatile("cp.async.commit_group;"); }

__device__ __forceinline__ void ldsm_x4(uint32_t& r0, uint32_t& r1, uint32_t& r2,
                                        uint32_t& r3, uint32_t addr) {
    asm volatile("ldmatrix.sync.aligned.m8n8.x4.shared.b16 {%0,%1,%2,%3}, [%4];"
                 : "=r"(r0), "=r"(r1), "=r"(r2), "=r"(r3) : "r"(addr));
}
__device__ __forceinline__ void ldsm_x4t(uint32_t& r0, uint32_t& r1, uint32_t& r2,
                                         uint32_t& r3, uint32_t addr) {
    asm volatile("ldmatrix.sync.aligned.m8n8.x4.trans.shared.b16 {%0,%1,%2,%3}, [%4];"
                 : "=r"(r0), "=r"(r1), "=r"(r2), "=r"(r3) : "r"(addr));
}
__device__ __forceinline__ void mma_bf16(float* c, const uint32_t* a,
                                         uint32_t b0, uint32_t b1) {
    asm volatile("mma.sync.aligned.m16n8k16.row.col.f32.bf16.bf16.f32 "
                 "{%0,%1,%2,%3}, {%4,%5,%6,%7}, {%8,%9}, {%0,%1,%2,%3};"
                 : "+f"(c[0]), "+f"(c[1]), "+f"(c[2]), "+f"(c[3])
                 : "r"(a[0]), "r"(a[1]), "r"(a[2]), "r"(a[3]), "r"(b0), "r"(b1));
}
__device__ __forceinline__ float ex2_(float x) {
    float r; asm("ex2.approx.f32 %0, %1;" : "=f"(r) : "f"(x)); return r;
}

// round-nearest split
__device__ __forceinline__ void split2(float a, float b, uint32_t& h, uint32_t& l) {
    __nv_bfloat16 ha = __float2bfloat16(a), hb = __float2bfloat16(b);
    __nv_bfloat16 la = __float2bfloat16(a - __bfloat162float(ha));
    __nv_bfloat16 lb = __float2bfloat16(b - __bfloat162float(hb));
    __nv_bfloat162 hh(ha, hb), ll(la, lb);
    h = *(uint32_t*)&hh;
    l = *(uint32_t*)&ll;
}
// cheap truncation split
__device__ __forceinline__ void split2t(float a, float b, uint32_t& h, uint32_t& l) {
    const uint32_t ua = __float_as_uint(a), ub = __float_as_uint(b);
    h = __byte_perm(ua, ub, 0x7632);
    const float ra = a - __uint_as_float(ua & 0xffff0000u);
    const float rb = b - __uint_as_float(ub & 0xffff0000u);
    asm("cvt.rn.bf16x2.f32 %0, %1, %2;" : "=r"(l) : "f"(rb), "f"(ra));
}

// ---------------------------------------------------------------------------
// Conversion kernels (inputs/weights only)
// ---------------------------------------------------------------------------
__global__ void split_rows_kernel(const float* __restrict__ in,
                                  __nv_bfloat16* __restrict__ hi,
                                  __nv_bfloat16* __restrict__ lo, int n4)
{
    int i = blockIdx.x * blockDim.x + threadIdx.x;
    if (i >= n4) return;
    float4 v = ((const float4*)in)[i];
    uint32_t h0, l0, h1, l1;
    split2(v.x, v.y, h0, l0);
    split2(v.z, v.w, h1, l1);
    uint32_t* hp = (uint32_t*)(hi + 4 * (size_t)i);
    uint32_t* lp = (uint32_t*)(lo + 4 * (size_t)i);
    hp[0] = h0; hp[1] = h1;
    lp[0] = l0; lp[1] = l1;
}

__global__ void split_transpose_kernel(const float* __restrict__ w,
                                       __nv_bfloat16* __restrict__ hiT,
                                       __nv_bfloat16* __restrict__ loT, int K, int N)
{
    __shared__ float t[32][33];
    const int n0 = blockIdx.x * 32, k0 = blockIdx.y * 32;
    const int tx = threadIdx.x, ty = threadIdx.y;
#pragma unroll
    for (int j = 0; j < 4; j++)
        t[ty + j * 8][tx] = w[(size_t)(k0 + ty + j * 8) * N + n0 + tx];
    __syncthreads();
#pragma unroll
    for (int j = 0; j < 4; j++) {
        const int n = ty + j * 8;
        float v = t[tx][n];
        __nv_bfloat16 h = __float2bfloat16(v);
        __nv_bfloat16 l = __float2bfloat16(v - __bfloat162float(h));
        hiT[(size_t)(n0 + n) * K + k0 + tx] = h;
        loT[(size_t)(n0 + n) * K + k0 + tx] = l;
    }
}

// ---------------------------------------------------------------------------
// GEMM: C = (Ahi+Alo)[M,K] @ (Bhi+Blo)[N,K]^T + bias
// OUT=0: fp32 out.  OUT=1: bf16 hi/lo row-major, cols<768 scaled by log2e/8.
// 128x128 tile, BK=64, 8 warps, 3-stage cp.async, SW128 smem.
// ---------------------------------------------------------------------------
#define G_STAGE 65536
#define G_SMEM  (3 * G_STAGE)

__device__ __forceinline__ void gemm_load_chunk(
    uint32_t sb, const __nv_bfloat16* Ahi, const __nv_bfloat16* Alo,
    const __nv_bfloat16* Bhi, const __nv_bfloat16* Blo,
    int rowBase, int colBase, int K, int kc, int stage, int tid)
{
    const uint32_t base = sb + stage * G_STAGE;
    const int k0 = kc * 64;
    const __nv_bfloat16* srcs[4] = { Ahi, Alo, Bhi, Blo };
#pragma unroll
    for (int t = 0; t < 4; t++) {
        const __nv_bfloat16* src = srcs[t];
        const int gb = (t < 2) ? rowBase : colBase;
        const uint32_t soff = base + t * 16384;
#pragma unroll
        for (int i = 0; i < 4; i++) {
            const int seg = tid + i * 256;
            const int r = seg >> 3, g = seg & 7;
            cpa16(soff + SWZ(r * 128 + g * 16),
                  src + (size_t)(gb + r) * K + k0 + g * 8);
        }
    }
    cpa_commit();
}

template <int OUT>
__global__ __launch_bounds__(256, 1)
void gemm_mma_kernel(const __nv_bfloat16* __restrict__ Ahi, const __nv_bfloat16* __restrict__ Alo,
                     const __nv_bfloat16* __restrict__ Bhi, const __nv_bfloat16* __restrict__ Blo,
                     const float* __restrict__ bias, float* __restrict__ Cm,
                     __nv_bfloat16* __restrict__ Chi, __nv_bfloat16* __restrict__ Clo,
                     int M, int N, int K)
{
    extern __shared__ char smem[];
    const uint32_t sb = smem_u32(smem);
    const int tid = threadIdx.x, wid = tid >> 5, lane = tid & 31;
    const int wm = wid >> 2, wn = wid & 3;
    const int rowBase = blockIdx.y * 128, colBase = blockIdx.x * 128;
    const int NK = K / 64;

    float c[4][4][4];
#pragma unroll
    for (int i = 0; i < 4; i++)
#pragma unroll
        for (int j = 0; j < 4; j++)
#pragma unroll
            for (int k = 0; k < 4; k++) c[i][j][k] = 0.f;

    gemm_load_chunk(sb, Ahi, Alo, Bhi, Blo, rowBase, colBase, K, 0, 0, tid);
    gemm_load_chunk(sb, Ahi, Alo, Bhi, Blo, rowBase, colBase, K, 1, 1, tid);
    gemm_load_chunk(sb, Ahi, Alo, Bhi, Blo, rowBase, colBase, K, 2, 2, tid);

    const int aRow = wm * 64 + (lane & 15);
    const uint32_t aSegOff = ((lane >> 4) & 1) * 16;
    // x4 B addressing: lanes 16-31 take the odd nj
    const int bRow4 = wn * 32 + ((lane >> 4) & 1) * 8 + (lane & 7);
    const uint32_t bSegOff = ((lane >> 3) & 1) * 16;

    for (int kc = 0; kc < NK; kc++) {
        if (kc + 1 >= NK)      asm volatile("cp.async.wait_group 0;" ::: "memory");
        else if (kc + 2 >= NK) asm volatile("cp.async.wait_group 1;" ::: "memory");
        else                   asm volatile("cp.async.wait_group 2;" ::: "memory");
        __syncthreads();
        const uint32_t st = sb + (kc % 3) * G_STAGE;
#pragma unroll
        for (int ks = 0; ks < 4; ks++) {
            uint32_t bh[4][2], bl[4][2];
#pragma unroll
            for (int nj = 0; nj < 4; nj += 2) {
                const uint32_t boff = SWZ((uint32_t)(bRow4 + nj * 8) * 128 + ks * 32 + bSegOff);
                ldsm_x4(bh[nj][0], bh[nj][1], bh[nj + 1][0], bh[nj + 1][1], st + 32768 + boff);
                ldsm_x4(bl[nj][0], bl[nj][1], bl[nj + 1][0], bl[nj + 1][1], st + 49152 + boff);
            }
#pragma unroll
            for (int mi = 0; mi < 4; mi++) {
                uint32_t ah[4], al[4];
                const uint32_t aoff = SWZ((uint32_t)(aRow + mi * 16) * 128 + ks * 32 + aSegOff);
                ldsm_x4(ah[0], ah[1], ah[2], ah[3], st + aoff);
                ldsm_x4(al[0], al[1], al[2], al[3], st + 16384 + aoff);
#pragma unroll
                for (int nj = 0; nj < 4; nj++) {
                    mma_bf16(c[mi][nj], ah, bh[nj][0], bh[nj][1]);
                    mma_bf16(c[mi][nj], al, bh[nj][0], bh[nj][1]);
                    mma_bf16(c[mi][nj], ah, bl[nj][0], bl[nj][1]);
                }
            }
        }
        __syncthreads();
        if (kc + 3 < NK)
            gemm_load_chunk(sb, Ahi, Alo, Bhi, Blo, rowBase, colBase, K,
                            kc + 3, kc % 3, tid);
    }

    const int g = lane >> 2, q2 = (lane & 3) * 2;
    if (OUT == 0) {
#pragma unroll
        for (int mi = 0; mi < 4; mi++) {
            const int row0 = rowBase + wm * 64 + mi * 16 + g;
#pragma unroll
            for (int nj = 0; nj < 4; nj++) {
                const int col = colBase + wn * 32 + nj * 8 + q2;
                const float bx = bias[col], by = bias[col + 1];
                float2 v0 = make_float2(c[mi][nj][0] + bx, c[mi][nj][1] + by);
                float2 v1 = make_float2(c[mi][nj][2] + bx, c[mi][nj][3] + by);
                *(float2*)(Cm + (size_t)row0 * N + col) = v0;
                *(float2*)(Cm + (size_t)(row0 + 8) * N + col) = v1;
            }
        }
    } else {
        // bf16 hi/lo row-major; Q columns (<768) pre-scaled for exp2 softmax
        const float scl = (colBase < 768) ? 0.18033688f : 1.0f;
#pragma unroll
        for (int mi = 0; mi < 4; mi++) {
            const int row0 = rowBase + wm * 64 + mi * 16 + g;
#pragma unroll
            for (int nj = 0; nj < 4; nj++) {
                const int col = colBase + wn * 32 + nj * 8 + q2;
                const float bx = bias[col], by = bias[col + 1];
                uint32_t h0, l0, h1, l1;
                split2t((c[mi][nj][0] + bx) * scl, (c[mi][nj][1] + by) * scl, h0, l0);
                split2t((c[mi][nj][2] + bx) * scl, (c[mi][nj][3] + by) * scl, h1, l1);
                *(uint32_t*)(Chi + (size_t)row0 * N + col) = h0;
                *(uint32_t*)(Clo + (size_t)row0 * N + col) = l0;
                *(uint32_t*)(Chi + (size_t)(row0 + 8) * N + col) = h1;
                *(uint32_t*)(Clo + (size_t)(row0 + 8) * N + col) = l1;
            }
        }
    }
}

// ---------------------------------------------------------------------------
// Flash attention: strided row-major qkv hi/lo input; 3-stage cp.async ring;
// S(kt+1) interleaved with softmax(kt); x4 ldmatrix.
// 8 warps x 16 q-rows, k-tile 64. smem: Q 32K + 3x32K = 128K.
// ---------------------------------------------------------------------------
#define SM_QHI 0
#define SM_QLO 16384
#define SM_ST  32768
#define A_SMEM 131072

__device__ __forceinline__ void attn_load_kv(
    uint32_t sb, const __nv_bfloat16* qkvh, const __nv_bfloat16* qkvl,
    size_t base0, int kBase, int stage, int tid)
{
    const uint32_t st = sb + SM_ST + stage * 32768;
#pragma unroll
    for (int i = 0; i < 2; i++) {
        const int seg = tid + i * 256;
        const int r = seg >> 3, gsg = seg & 7;
        const size_t goff = base0 + (size_t)(kBase + r) * QKVC_ + gsg * 8;
        const uint32_t soff = SWZ((uint32_t)r * 128 + gsg * 16);
        cpa16(st + soff,         qkvh + goff + 768);    // K hi
        cpa16(st + 8192 + soff,  qkvl + goff + 768);    // K lo
        cpa16(st + 16384 + soff, qkvh + goff + 1536);   // V hi
        cpa16(st + 24576 + soff, qkvl + goff + 1536);   // V lo
    }
    cpa_commit();
}

__global__ __launch_bounds__(256, 1)
void attn_mma_kernel(const __nv_bfloat16* __restrict__ qkvh,
                     const __nv_bfloat16* __restrict__ qkvl,
                     __nv_bfloat16* __restrict__ yhi, __nv_bfloat16* __restrict__ ylo)
{
    extern __shared__ char smem[];
    const uint32_t sb = smem_u32(smem);
    const int qt = (int)gridDim.x - 1 - (int)blockIdx.x;
    const int bh = blockIdx.y;
    const int b = bh / H_, h = bh % H_;
    const int tid = threadIdx.x, wid = tid >> 5, lane = tid & 31;
    const int qBase = qt * 128;
    const size_t base0 = (size_t)b * T_ * QKVC_ + h * 64;
    const int ktMax = 2 * qt + 1;

    // ---- prologue: Q (group 0), KV0 (g1), KV1 (g2) ----
#pragma unroll
    for (int i = 0; i < 4; i++) {
        const int seg = tid + i * 256;
        const int r = seg >> 3, gsg = seg & 7;
        const size_t goff = base0 + (size_t)(qBase + r) * QKVC_ + gsg * 8;
        const uint32_t soff = SWZ((uint32_t)r * 128 + gsg * 16);
        cpa16(sb + SM_QHI + soff, qkvh + goff);
        cpa16(sb + SM_QLO + soff, qkvl + goff);
    }
    cpa_commit();
    attn_load_kv(sb, qkvh, qkvl, base0, 0,  0, tid);
    attn_load_kv(sb, qkvh, qkvl, base0, 64, 1, tid);
    asm volatile("cp.async.wait_group 1;" ::: "memory");
    __syncthreads();

    // ---- Q fragments ----
    uint32_t qh[4][4], ql[4][4];
    {
        const int aRow = wid * 16 + (lane & 15);
        const uint32_t aSeg = ((lane >> 4) & 1) * 16;
#pragma unroll
        for (int ks = 0; ks < 4; ks++) {
            const uint32_t aoff = SWZ((uint32_t)aRow * 128 + ks * 32 + aSeg);
            ldsm_x4(qh[ks][0], qh[ks][1], qh[ks][2], qh[ks][3], sb + SM_QHI + aoff);
            ldsm_x4(ql[ks][0], ql[ks][1], ql[ks][2], ql[ks][3], sb + SM_QLO + aoff);
        }
    }

    float o[8][4];
#pragma unroll
    for (int d = 0; d < 8; d++)
#pragma unroll
        for (int k = 0; k < 4; k++) o[d][k] = 0.f;
    float m0 = -1e30f, m1 = -1e30f, l0s = 0.f, l1s = 0.f;

    const int g = lane >> 2, q2 = (lane & 3) * 2;
    const int qRowMin = qBase + wid * 16;
    const int row0 = qRowMin + g;
    const int wktMax = (qRowMin + 15) >> 6;

    // x4 K addressing (lanes 16-31 -> odd nj); x4t V (lanes 16-31 -> odd dj)
    const int bRow4 = ((lane >> 4) & 1) * 8 + (lane & 7);
    const uint32_t bSeg = ((lane >> 3) & 1) * 16;
    const int vRowL = lane & 15;
    const uint32_t vSeg = ((lane >> 4) & 1) * 16;

    // ---- S(0) ----
    float sc[8][4];
    {
        const uint32_t st0 = sb + SM_ST;
#pragma unroll
        for (int nj = 0; nj < 8; nj += 2) {
#pragma unroll
            for (int k = 0; k < 4; k++) { sc[nj][k] = 0.f; sc[nj + 1][k] = 0.f; }
#pragma unroll
            for (int ks = 0; ks < 4; ks++) {
                const uint32_t boff = SWZ((uint32_t)(nj * 8 + bRow4) * 128 + ks * 32 + bSeg);
                uint32_t k0, k1, k2, k3;
                ldsm_x4(k0, k1, k2, k3, st0 + boff);
                mma_bf16(sc[nj],     qh[ks], k0, k1);
                mma_bf16(sc[nj],     ql[ks], k0, k1);
                mma_bf16(sc[nj + 1], qh[ks], k2, k3);
                mma_bf16(sc[nj + 1], ql[ks], k2, k3);
                ldsm_x4(k0, k1, k2, k3, st0 + 8192 + boff);
                mma_bf16(sc[nj],     qh[ks], k0, k1);
                mma_bf16(sc[nj + 1], qh[ks], k2, k3);
            }
        }
    }

    for (int kt = 0; kt <= ktMax; kt++) {
        const int kBase = kt * 64;
        if (kt + 2 <= ktMax) {
            attn_load_kv(sb, qkvh, qkvl, base0, (kt + 2) * 64, (kt + 2) % 3, tid);
            asm volatile("cp.async.wait_group 1;" ::: "memory");
        } else {
            asm volatile("cp.async.wait_group 0;" ::: "memory");
        }
        __syncthreads();

        const bool doP = (kt <= wktMax);
        const bool doS = (kt + 1 <= ktMax) && (kt + 1 <= wktMax);

        if (doP) {
            const uint32_t stP = sb + SM_ST + (kt % 3) * 32768;
            const uint32_t stS = sb + SM_ST + ((kt + 1) % 3) * 32768;

            if (kBase + 63 > qRowMin) {
#pragma unroll
                for (int nj = 0; nj < 8; nj++) {
                    const int col = kBase + nj * 8 + q2;
                    if (col > row0)         sc[nj][0] = -1e30f;
                    if (col + 1 > row0)     sc[nj][1] = -1e30f;
                    if (col > row0 + 8)     sc[nj][2] = -1e30f;
                    if (col + 1 > row0 + 8) sc[nj][3] = -1e30f;
                }
            }

            float mx0 = -1e30f, mx1 = -1e30f;
#pragma unroll
            for (int nj = 0; nj < 8; nj++) {
                mx0 = fmaxf(mx0, fmaxf(sc[nj][0], sc[nj][1]));
                mx1 = fmaxf(mx1, fmaxf(sc[nj][2], sc[nj][3]));
            }
            mx0 = fmaxf(mx0, __shfl_xor_sync(0xffffffffu, mx0, 1));
            mx0 = fmaxf(mx0, __shfl_xor_sync(0xffffffffu, mx0, 2));
            mx1 = fmaxf(mx1, __shfl_xor_sync(0xffffffffu, mx1, 1));
            mx1 = fmaxf(mx1, __shfl_xor_sync(0xffffffffu, mx1, 2));
            const float mn0 = fmaxf(m0, mx0), mn1 = fmaxf(m1, mx1);
            const float al0 = ex2_(m0 - mn0), al1 = ex2_(m1 - mn1);
            m0 = mn0; m1 = mn1;

            float s0 = 0.f, s1 = 0.f;
            float sn[8][4];
            if (doS) {
                // S(kt+1) interleaved with exp2(kt)
#pragma unroll
                for (int nj = 0; nj < 8; nj += 2) {
#pragma unroll
                    for (int k = 0; k < 4; k++) { sn[nj][k] = 0.f; sn[nj + 1][k] = 0.f; }
#pragma unroll
                    for (int ks = 0; ks < 4; ks++) {
                        const uint32_t boff = SWZ((uint32_t)(nj * 8 + bRow4) * 128 + ks * 32 + bSeg);
                        uint32_t k0, k1, k2, k3;
                        ldsm_x4(k0, k1, k2, k3, stS + boff);
                        mma_bf16(sn[nj],     qh[ks], k0, k1);
                        mma_bf16(sn[nj],     ql[ks], k0, k1);
                        mma_bf16(sn[nj + 1], qh[ks], k2, k3);
                        mma_bf16(sn[nj + 1], ql[ks], k2, k3);
                        ldsm_x4(k0, k1, k2, k3, stS + 8192 + boff);
                        mma_bf16(sn[nj],     qh[ks], k0, k1);
                        mma_bf16(sn[nj + 1], qh[ks], k2, k3);
                    }
#pragma unroll
                    for (int u = 0; u < 2; u++) {
                        sc[nj + u][0] = ex2_(sc[nj + u][0] - mn0);
                        sc[nj + u][1] = ex2_(sc[nj + u][1] - mn0);
                        sc[nj + u][2] = ex2_(sc[nj + u][2] - mn1);
                        sc[nj + u][3] = ex2_(sc[nj + u][3] - mn1);
                        s0 += sc[nj + u][0] + sc[nj + u][1];
                        s1 += sc[nj + u][2] + sc[nj + u][3];
                    }
                }
            } else {
#pragma unroll
                for (int nj = 0; nj < 8; nj++) {
                    sc[nj][0] = ex2_(sc[nj][0] - mn0);
                    sc[nj][1] = ex2_(sc[nj][1] - mn0);
                    sc[nj][2] = ex2_(sc[nj][2] - mn1);
                    sc[nj][3] = ex2_(sc[nj][3] - mn1);
                    s0 += sc[nj][0] + sc[nj][1];
                    s1 += sc[nj][2] + sc[nj][3];
                }
            }
            s0 += __shfl_xor_sync(0xffffffffu, s0, 1);
            s0 += __shfl_xor_sync(0xffffffffu, s0, 2);
            s1 += __shfl_xor_sync(0xffffffffu, s1, 1);
            s1 += __shfl_xor_sync(0xffffffffu, s1, 2);
            l0s = l0s * al0 + s0;
            l1s = l1s * al1 + s1;

            uint32_t ph[4][4], pl[4][4];
#pragma unroll
            for (int ks = 0; ks < 4; ks++) {
                split2t(sc[2 * ks][0],     sc[2 * ks][1],     ph[ks][0], pl[ks][0]);
                split2t(sc[2 * ks][2],     sc[2 * ks][3],     ph[ks][1], pl[ks][1]);
                split2t(sc[2 * ks + 1][0], sc[2 * ks + 1][1], ph[ks][2], pl[ks][2]);
                split2t(sc[2 * ks + 1][2], sc[2 * ks + 1][3], ph[ks][3], pl[ks][3]);
            }

            // PV(kt) + O rescale, x4t V loads (dj pairs)
#pragma unroll
            for (int dj = 0; dj < 8; dj += 2) {
#pragma unroll
                for (int u = 0; u < 2; u++) {
                    o[dj + u][0] *= al0; o[dj + u][1] *= al0;
                    o[dj + u][2] *= al1; o[dj + u][3] *= al1;
                }
#pragma unroll
                for (int ks = 0; ks < 4; ks++) {
                    const uint32_t voff = SWZ((uint32_t)(ks * 16 + vRowL) * 128 + dj * 16 + vSeg);
                    uint32_t v0, v1, v2, v3;
                    ldsm_x4t(v0, v1, v2, v3, stP + 16384 + voff);
                    mma_bf16(o[dj],     ph[ks], v0, v1);
                    mma_bf16(o[dj],     pl[ks], v0, v1);
                    mma_bf16(o[dj + 1], ph[ks], v2, v3);
                    mma_bf16(o[dj + 1], pl[ks], v2, v3);
                    ldsm_x4t(v0, v1, v2, v3, stP + 24576 + voff);
                    mma_bf16(o[dj],     ph[ks], v0, v1);
                    mma_bf16(o[dj + 1], ph[ks], v2, v3);
                }
            }

            if (doS) {
#pragma unroll
                for (int nj = 0; nj < 8; nj++)
#pragma unroll
                    for (int k = 0; k < 4; k++) sc[nj][k] = sn[nj][k];
            }
        }
        __syncthreads();
    }

    const float inv0 = 1.0f / l0s, inv1 = 1.0f / l1s;
#pragma unroll
    for (int dj = 0; dj < 8; dj++) {
        uint32_t h0, l0, h1, l1;
        split2t(o[dj][0] * inv0, o[dj][1] * inv0, h0, l0);
        split2t(o[dj][2] * inv1, o[dj][3] * inv1, h1, l1);
        const size_t r0 = ((size_t)b * T_ + row0) * C_ + h * 64 + dj * 8 + q2;
        const size_t r1 = r0 + 8 * C_;
        *(uint32_t*)(yhi + r0) = h0;
        *(uint32_t*)(ylo + r0) = l0;
        *(uint32_t*)(yhi + r1) = h1;
        *(uint32_t*)(ylo + r1) = l1;
    }
}

// ---------------------------------------------------------------------------
extern "C" void kernel_launch(void* const* d_in, const int* in_sizes, int n_in,
                              void* d_out, int out_size)
{
    const float* x      = (const float*)d_in[0];
    const float* w_attn = (const float*)d_in[1];
    const float* b_attn = (const float*)d_in[2];
    const float* w_proj = (const float*)d_in[3];
    const float* b_proj = (const float*)d_in[4];
    float* out = (float*)d_out;

    __nv_bfloat16 *qkvhi, *qkvlo, *xhi, *xlo, *yhi, *ylo, *wah, *wal, *wph, *wpl;
    cudaGetSymbolAddress((void**)&qkvhi, g_qkvhi);
    cudaGetSymbolAddress((void**)&qkvlo, g_qkvlo);
    cudaGetSymbolAddress((void**)&xhi, g_xhi);
    cudaGetSymbolAddress((void**)&xlo, g_xlo);
    cudaGetSymbolAddress((void**)&yhi, g_yhi);
    cudaGetSymbolAddress((void**)&ylo, g_ylo);
    cudaGetSymbolAddress((void**)&wah, g_wa_hi);
    cudaGetSymbolAddress((void**)&wal, g_wa_lo);
    cudaGetSymbolAddress((void**)&wph, g_wp_hi);
    cudaGetSymbolAddress((void**)&wpl, g_wp_lo);

    cudaFuncSetAttribute(gemm_mma_kernel<0>,
                         cudaFuncAttributeMaxDynamicSharedMemorySize, G_SMEM);
    cudaFuncSetAttribute(gemm_mma_kernel<1>,
                         cudaFuncAttributeMaxDynamicSharedMemorySize, G_SMEM);
    cudaFuncSetAttribute(attn_mma_kernel,
                         cudaFuncAttributeMaxDynamicSharedMemorySize, A_SMEM);

    // input/weight conversions
    {
        int n4 = ROWS_ * C_ / 4;
        split_rows_kernel<<<(n4 + 255) / 256, 256>>>(x, xhi, xlo, n4);
        dim3 bt(32, 8);
        split_transpose_kernel<<<dim3(QKVC_ / 32, C_ / 32), bt>>>(w_attn, wah, wal, C_, QKVC_);
        split_transpose_kernel<<<dim3(C_ / 32,    C_ / 32), bt>>>(w_proj, wph, wpl, C_, C_);
    }
    // Stage 1: qkv GEMM -> row-major bf16 hi/lo (Q pre-scaled)
    {
        dim3 grid(QKVC_ / 128, ROWS_ / 128);
        gemm_mma_kernel<1><<<grid, 256, G_SMEM>>>(xhi, xlo, wah, wal, b_attn,
                                                  nullptr, qkvhi, qkvlo,
                                                  ROWS_, QKVC_, C_);
    }
    // Stage 2: attention (strided row-major reads) -> y bf16 hi/lo
    {
        dim3 grid(T_ / 128, B_ * H_);
        attn_mma_kernel<<<grid, 256, A_SMEM>>>(qkvhi, qkvlo, yhi, ylo);
    }
    // Stage 3: out = y @ w_proj + b_proj
    {
        dim3 grid(C_ / 128, ROWS_ / 128);
        gemm_mma_kernel<0><<<grid, 256, G_SMEM>>>(yhi, ylo, wph, wpl, b_proj, out,
                                                  nullptr, nullptr, ROWS_, C_, C_);
    }
}

// round 10
// speedup vs baseline: 1.7596x; 1.1129x over previous
#include <cuda_runtime.h>
#include <cuda_bf16.h>
#include <cuda_fp16.h>
#include <cstdint>

// ---------------------------------------------------------------------------
// CausalSelfAttention on GB300 (sm_103 family target — no 'a' features).
// gemm1 (qkv):  bf16 3-pass mma; epilogue -> Q,K bf16 hi/lo (Q*log2e/8), V fp16
// attention:    S bf16 3-pass; PV fp16 2-pass; single-sync 3-stage ring
// gemm3 (proj): fp16 2-pass (y fp16 hi/lo, w_proj fp16 single)
// ---------------------------------------------------------------------------

#define B_ 4
#define T_ 2048
#define C_ 768
#define H_ 12
#define ROWS_ 8192
#define QKVC_ 2304

// ---------------- scratch ---------------------------------------------------
__device__ __align__(256) __nv_bfloat16  g_qkvhi[ROWS_ * QKVC_];   // V cols: fp16
__device__ __align__(256) __nv_bfloat16  g_qkvlo[ROWS_ * QKVC_];
__device__ __align__(256) __nv_bfloat16  g_xhi[ROWS_ * C_];
__device__ __align__(256) __nv_bfloat16  g_xlo[ROWS_ * C_];
__device__ __align__(256) __nv_bfloat16  g_yhi[ROWS_ * C_];        // fp16 payload
__device__ __align__(256) __nv_bfloat16  g_ylo[ROWS_ * C_];        // fp16 payload
__device__ __align__(256) __nv_bfloat16  g_wa_hi[QKVC_ * C_];
__device__ __align__(256) __nv_bfloat16  g_wa_lo[QKVC_ * C_];
__device__ __align__(256) __nv_bfloat16  g_wp_h[C_ * C_];          // fp16 payload

// ---------------- helpers ---------------------------------------------------
__device__ __forceinline__ uint32_t smem_u32(const void* p) {
    uint32_t a;
    asm("{ .reg .u64 t; cvta.to.shared.u64 t, %1; cvt.u32.u64 %0, t; }"
        : "=r"(a) : "l"(p));
    return a;
}
#define SWZ(x) ((x) ^ (((x) >> 3) & 0x70))

__device__ __forceinline__ void cpa16(uint32_t dst, const void* src) {
    asm volatile("cp.async.cg.shared.global [%0], [%1], 16;" :: "r"(dst), "l"(src));
}
__device__ __forceinline__ void cpa_commit() { asm volatile("cp.async.commit_group;"); }

__device__ __forceinline__ void ldsm_x4(uint32_t& r0, uint32_t& r1, uint32_t& r2,
                                        uint32_t& r3, uint32_t addr) {
    asm volatile("ldmatrix.sync.aligned.m8n8.x4.shared.b16 {%0,%1,%2,%3}, [%4];"
                 : "=r"(r0), "=r"(r1), "=r"(r2), "=r"(r3) : "r"(addr));
}
__device__ __forceinline__ void ldsm_x4t(uint32_t& r0, uint32_t& r1, uint32_t& r2,
                                         uint32_t& r3, uint32_t addr) {
    asm volatile("ldmatrix.sync.aligned.m8n8.x4.trans.shared.b16 {%0,%1,%2,%3}, [%4];"
                 : "=r"(r0), "=r"(r1), "=r"(r2), "=r"(r3) : "r"(addr));
}
__device__ __forceinline__ void mma_bf16(float* c, const uint32_t* a,
                                         uint32_t b0, uint32_t b1) {
    asm volatile("mma.sync.aligned.m16n8k16.row.col.f32.bf16.bf16.f32 "
                 "{%0,%1,%2,%3}, {%4,%5,%6,%7}, {%8,%9}, {%0,%1,%2,%3};"
                 : "+f"(c[0]), "+f"(c[1]), "+f"(c[2]), "+f"(c[3])
                 : "r"(a[0]), "r"(a[1]), "r"(a[2]), "r"(a[3]), "r"(b0), "r"(b1));
}
__device__ __forceinline__ void mma_f16(float* c, const uint32_t* a,
                                        uint32_t b0, uint32_t b1) {
    asm volatile("mma.sync.aligned.m16n8k16.row.col.f32.f16.f16.f32 "
                 "{%0,%1,%2,%3}, {%4,%5,%6,%7}, {%8,%9}, {%0,%1,%2,%3};"
                 : "+f"(c[0]), "+f"(c[1]), "+f"(c[2]), "+f"(c[3])
                 : "r"(a[0]), "r"(a[1]), "r"(a[2]), "r"(a[3]), "r"(b0), "r"(b1));
}
__device__ __forceinline__ float ex2_(float x) {
    float r; asm("ex2.approx.f32 %0, %1;" : "=f"(r) : "f"(x)); return r;
}

// round-nearest bf16 split
__device__ __forceinline__ void split2(float a, float b, uint32_t& h, uint32_t& l) {
    __nv_bfloat16 ha = __float2bfloat16(a), hb = __float2bfloat16(b);
    __nv_bfloat16 la = __float2bfloat16(a - __bfloat162float(ha));
    __nv_bfloat16 lb = __float2bfloat16(b - __bfloat162float(hb));
    __nv_bfloat162 hh(ha, hb), ll(la, lb);
    h = *(uint32_t*)&hh;
    l = *(uint32_t*)&ll;
}
// truncation bf16 split
__device__ __forceinline__ void split2t(float a, float b, uint32_t& h, uint32_t& l) {
    const uint32_t ua = __float_as_uint(a), ub = __float_as_uint(b);
    h = __byte_perm(ua, ub, 0x7632);
    const float ra = a - __uint_as_float(ua & 0xffff0000u);
    const float rb = b - __uint_as_float(ub & 0xffff0000u);
    asm("cvt.rn.bf16x2.f32 %0, %1, %2;" : "=r"(l) : "f"(rb), "f"(ra));
}
// fp16 hi/lo split
__device__ __forceinline__ void split2h(float a, float b, uint32_t& h, uint32_t& l) {
    __half2 hh = __floats2half2_rn(a, b);
    float2 hf = __half22float2(hh);
    __half2 ll = __floats2half2_rn(a - hf.x, b - hf.y);
    h = *(uint32_t*)&hh;
    l = *(uint32_t*)&ll;
}

// ---------------------------------------------------------------------------
// Conversion kernels
// ---------------------------------------------------------------------------
__global__ void split_rows_kernel(const float* __restrict__ in,
                                  __nv_bfloat16* __restrict__ hi,
                                  __nv_bfloat16* __restrict__ lo, int n4)
{
    int i = blockIdx.x * blockDim.x + threadIdx.x;
    if (i >= n4) return;
    float4 v = ((const float4*)in)[i];
    uint32_t h0, l0, h1, l1;
    split2(v.x, v.y, h0, l0);
    split2(v.z, v.w, h1, l1);
    uint32_t* hp = (uint32_t*)(hi + 4 * (size_t)i);
    uint32_t* lp = (uint32_t*)(lo + 4 * (size_t)i);
    hp[0] = h0; hp[1] = h1;
    lp[0] = l0; lp[1] = l1;
}

__global__ void split_transpose_kernel(const float* __restrict__ w,
                                       __nv_bfloat16* __restrict__ hiT,
                                       __nv_bfloat16* __restrict__ loT, int K, int N)
{
    __shared__ float t[32][33];
    const int n0 = blockIdx.x * 32, k0 = blockIdx.y * 32;
    const int tx = threadIdx.x, ty = threadIdx.y;
#pragma unroll
    for (int j = 0; j < 4; j++)
        t[ty + j * 8][tx] = w[(size_t)(k0 + ty + j * 8) * N + n0 + tx];
    __syncthreads();
#pragma unroll
    for (int j = 0; j < 4; j++) {
        const int n = ty + j * 8;
        float v = t[tx][n];
        __nv_bfloat16 h = __float2bfloat16(v);
        __nv_bfloat16 l = __float2bfloat16(v - __bfloat162float(h));
        hiT[(size_t)(n0 + n) * K + k0 + tx] = h;
        loT[(size_t)(n0 + n) * K + k0 + tx] = l;
    }
}

// w [K,N] fp32 -> [N,K] fp16 single
__global__ void transpose_h_kernel(const float* __restrict__ w,
                                   __half* __restrict__ wT, int K, int N)
{
    __shared__ float t[32][33];
    const int n0 = blockIdx.x * 32, k0 = blockIdx.y * 32;
    const int tx = threadIdx.x, ty = threadIdx.y;
#pragma unroll
    for (int j = 0; j < 4; j++)
        t[ty + j * 8][tx] = w[(size_t)(k0 + ty + j * 8) * N + n0 + tx];
    __syncthreads();
#pragma unroll
    for (int j = 0; j < 4; j++) {
        const int n = ty + j * 8;
        wT[(size_t)(n0 + n) * K + k0 + tx] = __float2half(t[tx][n]);
    }
}

// ---------------------------------------------------------------------------
// GEMM 1 (qkv): bf16 3-pass, single-sync 3-stage pipeline.
// Epilogue: sec0 -> Q bf16 pair *log2e/8; sec1 -> K bf16 pair; sec2 -> V fp16.
// ---------------------------------------------------------------------------
#define G_STAGE 65536
#define G_SMEM  (3 * G_STAGE)

__device__ __forceinline__ void qkv_load_chunk(
    uint32_t sb, const __nv_bfloat16* Ahi, const __nv_bfloat16* Alo,
    const __nv_bfloat16* Bhi, const __nv_bfloat16* Blo,
    int rowBase, int colBase, int K, int kc, int stage, int tid)
{
    const uint32_t base = sb + stage * G_STAGE;
    const int k0 = kc * 64;
    const __nv_bfloat16* srcs[4] = { Ahi, Alo, Bhi, Blo };
#pragma unroll
    for (int t = 0; t < 4; t++) {
        const __nv_bfloat16* src = srcs[t];
        const int gb = (t < 2) ? rowBase : colBase;
        const uint32_t soff = base + t * 16384;
#pragma unroll
        for (int i = 0; i < 4; i++) {
            const int seg = tid + i * 256;
            const int r = seg >> 3, g = seg & 7;
            cpa16(soff + SWZ(r * 128 + g * 16),
                  src + (size_t)(gb + r) * K + k0 + g * 8);
        }
    }
    cpa_commit();
}

__global__ __launch_bounds__(256, 1)
void gemm_qkv_kernel(const __nv_bfloat16* __restrict__ Ahi, const __nv_bfloat16* __restrict__ Alo,
                     const __nv_bfloat16* __restrict__ Bhi, const __nv_bfloat16* __restrict__ Blo,
                     const float* __restrict__ bias,
                     __nv_bfloat16* __restrict__ Chi, __nv_bfloat16* __restrict__ Clo,
                     int M, int N, int K)
{
    extern __shared__ char smem[];
    const uint32_t sb = smem_u32(smem);
    const int tid = threadIdx.x, wid = tid >> 5, lane = tid & 31;
    const int wm = wid >> 2, wn = wid & 3;
    const int rowBase = blockIdx.y * 128, colBase = blockIdx.x * 128;
    const int NK = K / 64;   // 12

    float c[4][4][4];
#pragma unroll
    for (int i = 0; i < 4; i++)
#pragma unroll
        for (int j = 0; j < 4; j++)
#pragma unroll
            for (int k = 0; k < 4; k++) c[i][j][k] = 0.f;

    qkv_load_chunk(sb, Ahi, Alo, Bhi, Blo, rowBase, colBase, K, 0, 0, tid);
    qkv_load_chunk(sb, Ahi, Alo, Bhi, Blo, rowBase, colBase, K, 1, 1, tid);

    const int aRow = wm * 64 + (lane & 15);
    const uint32_t aSegOff = ((lane >> 4) & 1) * 16;
    const int bRow4 = wn * 32 + ((lane >> 4) & 1) * 8 + (lane & 7);
    const uint32_t bSegOff = ((lane >> 3) & 1) * 16;

    for (int kc = 0; kc < NK; kc++) {
        if (kc + 1 < NK) asm volatile("cp.async.wait_group 1;" ::: "memory");
        else             asm volatile("cp.async.wait_group 0;" ::: "memory");
        __syncthreads();
        if (kc + 2 < NK)
            qkv_load_chunk(sb, Ahi, Alo, Bhi, Blo, rowBase, colBase, K,
                           kc + 2, (kc + 2) % 3, tid);
        const uint32_t st = sb + (kc % 3) * G_STAGE;
#pragma unroll
        for (int ks = 0; ks < 4; ks++) {
            uint32_t bh[4][2], bl[4][2];
#pragma unroll
            for (int nj = 0; nj < 4; nj += 2) {
                const uint32_t boff = SWZ((uint32_t)(bRow4 + nj * 8) * 128 + ks * 32 + bSegOff);
                ldsm_x4(bh[nj][0], bh[nj][1], bh[nj + 1][0], bh[nj + 1][1], st + 32768 + boff);
                ldsm_x4(bl[nj][0], bl[nj][1], bl[nj + 1][0], bl[nj + 1][1], st + 49152 + boff);
            }
#pragma unroll
            for (int mi = 0; mi < 4; mi++) {
                uint32_t ah[4], al[4];
                const uint32_t aoff = SWZ((uint32_t)(aRow + mi * 16) * 128 + ks * 32 + aSegOff);
                ldsm_x4(ah[0], ah[1], ah[2], ah[3], st + aoff);
                ldsm_x4(al[0], al[1], al[2], al[3], st + 16384 + aoff);
#pragma unroll
                for (int nj = 0; nj < 4; nj++) {
                    mma_bf16(c[mi][nj], ah, bh[nj][0], bh[nj][1]);
                    mma_bf16(c[mi][nj], al, bh[nj][0], bh[nj][1]);
                    mma_bf16(c[mi][nj], ah, bl[nj][0], bl[nj][1]);
                }
            }
        }
    }

    const int g = lane >> 2, q2 = (lane & 3) * 2;
    const int sec = colBase / 768;                 // block-uniform
    const float scl = (sec == 0) ? 0.18033688f : 1.0f;
#pragma unroll
    for (int mi = 0; mi < 4; mi++) {
        const int row0 = rowBase + wm * 64 + mi * 16 + g;
#pragma unroll
        for (int nj = 0; nj < 4; nj++) {
            const int col = colBase + wn * 32 + nj * 8 + q2;
            const float bx = bias[col], by = bias[col + 1];
            const float a0 = c[mi][nj][0] + bx, a1 = c[mi][nj][1] + by;
            const float a2 = c[mi][nj][2] + bx, a3 = c[mi][nj][3] + by;
            if (sec == 2) {
                __half2 v0 = __floats2half2_rn(a0, a1);
                __half2 v1 = __floats2half2_rn(a2, a3);
                *(uint32_t*)(Chi + (size_t)row0 * N + col) = *(uint32_t*)&v0;
                *(uint32_t*)(Chi + (size_t)(row0 + 8) * N + col) = *(uint32_t*)&v1;
            } else {
                uint32_t h0, l0, h1, l1;
                split2t(a0 * scl, a1 * scl, h0, l0);
                split2t(a2 * scl, a3 * scl, h1, l1);
                *(uint32_t*)(Chi + (size_t)row0 * N + col) = h0;
                *(uint32_t*)(Clo + (size_t)row0 * N + col) = l0;
                *(uint32_t*)(Chi + (size_t)(row0 + 8) * N + col) = h1;
                *(uint32_t*)(Clo + (size_t)(row0 + 8) * N + col) = l1;
            }
        }
    }
}

// ---------------------------------------------------------------------------
// GEMM 3 (proj): fp16 2-pass (A hi/lo fp16, B single fp16), fp32 out.
// ---------------------------------------------------------------------------
#define P_STAGE 49152
#define P_SMEM  (3 * P_STAGE)

__device__ __forceinline__ void proj_load_chunk(
    uint32_t sb, const __nv_bfloat16* Ahi, const __nv_bfloat16* Alo,
    const __half* Bm, int rowBase, int colBase, int K, int kc, int stage, int tid)
{
    const uint32_t base = sb + stage * P_STAGE;
    const int k0 = kc * 64;
#pragma unroll
    for (int i = 0; i < 4; i++) {
        const int seg = tid + i * 256;
        const int r = seg >> 3, g = seg & 7;
        const uint32_t soff = SWZ(r * 128 + g * 16);
        cpa16(base + soff,         Ahi + (size_t)(rowBase + r) * K + k0 + g * 8);
        cpa16(base + 16384 + soff, Alo + (size_t)(rowBase + r) * K + k0 + g * 8);
        cpa16(base + 32768 + soff, Bm  + (size_t)(colBase + r) * K + k0 + g * 8);
    }
    cpa_commit();
}

__global__ __launch_bounds__(256, 1)
void gemm_proj_kernel(const __nv_bfloat16* __restrict__ Ahi, const __nv_bfloat16* __restrict__ Alo,
                      const __half* __restrict__ Bm,
                      const float* __restrict__ bias, float* __restrict__ Cm,
                      int M, int N, int K)
{
    extern __shared__ char smem[];
    const uint32_t sb = smem_u32(smem);
    const int tid = threadIdx.x, wid = tid >> 5, lane = tid & 31;
    const int wm = wid >> 2, wn = wid & 3;
    const int rowBase = blockIdx.y * 128, colBase = blockIdx.x * 128;
    const int NK = K / 64;

    float c[4][4][4];
#pragma unroll
    for (int i = 0; i < 4; i++)
#pragma unroll
        for (int j = 0; j < 4; j++)
#pragma unroll
            for (int k = 0; k < 4; k++) c[i][j][k] = 0.f;

    proj_load_chunk(sb, Ahi, Alo, Bm, rowBase, colBase, K, 0, 0, tid);
    proj_load_chunk(sb, Ahi, Alo, Bm, rowBase, colBase, K, 1, 1, tid);

    const int aRow = wm * 64 + (lane & 15);
    const uint32_t aSegOff = ((lane >> 4) & 1) * 16;
    const int bRow4 = wn * 32 + ((lane >> 4) & 1) * 8 + (lane & 7);
    const uint32_t bSegOff = ((lane >> 3) & 1) * 16;

    for (int kc = 0; kc < NK; kc++) {
        if (kc + 1 < NK) asm volatile("cp.async.wait_group 1;" ::: "memory");
        else             asm volatile("cp.async.wait_group 0;" ::: "memory");
        __syncthreads();
        if (kc + 2 < NK)
            proj_load_chunk(sb, Ahi, Alo, Bm, rowBase, colBase, K,
                            kc + 2, (kc + 2) % 3, tid);
        const uint32_t st = sb + (kc % 3) * P_STAGE;
#pragma unroll
        for (int ks = 0; ks < 4; ks++) {
            uint32_t bf[4][2];
#pragma unroll
            for (int nj = 0; nj < 4; nj += 2) {
                const uint32_t boff = SWZ((uint32_t)(bRow4 + nj * 8) * 128 + ks * 32 + bSegOff);
                ldsm_x4(bf[nj][0], bf[nj][1], bf[nj + 1][0], bf[nj + 1][1], st + 32768 + boff);
            }
#pragma unroll
            for (int mi = 0; mi < 4; mi++) {
                uint32_t ah[4], al[4];
                const uint32_t aoff = SWZ((uint32_t)(aRow + mi * 16) * 128 + ks * 32 + aSegOff);
                ldsm_x4(ah[0], ah[1], ah[2], ah[3], st + aoff);
                ldsm_x4(al[0], al[1], al[2], al[3], st + 16384 + aoff);
#pragma unroll
                for (int nj = 0; nj < 4; nj++) {
                    mma_f16(c[mi][nj], ah, bf[nj][0], bf[nj][1]);
                    mma_f16(c[mi][nj], al, bf[nj][0], bf[nj][1]);
                }
            }
        }
    }

    const int g = lane >> 2, q2 = (lane & 3) * 2;
#pragma unroll
    for (int mi = 0; mi < 4; mi++) {
        const int row0 = rowBase + wm * 64 + mi * 16 + g;
#pragma unroll
        for (int nj = 0; nj < 4; nj++) {
            const int col = colBase + wn * 32 + nj * 8 + q2;
            const float bx = bias[col], by = bias[col + 1];
            float2 v0 = make_float2(c[mi][nj][0] + bx, c[mi][nj][1] + by);
            float2 v1 = make_float2(c[mi][nj][2] + bx, c[mi][nj][3] + by);
            *(float2*)(Cm + (size_t)row0 * N + col) = v0;
            *(float2*)(Cm + (size_t)(row0 + 8) * N + col) = v1;
        }
    }
}

// ---------------------------------------------------------------------------
// Flash attention: S bf16 3-pass (interleaved with softmax), PV fp16 2-pass.
// Single-sync 3-stage ring, stage = Khi 8K | Klo 8K | Vf16 8K = 24K.
// smem: Q 32K + 3x24K = 104K.
// ---------------------------------------------------------------------------
#define SM_QHI 0
#define SM_QLO 16384
#define SM_ST  32768
#define A_STAGE 24576
#define A_SMEM (SM_ST + 3 * A_STAGE)

__device__ __forceinline__ void attn_load_kv(
    uint32_t sb, const __nv_bfloat16* qkvh, const __nv_bfloat16* qkvl,
    size_t base0, int kBase, int stage, int tid)
{
    const uint32_t st = sb + SM_ST + stage * A_STAGE;
#pragma unroll
    for (int i = 0; i < 2; i++) {
        const int seg = tid + i * 256;
        const int r = seg >> 3, gsg = seg & 7;
        const size_t goff = base0 + (size_t)(kBase + r) * QKVC_ + gsg * 8;
        const uint32_t soff = SWZ((uint32_t)r * 128 + gsg * 16);
        cpa16(st + soff,         qkvh + goff + 768);    // K hi (bf16)
        cpa16(st + 8192 + soff,  qkvl + goff + 768);    // K lo (bf16)
        cpa16(st + 16384 + soff, qkvh + goff + 1536);   // V (fp16)
    }
    cpa_commit();
}

__global__ __launch_bounds__(256, 1)
void attn_mma_kernel(const __nv_bfloat16* __restrict__ qkvh,
                     const __nv_bfloat16* __restrict__ qkvl,
                     __nv_bfloat16* __restrict__ yhi, __nv_bfloat16* __restrict__ ylo)
{
    extern __shared__ char smem[];
    const uint32_t sb = smem_u32(smem);
    const int qt = (int)gridDim.x - 1 - (int)blockIdx.x;
    const int bh = blockIdx.y;
    const int b = bh / H_, h = bh % H_;
    const int tid = threadIdx.x, wid = tid >> 5, lane = tid & 31;
    const int qBase = qt * 128;
    const size_t base0 = (size_t)b * T_ * QKVC_ + h * 64;
    const int ktMax = 2 * qt + 1;

    // ---- prologue: Q (g0), KV0 (g1), KV1 (g2) ----
#pragma unroll
    for (int i = 0; i < 4; i++) {
        const int seg = tid + i * 256;
        const int r = seg >> 3, gsg = seg & 7;
        const size_t goff = base0 + (size_t)(qBase + r) * QKVC_ + gsg * 8;
        const uint32_t soff = SWZ((uint32_t)r * 128 + gsg * 16);
        cpa16(sb + SM_QHI + soff, qkvh + goff);
        cpa16(sb + SM_QLO + soff, qkvl + goff);
    }
    cpa_commit();
    attn_load_kv(sb, qkvh, qkvl, base0, 0,  0, tid);
    attn_load_kv(sb, qkvh, qkvl, base0, 64, 1, tid);
    asm volatile("cp.async.wait_group 1;" ::: "memory");   // Q + KV0 ready
    __syncthreads();

    // ---- Q fragments ----
    uint32_t qh[4][4], ql[4][4];
    {
        const int aRow = wid * 16 + (lane & 15);
        const uint32_t aSeg = ((lane >> 4) & 1) * 16;
#pragma unroll
        for (int ks = 0; ks < 4; ks++) {
            const uint32_t aoff = SWZ((uint32_t)aRow * 128 + ks * 32 + aSeg);
            ldsm_x4(qh[ks][0], qh[ks][1], qh[ks][2], qh[ks][3], sb + SM_QHI + aoff);
            ldsm_x4(ql[ks][0], ql[ks][1], ql[ks][2], ql[ks][3], sb + SM_QLO + aoff);
        }
    }

    float o[8][4];
#pragma unroll
    for (int d = 0; d < 8; d++)
#pragma unroll
        for (int k = 0; k < 4; k++) o[d][k] = 0.f;
    float m0 = -1e30f, m1 = -1e30f, l0s = 0.f, l1s = 0.f;

    const int g = lane >> 2, q2 = (lane & 3) * 2;
    const int qRowMin = qBase + wid * 16;
    const int row0 = qRowMin + g;
    const int wktMax = (qRowMin + 15) >> 6;

    const int bRow4 = ((lane >> 4) & 1) * 8 + (lane & 7);
    const uint32_t bSeg = ((lane >> 3) & 1) * 16;
    const int vRowL = lane & 15;
    const uint32_t vSeg = ((lane >> 4) & 1) * 16;

    // ---- S(0) ----
    float sc[8][4];
    {
        const uint32_t st0 = sb + SM_ST;
#pragma unroll
        for (int nj = 0; nj < 8; nj += 2) {
#pragma unroll
            for (int k = 0; k < 4; k++) { sc[nj][k] = 0.f; sc[nj + 1][k] = 0.f; }
#pragma unroll
            for (int ks = 0; ks < 4; ks++) {
                const uint32_t boff = SWZ((uint32_t)(nj * 8 + bRow4) * 128 + ks * 32 + bSeg);
                uint32_t k0, k1, k2, k3;
                ldsm_x4(k0, k1, k2, k3, st0 + boff);
                mma_bf16(sc[nj],     qh[ks], k0, k1);
                mma_bf16(sc[nj],     ql[ks], k0, k1);
                mma_bf16(sc[nj + 1], qh[ks], k2, k3);
                mma_bf16(sc[nj + 1], ql[ks], k2, k3);
                ldsm_x4(k0, k1, k2, k3, st0 + 8192 + boff);
                mma_bf16(sc[nj],     qh[ks], k0, k1);
                mma_bf16(sc[nj + 1], qh[ks], k2, k3);
            }
        }
    }

    for (int kt = 0; kt <= ktMax; kt++) {
        const int kBase = kt * 64;
        asm volatile("cp.async.wait_group 0;" ::: "memory");   // KV(kt+1) ready
        __syncthreads();                                        // all warps past kt-1
        if (kt + 2 <= ktMax)
            attn_load_kv(sb, qkvh, qkvl, base0, (kt + 2) * 64, (kt + 2) % 3, tid);

        const bool doP = (kt <= wktMax);
        const bool doS = (kt + 1 <= ktMax) && (kt + 1 <= wktMax);

        if (doP) {
            const uint32_t stP = sb + SM_ST + (kt % 3) * A_STAGE;
            const uint32_t stS = sb + SM_ST + ((kt + 1) % 3) * A_STAGE;

            if (kBase + 63 > qRowMin) {
#pragma unroll
                for (int nj = 0; nj < 8; nj++) {
                    const int col = kBase + nj * 8 + q2;
                    if (col > row0)         sc[nj][0] = -1e30f;
                    if (col + 1 > row0)     sc[nj][1] = -1e30f;
                    if (col > row0 + 8)     sc[nj][2] = -1e30f;
                    if (col + 1 > row0 + 8) sc[nj][3] = -1e30f;
                }
            }

            float mx0 = -1e30f, mx1 = -1e30f;
#pragma unroll
            for (int nj = 0; nj < 8; nj++) {
                mx0 = fmaxf(mx0, fmaxf(sc[nj][0], sc[nj][1]));
                mx1 = fmaxf(mx1, fmaxf(sc[nj][2], sc[nj][3]));
            }
            mx0 = fmaxf(mx0, __shfl_xor_sync(0xffffffffu, mx0, 1));
            mx0 = fmaxf(mx0, __shfl_xor_sync(0xffffffffu, mx0, 2));
            mx1 = fmaxf(mx1, __shfl_xor_sync(0xffffffffu, mx1, 1));
            mx1 = fmaxf(mx1, __shfl_xor_sync(0xffffffffu, mx1, 2));
            const float mn0 = fmaxf(m0, mx0), mn1 = fmaxf(m1, mx1);
            const float al0 = ex2_(m0 - mn0), al1 = ex2_(m1 - mn1);
            m0 = mn0; m1 = mn1;

            float s0 = 0.f, s1 = 0.f;
            float sn[8][4];
            if (doS) {
#pragma unroll
                for (int nj = 0; nj < 8; nj += 2) {
#pragma unroll
                    for (int k = 0; k < 4; k++) { sn[nj][k] = 0.f; sn[nj + 1][k] = 0.f; }
#pragma unroll
                    for (int ks = 0; ks < 4; ks++) {
                        const uint32_t boff = SWZ((uint32_t)(nj * 8 + bRow4) * 128 + ks * 32 + bSeg);
                        uint32_t k0, k1, k2, k3;
                        ldsm_x4(k0, k1, k2, k3, stS + boff);
                        mma_bf16(sn[nj],     qh[ks], k0, k1);
                        mma_bf16(sn[nj],     ql[ks], k0, k1);
                        mma_bf16(sn[nj + 1], qh[ks], k2, k3);
                        mma_bf16(sn[nj + 1], ql[ks], k2, k3);
                        ldsm_x4(k0, k1, k2, k3, stS + 8192 + boff);
                        mma_bf16(sn[nj],     qh[ks], k0, k1);
                        mma_bf16(sn[nj + 1], qh[ks], k2, k3);
                    }
#pragma unroll
                    for (int u = 0; u < 2; u++) {
                        sc[nj + u][0] = ex2_(sc[nj + u][0] - mn0);
                        sc[nj + u][1] = ex2_(sc[nj + u][1] - mn0);
                        sc[nj + u][2] = ex2_(sc[nj + u][2] - mn1);
                        sc[nj + u][3] = ex2_(sc[nj + u][3] - mn1);
                        s0 += sc[nj + u][0] + sc[nj + u][1];
                        s1 += sc[nj + u][2] + sc[nj + u][3];
                    }
                }
            } else {
#pragma unroll
                for (int nj = 0; nj < 8; nj++) {
                    sc[nj][0] = ex2_(sc[nj][0] - mn0);
                    sc[nj][1] = ex2_(sc[nj][1] - mn0);
                    sc[nj][2] = ex2_(sc[nj][2] - mn1);
                    sc[nj][3] = ex2_(sc[nj][3] - mn1);
                    s0 += sc[nj][0] + sc[nj][1];
                    s1 += sc[nj][2] + sc[nj][3];
                }
            }
            s0 += __shfl_xor_sync(0xffffffffu, s0, 1);
            s0 += __shfl_xor_sync(0xffffffffu, s0, 2);
            s1 += __shfl_xor_sync(0xffffffffu, s1, 1);
            s1 += __shfl_xor_sync(0xffffffffu, s1, 2);
            l0s = l0s * al0 + s0;
            l1s = l1s * al1 + s1;

            // ---- P fragments (fp16 hi/lo) ----
            uint32_t ph[4][4], pl[4][4];
#pragma unroll
            for (int ks = 0; ks < 4; ks++) {
                split2h(sc[2 * ks][0],     sc[2 * ks][1],     ph[ks][0], pl[ks][0]);
                split2h(sc[2 * ks][2],     sc[2 * ks][3],     ph[ks][1], pl[ks][1]);
                split2h(sc[2 * ks + 1][0], sc[2 * ks + 1][1], ph[ks][2], pl[ks][2]);
                split2h(sc[2 * ks + 1][2], sc[2 * ks + 1][3], ph[ks][3], pl[ks][3]);
            }

            // ---- PV(kt) fp16 2-pass + O rescale ----
#pragma unroll
            for (int dj = 0; dj < 8; dj += 2) {
#pragma unroll
                for (int u = 0; u < 2; u++) {
                    o[dj + u][0] *= al0; o[dj + u][1] *= al0;
                    o[dj + u][2] *= al1; o[dj + u][3] *= al1;
                }
#pragma unroll
                for (int ks = 0; ks < 4; ks++) {
                    const uint32_t voff = SWZ((uint32_t)(ks * 16 + vRowL) * 128 + dj * 16 + vSeg);
                    uint32_t v0, v1, v2, v3;
                    ldsm_x4t(v0, v1, v2, v3, stP + 16384 + voff);
                    mma_f16(o[dj],     ph[ks], v0, v1);
                    mma_f16(o[dj],     pl[ks], v0, v1);
                    mma_f16(o[dj + 1], ph[ks], v2, v3);
                    mma_f16(o[dj + 1], pl[ks], v2, v3);
                }
            }

            if (doS) {
#pragma unroll
                for (int nj = 0; nj < 8; nj++)
#pragma unroll
                    for (int k = 0; k < 4; k++) sc[nj][k] = sn[nj][k];
            }
        }
    }

    // ---- epilogue: O/l -> fp16 hi/lo for proj GEMM ----
    const float inv0 = 1.0f / l0s, inv1 = 1.0f / l1s;
#pragma unroll
    for (int dj = 0; dj < 8; dj++) {
        uint32_t h0, l0, h1, l1;
        split2h(o[dj][0] * inv0, o[dj][1] * inv0, h0, l0);
        split2h(o[dj][2] * inv1, o[dj][3] * inv1, h1, l1);
        const size_t r0 = ((size_t)b * T_ + row0) * C_ + h * 64 + dj * 8 + q2;
        const size_t r1 = r0 + 8 * C_;
        *(uint32_t*)(yhi + r0) = h0;
        *(uint32_t*)(ylo + r0) = l0;
        *(uint32_t*)(yhi + r1) = h1;
        *(uint32_t*)(ylo + r1) = l1;
    }
}

// ---------------------------------------------------------------------------
extern "C" void kernel_launch(void* const* d_in, const int* in_sizes, int n_in,
                              void* d_out, int out_size)
{
    const float* x      = (const float*)d_in[0];
    const float* w_attn = (const float*)d_in[1];
    const float* b_attn = (const float*)d_in[2];
    const float* w_proj = (const float*)d_in[3];
    const float* b_proj = (const float*)d_in[4];
    float* out = (float*)d_out;

    __nv_bfloat16 *qkvhi, *qkvlo, *xhi, *xlo, *yhi, *ylo, *wah, *wal, *wph;
    cudaGetSymbolAddress((void**)&qkvhi, g_qkvhi);
    cudaGetSymbolAddress((void**)&qkvlo, g_qkvlo);
    cudaGetSymbolAddress((void**)&xhi, g_xhi);
    cudaGetSymbolAddress((void**)&xlo, g_xlo);
    cudaGetSymbolAddress((void**)&yhi, g_yhi);
    cudaGetSymbolAddress((void**)&ylo, g_ylo);
    cudaGetSymbolAddress((void**)&wah, g_wa_hi);
    cudaGetSymbolAddress((void**)&wal, g_wa_lo);
    cudaGetSymbolAddress((void**)&wph, g_wp_h);

    cudaFuncSetAttribute(gemm_qkv_kernel,
                         cudaFuncAttributeMaxDynamicSharedMemorySize, G_SMEM);
    cudaFuncSetAttribute(gemm_proj_kernel,
                         cudaFuncAttributeMaxDynamicSharedMemorySize, P_SMEM);
    cudaFuncSetAttribute(attn_mma_kernel,
                         cudaFuncAttributeMaxDynamicSharedMemorySize, A_SMEM);

    // input/weight conversions
    {
        int n4 = ROWS_ * C_ / 4;
        split_rows_kernel<<<(n4 + 255) / 256, 256>>>(x, xhi, xlo, n4);
        dim3 bt(32, 8);
        split_transpose_kernel<<<dim3(QKVC_ / 32, C_ / 32), bt>>>(w_attn, wah, wal, C_, QKVC_);
        transpose_h_kernel<<<dim3(C_ / 32, C_ / 32), bt>>>(w_proj, (__half*)wph, C_, C_);
    }
    // Stage 1: qkv GEMM -> Q,K bf16 hi/lo + V fp16
    {
        dim3 grid(QKVC_ / 128, ROWS_ / 128);
        gemm_qkv_kernel<<<grid, 256, G_SMEM>>>(xhi, xlo, wah, wal, b_attn,
                                               qkvhi, qkvlo, ROWS_, QKVC_, C_);
    }
    // Stage 2: attention -> y fp16 hi/lo
    {
        dim3 grid(T_ / 128, B_ * H_);
        attn_mma_kernel<<<grid, 256, A_SMEM>>>(qkvhi, qkvlo, yhi, ylo);
    }
    // Stage 3: out = y @ w_proj + b_proj  (fp16 2-pass)
    {
        dim3 grid(C_ / 128, ROWS_ / 128);
        gemm_proj_kernel<<<grid, 256, P_SMEM>>>(yhi, ylo, (const __half*)wph,
                                                b_proj, out, ROWS_, C_, C_);
    }
}

// round 12
// speedup vs baseline: 2.1022x; 1.1947x over previous
#include <cuda_runtime.h>
#include <cuda_bf16.h>
#include <cuda_fp16.h>
#include <cstdint>

// ---------------------------------------------------------------------------
// CausalSelfAttention on GB300 (sm_103 family target — no 'a' features).
// Uniform fp16 2-pass mma.sync scheme:
//   gemm1 (qkv):  x fp16 hi/lo × w_attn fp16 single -> Q,K fp16 hi/lo, V fp16
//   attention:    S = Q(hi/lo) × K(single) 2-pass; PV = P(hi/lo) × V(single)
//   gemm3 (proj): y fp16 hi/lo × w_proj fp16 single -> fp32 out
// ---------------------------------------------------------------------------

#define B_ 4
#define T_ 2048
#define C_ 768
#define H_ 12
#define ROWS_ 8192
#define QKVC_ 2304

// ---------------- scratch (fp16 payload in 2-byte arrays) -------------------
__device__ __align__(256) __half  g_qkvhi[ROWS_ * QKVC_];   // Q,K hi; V single
__device__ __align__(256) __half  g_qkvlo[ROWS_ * QKVC_];   // Q,K lo
__device__ __align__(256) __half  g_xhi[ROWS_ * C_];
__device__ __align__(256) __half  g_xlo[ROWS_ * C_];
__device__ __align__(256) __half  g_yhi[ROWS_ * C_];
__device__ __align__(256) __half  g_ylo[ROWS_ * C_];
__device__ __align__(256) __half  g_wa[QKVC_ * C_];         // w_attn^T fp16
__device__ __align__(256) __half  g_wp[C_ * C_];            // w_proj^T fp16

// ---------------- helpers ---------------------------------------------------
__device__ __forceinline__ uint32_t smem_u32(const void* p) {
    uint32_t a;
    asm("{ .reg .u64 t; cvta.to.shared.u64 t, %1; cvt.u32.u64 %0, t; }"
        : "=r"(a) : "l"(p));
    return a;
}
#define SWZ(x) ((x) ^ (((x) >> 3) & 0x70))

__device__ __forceinline__ void cpa16(uint32_t dst, const void* src) {
    asm volatile("cp.async.cg.shared.global [%0], [%1], 16;" :: "r"(dst), "l"(src));
}
__device__ __forceinline__ void cpa_commit() { asm volatile("cp.async.commit_group;"); }

__device__ __forceinline__ void ldsm_x4(uint32_t& r0, uint32_t& r1, uint32_t& r2,
                                        uint32_t& r3, uint32_t addr) {
    asm volatile("ldmatrix.sync.aligned.m8n8.x4.shared.b16 {%0,%1,%2,%3}, [%4];"
                 : "=r"(r0), "=r"(r1), "=r"(r2), "=r"(r3) : "r"(addr));
}
__device__ __forceinline__ void ldsm_x4t(uint32_t& r0, uint32_t& r1, uint32_t& r2,
                                         uint32_t& r3, uint32_t addr) {
    asm volatile("ldmatrix.sync.aligned.m8n8.x4.trans.shared.b16 {%0,%1,%2,%3}, [%4];"
                 : "=r"(r0), "=r"(r1), "=r"(r2), "=r"(r3) : "r"(addr));
}
__device__ __forceinline__ void mma_f16(float* c, const uint32_t* a,
                                        uint32_t b0, uint32_t b1) {
    asm volatile("mma.sync.aligned.m16n8k16.row.col.f32.f16.f16.f32 "
                 "{%0,%1,%2,%3}, {%4,%5,%6,%7}, {%8,%9}, {%0,%1,%2,%3};"
                 : "+f"(c[0]), "+f"(c[1]), "+f"(c[2]), "+f"(c[3])
                 : "r"(a[0]), "r"(a[1]), "r"(a[2]), "r"(a[3]), "r"(b0), "r"(b1));
}
__device__ __forceinline__ float ex2_(float x) {
    float r; asm("ex2.approx.f32 %0, %1;" : "=f"(r) : "f"(x)); return r;
}
// fp16 hi/lo split
__device__ __forceinline__ void split2h(float a, float b, uint32_t& h, uint32_t& l) {
    __half2 hh = __floats2half2_rn(a, b);
    float2 hf = __half22float2(hh);
    __half2 ll = __floats2half2_rn(a - hf.x, b - hf.y);
    h = *(uint32_t*)&hh;
    l = *(uint32_t*)&ll;
}

// ---------------------------------------------------------------------------
// Conversion kernels
// ---------------------------------------------------------------------------
__global__ void split_rows_h_kernel(const float* __restrict__ in,
                                    __half* __restrict__ hi,
                                    __half* __restrict__ lo, int n4)
{
    int i = blockIdx.x * blockDim.x + threadIdx.x;
    if (i >= n4) return;
    float4 v = ((const float4*)in)[i];
    uint32_t h0, l0, h1, l1;
    split2h(v.x, v.y, h0, l0);
    split2h(v.z, v.w, h1, l1);
    uint32_t* hp = (uint32_t*)(hi + 4 * (size_t)i);
    uint32_t* lp = (uint32_t*)(lo + 4 * (size_t)i);
    hp[0] = h0; hp[1] = h1;
    lp[0] = l0; lp[1] = l1;
}

// w [K,N] fp32 -> [N,K] fp16 single
__global__ void transpose_h_kernel(const float* __restrict__ w,
                                   __half* __restrict__ wT, int K, int N)
{
    __shared__ float t[32][33];
    const int n0 = blockIdx.x * 32, k0 = blockIdx.y * 32;
    const int tx = threadIdx.x, ty = threadIdx.y;
#pragma unroll
    for (int j = 0; j < 4; j++)
        t[ty + j * 8][tx] = w[(size_t)(k0 + ty + j * 8) * N + n0 + tx];
    __syncthreads();
#pragma unroll
    for (int j = 0; j < 4; j++) {
        const int n = ty + j * 8;
        wT[(size_t)(n0 + n) * K + k0 + tx] = __float2half(t[tx][n]);
    }
}

// ---------------------------------------------------------------------------
// fp16 2-pass GEMM: C = (Ahi+Alo)[M,K] @ B[N,K]^T + bias
// EPI 0: fp32 out.  EPI 1: qkv epilogue (Q,K fp16 hi/lo w/ Q scale; V single).
// 128x128 tile, BK=64, 8 warps, 3-stage single-sync cp.async pipeline.
// ---------------------------------------------------------------------------
#define P_STAGE 49152          // Ahi 16K | Alo 16K | B 16K
#define P_SMEM  (3 * P_STAGE)

__device__ __forceinline__ void f16_load_chunk(
    uint32_t sb, const __half* Ahi, const __half* Alo, const __half* Bm,
    int rowBase, int colBase, int K, int kc, int stage, int tid)
{
    const uint32_t base = sb + stage * P_STAGE;
    const int k0 = kc * 64;
#pragma unroll
    for (int i = 0; i < 4; i++) {
        const int seg = tid + i * 256;
        const int r = seg >> 3, g = seg & 7;
        const uint32_t soff = SWZ(r * 128 + g * 16);
        cpa16(base + soff,         Ahi + (size_t)(rowBase + r) * K + k0 + g * 8);
        cpa16(base + 16384 + soff, Alo + (size_t)(rowBase + r) * K + k0 + g * 8);
        cpa16(base + 32768 + soff, Bm  + (size_t)(colBase + r) * K + k0 + g * 8);
    }
    cpa_commit();
}

template <int EPI>
__global__ __launch_bounds__(256, 1)
void gemm_f16_kernel(const __half* __restrict__ Ahi, const __half* __restrict__ Alo,
                     const __half* __restrict__ Bm,
                     const float* __restrict__ bias, float* __restrict__ Cm,
                     __half* __restrict__ Chi, __half* __restrict__ Clo,
                     int M, int N, int K)
{
    extern __shared__ char smem[];
    const uint32_t sb = smem_u32(smem);
    const int tid = threadIdx.x, wid = tid >> 5, lane = tid & 31;
    const int wm = wid >> 2, wn = wid & 3;
    const int rowBase = blockIdx.y * 128, colBase = blockIdx.x * 128;
    const int NK = K / 64;

    float c[4][4][4];
#pragma unroll
    for (int i = 0; i < 4; i++)
#pragma unroll
        for (int j = 0; j < 4; j++)
#pragma unroll
            for (int k = 0; k < 4; k++) c[i][j][k] = 0.f;

    f16_load_chunk(sb, Ahi, Alo, Bm, rowBase, colBase, K, 0, 0, tid);
    f16_load_chunk(sb, Ahi, Alo, Bm, rowBase, colBase, K, 1, 1, tid);

    const int aRow = wm * 64 + (lane & 15);
    const uint32_t aSegOff = ((lane >> 4) & 1) * 16;
    const int bRow4 = wn * 32 + ((lane >> 4) & 1) * 8 + (lane & 7);
    const uint32_t bSegOff = ((lane >> 3) & 1) * 16;

    for (int kc = 0; kc < NK; kc++) {
        if (kc + 1 < NK) asm volatile("cp.async.wait_group 1;" ::: "memory");
        else             asm volatile("cp.async.wait_group 0;" ::: "memory");
        __syncthreads();
        if (kc + 2 < NK)
            f16_load_chunk(sb, Ahi, Alo, Bm, rowBase, colBase, K,
                           kc + 2, (kc + 2) % 3, tid);
        const uint32_t st = sb + (kc % 3) * P_STAGE;
#pragma unroll
        for (int ks = 0; ks < 4; ks++) {
            uint32_t bf[4][2];
#pragma unroll
            for (int nj = 0; nj < 4; nj += 2) {
                const uint32_t boff = SWZ((uint32_t)(bRow4 + nj * 8) * 128 + ks * 32 + bSegOff);
                ldsm_x4(bf[nj][0], bf[nj][1], bf[nj + 1][0], bf[nj + 1][1], st + 32768 + boff);
            }
#pragma unroll
            for (int mi = 0; mi < 4; mi++) {
                uint32_t ah[4], al[4];
                const uint32_t aoff = SWZ((uint32_t)(aRow + mi * 16) * 128 + ks * 32 + aSegOff);
                ldsm_x4(ah[0], ah[1], ah[2], ah[3], st + aoff);
                ldsm_x4(al[0], al[1], al[2], al[3], st + 16384 + aoff);
#pragma unroll
                for (int nj = 0; nj < 4; nj++) {
                    mma_f16(c[mi][nj], ah, bf[nj][0], bf[nj][1]);
                    mma_f16(c[mi][nj], al, bf[nj][0], bf[nj][1]);
                }
            }
        }
    }

    const int g = lane >> 2, q2 = (lane & 3) * 2;
    if (EPI == 0) {
#pragma unroll
        for (int mi = 0; mi < 4; mi++) {
            const int row0 = rowBase + wm * 64 + mi * 16 + g;
#pragma unroll
            for (int nj = 0; nj < 4; nj++) {
                const int col = colBase + wn * 32 + nj * 8 + q2;
                const float bx = bias[col], by = bias[col + 1];
                float2 v0 = make_float2(c[mi][nj][0] + bx, c[mi][nj][1] + by);
                float2 v1 = make_float2(c[mi][nj][2] + bx, c[mi][nj][3] + by);
                *(float2*)(Cm + (size_t)row0 * N + col) = v0;
                *(float2*)(Cm + (size_t)(row0 + 8) * N + col) = v1;
            }
        }
    } else {
        const int sec = colBase / 768;                 // block-uniform: 0=Q 1=K 2=V
        const float scl = (sec == 0) ? 0.18033688f : 1.0f;
#pragma unroll
        for (int mi = 0; mi < 4; mi++) {
            const int row0 = rowBase + wm * 64 + mi * 16 + g;
#pragma unroll
            for (int nj = 0; nj < 4; nj++) {
                const int col = colBase + wn * 32 + nj * 8 + q2;
                const float bx = bias[col], by = bias[col + 1];
                const float a0 = c[mi][nj][0] + bx, a1 = c[mi][nj][1] + by;
                const float a2 = c[mi][nj][2] + bx, a3 = c[mi][nj][3] + by;
                if (sec == 2) {
                    __half2 v0 = __floats2half2_rn(a0, a1);
                    __half2 v1 = __floats2half2_rn(a2, a3);
                    *(uint32_t*)(Chi + (size_t)row0 * N + col) = *(uint32_t*)&v0;
                    *(uint32_t*)(Chi + (size_t)(row0 + 8) * N + col) = *(uint32_t*)&v1;
                } else {
                    uint32_t h0, l0, h1, l1;
                    split2h(a0 * scl, a1 * scl, h0, l0);
                    split2h(a2 * scl, a3 * scl, h1, l1);
                    *(uint32_t*)(Chi + (size_t)row0 * N + col) = h0;
                    *(uint32_t*)(Clo + (size_t)row0 * N + col) = l0;
                    *(uint32_t*)(Chi + (size_t)(row0 + 8) * N + col) = h1;
                    *(uint32_t*)(Clo + (size_t)(row0 + 8) * N + col) = l1;
                }
            }
        }
    }
}

// ---------------------------------------------------------------------------
// Flash attention: S fp16 2-pass (Q hi/lo x K single), PV fp16 2-pass.
// Single-sync 3-stage ring, stage = K 8K | V 8K = 16K. smem: Q 32K + 48K.
// S(kt+1) interleaved with softmax(kt).
// ---------------------------------------------------------------------------
#define SM_QHI 0
#define SM_QLO 16384
#define SM_ST  32768
#define A_STAGE 16384
#define A_SMEM (SM_ST + 3 * A_STAGE)

__device__ __forceinline__ void attn_load_kv(
    uint32_t sb, const __half* qkvh, size_t base0, int kBase, int stage, int tid)
{
    const uint32_t st = sb + SM_ST + stage * A_STAGE;
#pragma unroll
    for (int i = 0; i < 2; i++) {
        const int seg = tid + i * 256;
        const int r = seg >> 3, gsg = seg & 7;
        const size_t goff = base0 + (size_t)(kBase + r) * QKVC_ + gsg * 8;
        const uint32_t soff = SWZ((uint32_t)r * 128 + gsg * 16);
        cpa16(st + soff,        qkvh + goff + 768);    // K (fp16 hi used as single)
        cpa16(st + 8192 + soff, qkvh + goff + 1536);   // V (fp16 single)
    }
    cpa_commit();
}

__global__ __launch_bounds__(256, 1)
void attn_mma_kernel(const __half* __restrict__ qkvh, const __half* __restrict__ qkvl,
                     __half* __restrict__ yhi, __half* __restrict__ ylo)
{
    extern __shared__ char smem[];
    const uint32_t sb = smem_u32(smem);
    const int qt = (int)gridDim.x - 1 - (int)blockIdx.x;
    const int bh = blockIdx.y;
    const int b = bh / H_, h = bh % H_;
    const int tid = threadIdx.x, wid = tid >> 5, lane = tid & 31;
    const int qBase = qt * 128;
    const size_t base0 = (size_t)b * T_ * QKVC_ + h * 64;
    const int ktMax = 2 * qt + 1;

    // ---- prologue: Q (g0), KV0 (g1), KV1 (g2) ----
#pragma unroll
    for (int i = 0; i < 4; i++) {
        const int seg = tid + i * 256;
        const int r = seg >> 3, gsg = seg & 7;
        const size_t goff = base0 + (size_t)(qBase + r) * QKVC_ + gsg * 8;
        const uint32_t soff = SWZ((uint32_t)r * 128 + gsg * 16);
        cpa16(sb + SM_QHI + soff, qkvh + goff);
        cpa16(sb + SM_QLO + soff, qkvl + goff);
    }
    cpa_commit();
    attn_load_kv(sb, qkvh, base0, 0,  0, tid);
    attn_load_kv(sb, qkvh, base0, 64, 1, tid);
    asm volatile("cp.async.wait_group 1;" ::: "memory");   // Q + KV0 ready
    __syncthreads();

    // ---- Q fragments (fp16 hi/lo) ----
    uint32_t qh[4][4], ql[4][4];
    {
        const int aRow = wid * 16 + (lane & 15);
        const uint32_t aSeg = ((lane >> 4) & 1) * 16;
#pragma unroll
        for (int ks = 0; ks < 4; ks++) {
            const uint32_t aoff = SWZ((uint32_t)aRow * 128 + ks * 32 + aSeg);
            ldsm_x4(qh[ks][0], qh[ks][1], qh[ks][2], qh[ks][3], sb + SM_QHI + aoff);
            ldsm_x4(ql[ks][0], ql[ks][1], ql[ks][2], ql[ks][3], sb + SM_QLO + aoff);
        }
    }

    float o[8][4];
#pragma unroll
    for (int d = 0; d < 8; d++)
#pragma unroll
        for (int k = 0; k < 4; k++) o[d][k] = 0.f;
    float m0 = -1e30f, m1 = -1e30f, l0s = 0.f, l1s = 0.f;

    const int g = lane >> 2, q2 = (lane & 3) * 2;
    const int qRowMin = qBase + wid * 16;
    const int row0 = qRowMin + g;
    const int wktMax = (qRowMin + 15) >> 6;

    const int bRow4 = ((lane >> 4) & 1) * 8 + (lane & 7);
    const uint32_t bSeg = ((lane >> 3) & 1) * 16;
    const int vRowL = lane & 15;
    const uint32_t vSeg = ((lane >> 4) & 1) * 16;

    // ---- S(0): 2-pass fp16 ----
    float sc[8][4];
    {
        const uint32_t st0 = sb + SM_ST;
#pragma unroll
        for (int nj = 0; nj < 8; nj += 2) {
#pragma unroll
            for (int k = 0; k < 4; k++) { sc[nj][k] = 0.f; sc[nj + 1][k] = 0.f; }
#pragma unroll
            for (int ks = 0; ks < 4; ks++) {
                const uint32_t boff = SWZ((uint32_t)(nj * 8 + bRow4) * 128 + ks * 32 + bSeg);
                uint32_t k0, k1, k2, k3;
                ldsm_x4(k0, k1, k2, k3, st0 + boff);
                mma_f16(sc[nj],     qh[ks], k0, k1);
                mma_f16(sc[nj],     ql[ks], k0, k1);
                mma_f16(sc[nj + 1], qh[ks], k2, k3);
                mma_f16(sc[nj + 1], ql[ks], k2, k3);
            }
        }
    }

    for (int kt = 0; kt <= ktMax; kt++) {
        const int kBase = kt * 64;
        asm volatile("cp.async.wait_group 0;" ::: "memory");   // KV(kt+1) ready
        __syncthreads();
        if (kt + 2 <= ktMax)
            attn_load_kv(sb, qkvh, base0, (kt + 2) * 64, (kt + 2) % 3, tid);

        const bool doP = (kt <= wktMax);
        const bool doS = (kt + 1 <= ktMax) && (kt + 1 <= wktMax);

        if (doP) {
            const uint32_t stP = sb + SM_ST + (kt % 3) * A_STAGE;
            const uint32_t stS = sb + SM_ST + ((kt + 1) % 3) * A_STAGE;

            if (kBase + 63 > qRowMin) {
#pragma unroll
                for (int nj = 0; nj < 8; nj++) {
                    const int col = kBase + nj * 8 + q2;
                    if (col > row0)         sc[nj][0] = -1e30f;
                    if (col + 1 > row0)     sc[nj][1] = -1e30f;
                    if (col > row0 + 8)     sc[nj][2] = -1e30f;
                    if (col + 1 > row0 + 8) sc[nj][3] = -1e30f;
                }
            }

            float mx0 = -1e30f, mx1 = -1e30f;
#pragma unroll
            for (int nj = 0; nj < 8; nj++) {
                mx0 = fmaxf(mx0, fmaxf(sc[nj][0], sc[nj][1]));
                mx1 = fmaxf(mx1, fmaxf(sc[nj][2], sc[nj][3]));
            }
            mx0 = fmaxf(mx0, __shfl_xor_sync(0xffffffffu, mx0, 1));
            mx0 = fmaxf(mx0, __shfl_xor_sync(0xffffffffu, mx0, 2));
            mx1 = fmaxf(mx1, __shfl_xor_sync(0xffffffffu, mx1, 1));
            mx1 = fmaxf(mx1, __shfl_xor_sync(0xffffffffu, mx1, 2));
            const float mn0 = fmaxf(m0, mx0), mn1 = fmaxf(m1, mx1);
            const float al0 = ex2_(m0 - mn0), al1 = ex2_(m1 - mn1);
            m0 = mn0; m1 = mn1;

            float s0 = 0.f, s1 = 0.f;
            float sn[8][4];
            if (doS) {
                // ---- S(kt+1) interleaved with exp2(kt) ----
#pragma unroll
                for (int nj = 0; nj < 8; nj += 2) {
#pragma unroll
                    for (int k = 0; k < 4; k++) { sn[nj][k] = 0.f; sn[nj + 1][k] = 0.f; }
#pragma unroll
                    for (int ks = 0; ks < 4; ks++) {
                        const uint32_t boff = SWZ((uint32_t)(nj * 8 + bRow4) * 128 + ks * 32 + bSeg);
                        uint32_t k0, k1, k2, k3;
                        ldsm_x4(k0, k1, k2, k3, stS + boff);
                        mma_f16(sn[nj],     qh[ks], k0, k1);
                        mma_f16(sn[nj],     ql[ks], k0, k1);
                        mma_f16(sn[nj + 1], qh[ks], k2, k3);
                        mma_f16(sn[nj + 1], ql[ks], k2, k3);
                    }
#pragma unroll
                    for (int u = 0; u < 2; u++) {
                        sc[nj + u][0] = ex2_(sc[nj + u][0] - mn0);
                        sc[nj + u][1] = ex2_(sc[nj + u][1] - mn0);
                        sc[nj + u][2] = ex2_(sc[nj + u][2] - mn1);
                        sc[nj + u][3] = ex2_(sc[nj + u][3] - mn1);
                        s0 += sc[nj + u][0] + sc[nj + u][1];
                        s1 += sc[nj + u][2] + sc[nj + u][3];
                    }
                }
            } else {
#pragma unroll
                for (int nj = 0; nj < 8; nj++) {
                    sc[nj][0] = ex2_(sc[nj][0] - mn0);
                    sc[nj][1] = ex2_(sc[nj][1] - mn0);
                    sc[nj][2] = ex2_(sc[nj][2] - mn1);
                    sc[nj][3] = ex2_(sc[nj][3] - mn1);
                    s0 += sc[nj][0] + sc[nj][1];
                    s1 += sc[nj][2] + sc[nj][3];
                }
            }
            s0 += __shfl_xor_sync(0xffffffffu, s0, 1);
            s0 += __shfl_xor_sync(0xffffffffu, s0, 2);
            s1 += __shfl_xor_sync(0xffffffffu, s1, 1);
            s1 += __shfl_xor_sync(0xffffffffu, s1, 2);
            l0s = l0s * al0 + s0;
            l1s = l1s * al1 + s1;

            // ---- P fragments (fp16 hi/lo) ----
            uint32_t ph[4][4], pl[4][4];
#pragma unroll
            for (int ks = 0; ks < 4; ks++) {
                split2h(sc[2 * ks][0],     sc[2 * ks][1],     ph[ks][0], pl[ks][0]);
                split2h(sc[2 * ks][2],     sc[2 * ks][3],     ph[ks][1], pl[ks][1]);
                split2h(sc[2 * ks + 1][0], sc[2 * ks + 1][1], ph[ks][2], pl[ks][2]);
                split2h(sc[2 * ks + 1][2], sc[2 * ks + 1][3], ph[ks][3], pl[ks][3]);
            }

            // ---- PV(kt) fp16 2-pass + O rescale ----
#pragma unroll
            for (int dj = 0; dj < 8; dj += 2) {
#pragma unroll
                for (int u = 0; u < 2; u++) {
                    o[dj + u][0] *= al0; o[dj + u][1] *= al0;
                    o[dj + u][2] *= al1; o[dj + u][3] *= al1;
                }
#pragma unroll
                for (int ks = 0; ks < 4; ks++) {
                    const uint32_t voff = SWZ((uint32_t)(ks * 16 + vRowL) * 128 + dj * 16 + vSeg);
                    uint32_t v0, v1, v2, v3;
                    ldsm_x4t(v0, v1, v2, v3, stP + 8192 + voff);
                    mma_f16(o[dj],     ph[ks], v0, v1);
                    mma_f16(o[dj],     pl[ks], v0, v1);
                    mma_f16(o[dj + 1], ph[ks], v2, v3);
                    mma_f16(o[dj + 1], pl[ks], v2, v3);
                }
            }

            if (doS) {
#pragma unroll
                for (int nj = 0; nj < 8; nj++)
#pragma unroll
                    for (int k = 0; k < 4; k++) sc[nj][k] = sn[nj][k];
            }
        }
    }

    // ---- epilogue: O/l -> fp16 hi/lo for proj GEMM ----
    const float inv0 = 1.0f / l0s, inv1 = 1.0f / l1s;
#pragma unroll
    for (int dj = 0; dj < 8; dj++) {
        uint32_t h0, l0, h1, l1;
        split2h(o[dj][0] * inv0, o[dj][1] * inv0, h0, l0);
        split2h(o[dj][2] * inv1, o[dj][3] * inv1, h1, l1);
        const size_t r0 = ((size_t)b * T_ + row0) * C_ + h * 64 + dj * 8 + q2;
        const size_t r1 = r0 + 8 * C_;
        *(uint32_t*)(yhi + r0) = h0;
        *(uint32_t*)(ylo + r0) = l0;
        *(uint32_t*)(yhi + r1) = h1;
        *(uint32_t*)(ylo + r1) = l1;
    }
}

// ---------------------------------------------------------------------------
extern "C" void kernel_launch(void* const* d_in, const int* in_sizes, int n_in,
                              void* d_out, int out_size)
{
    const float* x      = (const float*)d_in[0];
    const float* w_attn = (const float*)d_in[1];
    const float* b_attn = (const float*)d_in[2];
    const float* w_proj = (const float*)d_in[3];
    const float* b_proj = (const float*)d_in[4];
    float* out = (float*)d_out;

    __half *qkvhi, *qkvlo, *xhi, *xlo, *yhi, *ylo, *wa, *wp;
    cudaGetSymbolAddress((void**)&qkvhi, g_qkvhi);
    cudaGetSymbolAddress((void**)&qkvlo, g_qkvlo);
    cudaGetSymbolAddress((void**)&xhi, g_xhi);
    cudaGetSymbolAddress((void**)&xlo, g_xlo);
    cudaGetSymbolAddress((void**)&yhi, g_yhi);
    cudaGetSymbolAddress((void**)&ylo, g_ylo);
    cudaGetSymbolAddress((void**)&wa, g_wa);
    cudaGetSymbolAddress((void**)&wp, g_wp);

    cudaFuncSetAttribute(gemm_f16_kernel<0>,
                         cudaFuncAttributeMaxDynamicSharedMemorySize, P_SMEM);
    cudaFuncSetAttribute(gemm_f16_kernel<1>,
                         cudaFuncAttributeMaxDynamicSharedMemorySize, P_SMEM);
    cudaFuncSetAttribute(attn_mma_kernel,
                         cudaFuncAttributeMaxDynamicSharedMemorySize, A_SMEM);

    // conversions: x -> fp16 hi/lo; weights -> transposed fp16 single
    {
        int n4 = ROWS_ * C_ / 4;
        split_rows_h_kernel<<<(n4 + 255) / 256, 256>>>(x, xhi, xlo, n4);
        dim3 bt(32, 8);
        transpose_h_kernel<<<dim3(QKVC_ / 32, C_ / 32), bt>>>(w_attn, wa, C_, QKVC_);
        transpose_h_kernel<<<dim3(C_ / 32,    C_ / 32), bt>>>(w_proj, wp, C_, C_);
    }
    // Stage 1: qkv GEMM (fp16 2-pass) -> Q,K fp16 hi/lo + V fp16
    {
        dim3 grid(QKVC_ / 128, ROWS_ / 128);
        gemm_f16_kernel<1><<<grid, 256, P_SMEM>>>(xhi, xlo, wa, b_attn,
                                                  nullptr, qkvhi, qkvlo,
                                                  ROWS_, QKVC_, C_);
    }
    // Stage 2: attention -> y fp16 hi/lo
    {
        dim3 grid(T_ / 128, B_ * H_);
        attn_mma_kernel<<<grid, 256, A_SMEM>>>(qkvhi, qkvlo, yhi, ylo);
    }
    // Stage 3: out = y @ w_proj + b_proj (fp16 2-pass)
    {
        dim3 grid(C_ / 128, ROWS_ / 128);
        gemm_f16_kernel<0><<<grid, 256, P_SMEM>>>(yhi, ylo, wp, b_proj, out,
                                                  nullptr, nullptr, ROWS_, C_, C_);
    }
}

// round 13
// speedup vs baseline: 2.3336x; 1.1101x over previous
#include <cuda_runtime.h>
#include <cuda_bf16.h>
#include <cuda_fp16.h>
#include <cstdint>

// ---------------------------------------------------------------------------
// CausalSelfAttention on GB300 (sm_103 family target — no 'a' features).
// fp16 mma.sync scheme:
//   gemm1 (qkv):  128x256 tile, 64x64 warp tiles; x hi/lo × w_attn single
//   attention:    S = Q(hi/lo) × K(single) 2-pass; PV = P(single) × V(single)
//   gemm3 (proj): 128x128 tile; y hi/lo × w_proj single -> fp32 out
// ---------------------------------------------------------------------------

#define B_ 4
#define T_ 2048
#define C_ 768
#define H_ 12
#define ROWS_ 8192
#define QKVC_ 2304

// ---------------- scratch ---------------------------------------------------
__device__ __align__(256) __half  g_qkvhi[ROWS_ * QKVC_];   // Q,K hi; V single
__device__ __align__(256) __half  g_qkvlo[ROWS_ * QKVC_];   // Q,K lo
__device__ __align__(256) __half  g_xhi[ROWS_ * C_];
__device__ __align__(256) __half  g_xlo[ROWS_ * C_];
__device__ __align__(256) __half  g_yhi[ROWS_ * C_];
__device__ __align__(256) __half  g_ylo[ROWS_ * C_];
__device__ __align__(256) __half  g_wa[QKVC_ * C_];         // w_attn^T fp16
__device__ __align__(256) __half  g_wp[C_ * C_];            // w_proj^T fp16

// ---------------- helpers ---------------------------------------------------
__device__ __forceinline__ uint32_t smem_u32(const void* p) {
    uint32_t a;
    asm("{ .reg .u64 t; cvta.to.shared.u64 t, %1; cvt.u32.u64 %0, t; }"
        : "=r"(a) : "l"(p));
    return a;
}
#define SWZ(x) ((x) ^ (((x) >> 3) & 0x70))

__device__ __forceinline__ void cpa16(uint32_t dst, const void* src) {
    asm volatile("cp.async.cg.shared.global [%0], [%1], 16;" :: "r"(dst), "l"(src));
}
__device__ __forceinline__ void cpa_commit() { asm volatile("cp.async.commit_group;"); }

__device__ __forceinline__ void ldsm_x4(uint32_t& r0, uint32_t& r1, uint32_t& r2,
                                        uint32_t& r3, uint32_t addr) {
    asm volatile("ldmatrix.sync.aligned.m8n8.x4.shared.b16 {%0,%1,%2,%3}, [%4];"
                 : "=r"(r0), "=r"(r1), "=r"(r2), "=r"(r3) : "r"(addr));
}
__device__ __forceinline__ void ldsm_x4t(uint32_t& r0, uint32_t& r1, uint32_t& r2,
                                         uint32_t& r3, uint32_t addr) {
    asm volatile("ldmatrix.sync.aligned.m8n8.x4.trans.shared.b16 {%0,%1,%2,%3}, [%4];"
                 : "=r"(r0), "=r"(r1), "=r"(r2), "=r"(r3) : "r"(addr));
}
__device__ __forceinline__ void mma_f16(float* c, const uint32_t* a,
                                        uint32_t b0, uint32_t b1) {
    asm volatile("mma.sync.aligned.m16n8k16.row.col.f32.f16.f16.f32 "
                 "{%0,%1,%2,%3}, {%4,%5,%6,%7}, {%8,%9}, {%0,%1,%2,%3};"
                 : "+f"(c[0]), "+f"(c[1]), "+f"(c[2]), "+f"(c[3])
                 : "r"(a[0]), "r"(a[1]), "r"(a[2]), "r"(a[3]), "r"(b0), "r"(b1));
}
__device__ __forceinline__ float ex2_(float x) {
    float r; asm("ex2.approx.f32 %0, %1;" : "=f"(r) : "f"(x)); return r;
}
__device__ __forceinline__ void split2h(float a, float b, uint32_t& h, uint32_t& l) {
    __half2 hh = __floats2half2_rn(a, b);
    float2 hf = __half22float2(hh);
    __half2 ll = __floats2half2_rn(a - hf.x, b - hf.y);
    h = *(uint32_t*)&hh;
    l = *(uint32_t*)&ll;
}
__device__ __forceinline__ uint32_t packh2(float a, float b) {
    __half2 hh = __floats2half2_rn(a, b);
    return *(uint32_t*)&hh;
}

// ---------------------------------------------------------------------------
// Conversion kernels
// ---------------------------------------------------------------------------
__global__ void split_rows_h_kernel(const float* __restrict__ in,
                                    __half* __restrict__ hi,
                                    __half* __restrict__ lo, int n4)
{
    int i = blockIdx.x * blockDim.x + threadIdx.x;
    if (i >= n4) return;
    float4 v = ((const float4*)in)[i];
    uint32_t h0, l0, h1, l1;
    split2h(v.x, v.y, h0, l0);
    split2h(v.z, v.w, h1, l1);
    uint32_t* hp = (uint32_t*)(hi + 4 * (size_t)i);
    uint32_t* lp = (uint32_t*)(lo + 4 * (size_t)i);
    hp[0] = h0; hp[1] = h1;
    lp[0] = l0; lp[1] = l1;
}

__global__ void transpose_h_kernel(const float* __restrict__ w,
                                   __half* __restrict__ wT, int K, int N)
{
    __shared__ float t[32][33];
    const int n0 = blockIdx.x * 32, k0 = blockIdx.y * 32;
    const int tx = threadIdx.x, ty = threadIdx.y;
#pragma unroll
    for (int j = 0; j < 4; j++)
        t[ty + j * 8][tx] = w[(size_t)(k0 + ty + j * 8) * N + n0 + tx];
    __syncthreads();
#pragma unroll
    for (int j = 0; j < 4; j++) {
        const int n = ty + j * 8;
        wT[(size_t)(n0 + n) * K + k0 + tx] = __float2half(t[tx][n]);
    }
}

// ---------------------------------------------------------------------------
// GEMM 1 (qkv): 128x256 CTA tile, 8 warps 64x64, fp16 2-pass A hi/lo.
// Epilogue: Q,K fp16 hi/lo (Q *log2e/8); V fp16 single.
// ---------------------------------------------------------------------------
#define W_STAGE 65536          // Ahi 16K | Alo 16K | B 32K
#define W_SMEM  (3 * W_STAGE)

__device__ __forceinline__ void qkv_load_chunk(
    uint32_t sb, const __half* Ahi, const __half* Alo, const __half* Bm,
    int rowBase, int colBase, int K, int kc, int stage, int tid)
{
    const uint32_t base = sb + stage * W_STAGE;
    const int k0 = kc * 64;
#pragma unroll
    for (int i = 0; i < 4; i++) {
        const int seg = tid + i * 256;
        const int r = seg >> 3, g = seg & 7;
        const uint32_t soff = SWZ(r * 128 + g * 16);
        cpa16(base + soff,         Ahi + (size_t)(rowBase + r) * K + k0 + g * 8);
        cpa16(base + 16384 + soff, Alo + (size_t)(rowBase + r) * K + k0 + g * 8);
    }
#pragma unroll
    for (int i = 0; i < 8; i++) {
        const int seg = tid + i * 256;
        const int r = seg >> 3, g = seg & 7;
        cpa16(base + 32768 + SWZ(r * 128 + g * 16),
              Bm + (size_t)(colBase + r) * K + k0 + g * 8);
    }
    cpa_commit();
}

__global__ __launch_bounds__(256, 1)
void gemm_qkv_kernel(const __half* __restrict__ Ahi, const __half* __restrict__ Alo,
                     const __half* __restrict__ Bm,
                     const float* __restrict__ bias,
                     __half* __restrict__ Chi, __half* __restrict__ Clo,
                     int M, int N, int K)
{
    extern __shared__ char smem[];
    const uint32_t sb = smem_u32(smem);
    const int tid = threadIdx.x, wid = tid >> 5, lane = tid & 31;
    const int wm = wid >> 2, wn = wid & 3;        // 2 x 4 warps, 64x64 each
    const int rowBase = blockIdx.y * 128, colBase = blockIdx.x * 256;
    const int NK = K / 64;

    float c[4][8][4];
#pragma unroll
    for (int i = 0; i < 4; i++)
#pragma unroll
        for (int j = 0; j < 8; j++)
#pragma unroll
            for (int k = 0; k < 4; k++) c[i][j][k] = 0.f;

    qkv_load_chunk(sb, Ahi, Alo, Bm, rowBase, colBase, K, 0, 0, tid);
    qkv_load_chunk(sb, Ahi, Alo, Bm, rowBase, colBase, K, 1, 1, tid);

    const int aRow = wm * 64 + (lane & 15);
    const uint32_t aSegOff = ((lane >> 4) & 1) * 16;
    const int bRow4 = wn * 64 + ((lane >> 4) & 1) * 8 + (lane & 7);
    const uint32_t bSegOff = ((lane >> 3) & 1) * 16;

    for (int kc = 0; kc < NK; kc++) {
        if (kc + 1 < NK) asm volatile("cp.async.wait_group 1;" ::: "memory");
        else             asm volatile("cp.async.wait_group 0;" ::: "memory");
        __syncthreads();
        if (kc + 2 < NK)
            qkv_load_chunk(sb, Ahi, Alo, Bm, rowBase, colBase, K,
                           kc + 2, (kc + 2) % 3, tid);
        const uint32_t st = sb + (kc % 3) * W_STAGE;
#pragma unroll
        for (int ks = 0; ks < 4; ks++) {
            uint32_t bf[8][2];
#pragma unroll
            for (int nj = 0; nj < 8; nj += 2) {
                const uint32_t boff = SWZ((uint32_t)(bRow4 + nj * 8) * 128 + ks * 32 + bSegOff);
                ldsm_x4(bf[nj][0], bf[nj][1], bf[nj + 1][0], bf[nj + 1][1], st + 32768 + boff);
            }
#pragma unroll
            for (int mi = 0; mi < 4; mi++) {
                uint32_t ah[4], al[4];
                const uint32_t aoff = SWZ((uint32_t)(aRow + mi * 16) * 128 + ks * 32 + aSegOff);
                ldsm_x4(ah[0], ah[1], ah[2], ah[3], st + aoff);
                ldsm_x4(al[0], al[1], al[2], al[3], st + 16384 + aoff);
#pragma unroll
                for (int nj = 0; nj < 8; nj++) {
                    mma_f16(c[mi][nj], ah, bf[nj][0], bf[nj][1]);
                    mma_f16(c[mi][nj], al, bf[nj][0], bf[nj][1]);
                }
            }
        }
    }

    const int g = lane >> 2, q2 = (lane & 3) * 2;
    const int sec = colBase / 768;                 // block-uniform: 0=Q 1=K 2=V
    const float scl = (sec == 0) ? 0.18033688f : 1.0f;
#pragma unroll
    for (int mi = 0; mi < 4; mi++) {
        const int row0 = rowBase + wm * 64 + mi * 16 + g;
#pragma unroll
        for (int nj = 0; nj < 8; nj++) {
            const int col = colBase + wn * 64 + nj * 8 + q2;
            const float bx = bias[col], by = bias[col + 1];
            const float a0 = c[mi][nj][0] + bx, a1 = c[mi][nj][1] + by;
            const float a2 = c[mi][nj][2] + bx, a3 = c[mi][nj][3] + by;
            if (sec == 2) {
                *(uint32_t*)(Chi + (size_t)row0 * N + col) = packh2(a0, a1);
                *(uint32_t*)(Chi + (size_t)(row0 + 8) * N + col) = packh2(a2, a3);
            } else {
                uint32_t h0, l0, h1, l1;
                split2h(a0 * scl, a1 * scl, h0, l0);
                split2h(a2 * scl, a3 * scl, h1, l1);
                *(uint32_t*)(Chi + (size_t)row0 * N + col) = h0;
                *(uint32_t*)(Clo + (size_t)row0 * N + col) = l0;
                *(uint32_t*)(Chi + (size_t)(row0 + 8) * N + col) = h1;
                *(uint32_t*)(Clo + (size_t)(row0 + 8) * N + col) = l1;
            }
        }
    }
}

// ---------------------------------------------------------------------------
// GEMM 3 (proj): 128x128 tile, fp16 2-pass, fp32 out.
// ---------------------------------------------------------------------------
#define P_STAGE 49152
#define P_SMEM  (3 * P_STAGE)

__device__ __forceinline__ void proj_load_chunk(
    uint32_t sb, const __half* Ahi, const __half* Alo, const __half* Bm,
    int rowBase, int colBase, int K, int kc, int stage, int tid)
{
    const uint32_t base = sb + stage * P_STAGE;
    const int k0 = kc * 64;
#pragma unroll
    for (int i = 0; i < 4; i++) {
        const int seg = tid + i * 256;
        const int r = seg >> 3, g = seg & 7;
        const uint32_t soff = SWZ(r * 128 + g * 16);
        cpa16(base + soff,         Ahi + (size_t)(rowBase + r) * K + k0 + g * 8);
        cpa16(base + 16384 + soff, Alo + (size_t)(rowBase + r) * K + k0 + g * 8);
        cpa16(base + 32768 + soff, Bm  + (size_t)(colBase + r) * K + k0 + g * 8);
    }
    cpa_commit();
}

__global__ __launch_bounds__(256, 1)
void gemm_proj_kernel(const __half* __restrict__ Ahi, const __half* __restrict__ Alo,
                      const __half* __restrict__ Bm,
                      const float* __restrict__ bias, float* __restrict__ Cm,
                      int M, int N, int K)
{
    extern __shared__ char smem[];
    const uint32_t sb = smem_u32(smem);
    const int tid = threadIdx.x, wid = tid >> 5, lane = tid & 31;
    const int wm = wid >> 2, wn = wid & 3;
    const int rowBase = blockIdx.y * 128, colBase = blockIdx.x * 128;
    const int NK = K / 64;

    float c[4][4][4];
#pragma unroll
    for (int i = 0; i < 4; i++)
#pragma unroll
        for (int j = 0; j < 4; j++)
#pragma unroll
            for (int k = 0; k < 4; k++) c[i][j][k] = 0.f;

    proj_load_chunk(sb, Ahi, Alo, Bm, rowBase, colBase, K, 0, 0, tid);
    proj_load_chunk(sb, Ahi, Alo, Bm, rowBase, colBase, K, 1, 1, tid);

    const int aRow = wm * 64 + (lane & 15);
    const uint32_t aSegOff = ((lane >> 4) & 1) * 16;
    const int bRow4 = wn * 32 + ((lane >> 4) & 1) * 8 + (lane & 7);
    const uint32_t bSegOff = ((lane >> 3) & 1) * 16;

    for (int kc = 0; kc < NK; kc++) {
        if (kc + 1 < NK) asm volatile("cp.async.wait_group 1;" ::: "memory");
        else             asm volatile("cp.async.wait_group 0;" ::: "memory");
        __syncthreads();
        if (kc + 2 < NK)
            proj_load_chunk(sb, Ahi, Alo, Bm, rowBase, colBase, K,
                            kc + 2, (kc + 2) % 3, tid);
        const uint32_t st = sb + (kc % 3) * P_STAGE;
#pragma unroll
        for (int ks = 0; ks < 4; ks++) {
            uint32_t bf[4][2];
#pragma unroll
            for (int nj = 0; nj < 4; nj += 2) {
                const uint32_t boff = SWZ((uint32_t)(bRow4 + nj * 8) * 128 + ks * 32 + bSegOff);
                ldsm_x4(bf[nj][0], bf[nj][1], bf[nj + 1][0], bf[nj + 1][1], st + 32768 + boff);
            }
#pragma unroll
            for (int mi = 0; mi < 4; mi++) {
                uint32_t ah[4], al[4];
                const uint32_t aoff = SWZ((uint32_t)(aRow + mi * 16) * 128 + ks * 32 + aSegOff);
                ldsm_x4(ah[0], ah[1], ah[2], ah[3], st + aoff);
                ldsm_x4(al[0], al[1], al[2], al[3], st + 16384 + aoff);
#pragma unroll
                for (int nj = 0; nj < 4; nj++) {
                    mma_f16(c[mi][nj], ah, bf[nj][0], bf[nj][1]);
                    mma_f16(c[mi][nj], al, bf[nj][0], bf[nj][1]);
                }
            }
        }
    }

    const int g = lane >> 2, q2 = (lane & 3) * 2;
#pragma unroll
    for (int mi = 0; mi < 4; mi++) {
        const int row0 = rowBase + wm * 64 + mi * 16 + g;
#pragma unroll
        for (int nj = 0; nj < 4; nj++) {
            const int col = colBase + wn * 32 + nj * 8 + q2;
            const float bx = bias[col], by = bias[col + 1];
            float2 v0 = make_float2(c[mi][nj][0] + bx, c[mi][nj][1] + by);
            float2 v1 = make_float2(c[mi][nj][2] + bx, c[mi][nj][3] + by);
            *(float2*)(Cm + (size_t)row0 * N + col) = v0;
            *(float2*)(Cm + (size_t)(row0 + 8) * N + col) = v1;
        }
    }
}

// ---------------------------------------------------------------------------
// Flash attention: S fp16 2-pass (Q hi/lo x K single), PV fp16 1-pass (P single).
// Single-sync 3-stage ring, stage = K 8K | V 8K = 16K. smem: Q 32K + 48K.
// S(kt+1) interleaved with softmax(kt).
// ---------------------------------------------------------------------------
#define SM_QHI 0
#define SM_QLO 16384
#define SM_ST  32768
#define A_STAGE 16384
#define A_SMEM (SM_ST + 3 * A_STAGE)

__device__ __forceinline__ void attn_load_kv(
    uint32_t sb, const __half* qkvh, size_t base0, int kBase, int stage, int tid)
{
    const uint32_t st = sb + SM_ST + stage * A_STAGE;
#pragma unroll
    for (int i = 0; i < 2; i++) {
        const int seg = tid + i * 256;
        const int r = seg >> 3, gsg = seg & 7;
        const size_t goff = base0 + (size_t)(kBase + r) * QKVC_ + gsg * 8;
        const uint32_t soff = SWZ((uint32_t)r * 128 + gsg * 16);
        cpa16(st + soff,        qkvh + goff + 768);    // K single
        cpa16(st + 8192 + soff, qkvh + goff + 1536);   // V single
    }
    cpa_commit();
}

__global__ __launch_bounds__(256, 1)
void attn_mma_kernel(const __half* __restrict__ qkvh, const __half* __restrict__ qkvl,
                     __half* __restrict__ yhi, __half* __restrict__ ylo)
{
    extern __shared__ char smem[];
    const uint32_t sb = smem_u32(smem);
    const int qt = (int)gridDim.x - 1 - (int)blockIdx.x;
    const int bh = blockIdx.y;
    const int b = bh / H_, h = bh % H_;
    const int tid = threadIdx.x, wid = tid >> 5, lane = tid & 31;
    const int qBase = qt * 128;
    const size_t base0 = (size_t)b * T_ * QKVC_ + h * 64;
    const int ktMax = 2 * qt + 1;

#pragma unroll
    for (int i = 0; i < 4; i++) {
        const int seg = tid + i * 256;
        const int r = seg >> 3, gsg = seg & 7;
        const size_t goff = base0 + (size_t)(qBase + r) * QKVC_ + gsg * 8;
        const uint32_t soff = SWZ((uint32_t)r * 128 + gsg * 16);
        cpa16(sb + SM_QHI + soff, qkvh + goff);
        cpa16(sb + SM_QLO + soff, qkvl + goff);
    }
    cpa_commit();
    attn_load_kv(sb, qkvh, base0, 0,  0, tid);
    attn_load_kv(sb, qkvh, base0, 64, 1, tid);
    asm volatile("cp.async.wait_group 1;" ::: "memory");
    __syncthreads();

    uint32_t qh[4][4], ql[4][4];
    {
        const int aRow = wid * 16 + (lane & 15);
        const uint32_t aSeg = ((lane >> 4) & 1) * 16;
#pragma unroll
        for (int ks = 0; ks < 4; ks++) {
            const uint32_t aoff = SWZ((uint32_t)aRow * 128 + ks * 32 + aSeg);
            ldsm_x4(qh[ks][0], qh[ks][1], qh[ks][2], qh[ks][3], sb + SM_QHI + aoff);
            ldsm_x4(ql[ks][0], ql[ks][1], ql[ks][2], ql[ks][3], sb + SM_QLO + aoff);
        }
    }

    float o[8][4];
#pragma unroll
    for (int d = 0; d < 8; d++)
#pragma unroll
        for (int k = 0; k < 4; k++) o[d][k] = 0.f;
    float m0 = -1e30f, m1 = -1e30f, l0s = 0.f, l1s = 0.f;

    const int g = lane >> 2, q2 = (lane & 3) * 2;
    const int qRowMin = qBase + wid * 16;
    const int row0 = qRowMin + g;
    const int wktMax = (qRowMin + 15) >> 6;

    const int bRow4 = ((lane >> 4) & 1) * 8 + (lane & 7);
    const uint32_t bSeg = ((lane >> 3) & 1) * 16;
    const int vRowL = lane & 15;
    const uint32_t vSeg = ((lane >> 4) & 1) * 16;

    // ---- S(0) ----
    float sc[8][4];
    {
        const uint32_t st0 = sb + SM_ST;
#pragma unroll
        for (int nj = 0; nj < 8; nj += 2) {
#pragma unroll
            for (int k = 0; k < 4; k++) { sc[nj][k] = 0.f; sc[nj + 1][k] = 0.f; }
#pragma unroll
            for (int ks = 0; ks < 4; ks++) {
                const uint32_t boff = SWZ((uint32_t)(nj * 8 + bRow4) * 128 + ks * 32 + bSeg);
                uint32_t k0, k1, k2, k3;
                ldsm_x4(k0, k1, k2, k3, st0 + boff);
                mma_f16(sc[nj],     qh[ks], k0, k1);
                mma_f16(sc[nj],     ql[ks], k0, k1);
                mma_f16(sc[nj + 1], qh[ks], k2, k3);
                mma_f16(sc[nj + 1], ql[ks], k2, k3);
            }
        }
    }

    for (int kt = 0; kt <= ktMax; kt++) {
        const int kBase = kt * 64;
        asm volatile("cp.async.wait_group 0;" ::: "memory");
        __syncthreads();
        if (kt + 2 <= ktMax)
            attn_load_kv(sb, qkvh, base0, (kt + 2) * 64, (kt + 2) % 3, tid);

        const bool doP = (kt <= wktMax);
        const bool doS = (kt + 1 <= ktMax) && (kt + 1 <= wktMax);

        if (doP) {
            const uint32_t stP = sb + SM_ST + (kt % 3) * A_STAGE;
            const uint32_t stS = sb + SM_ST + ((kt + 1) % 3) * A_STAGE;

            if (kBase + 63 > qRowMin) {
#pragma unroll
                for (int nj = 0; nj < 8; nj++) {
                    const int col = kBase + nj * 8 + q2;
                    if (col > row0)         sc[nj][0] = -1e30f;
                    if (col + 1 > row0)     sc[nj][1] = -1e30f;
                    if (col > row0 + 8)     sc[nj][2] = -1e30f;
                    if (col + 1 > row0 + 8) sc[nj][3] = -1e30f;
                }
            }

            float mx0 = -1e30f, mx1 = -1e30f;
#pragma unroll
            for (int nj = 0; nj < 8; nj++) {
                mx0 = fmaxf(mx0, fmaxf(sc[nj][0], sc[nj][1]));
                mx1 = fmaxf(mx1, fmaxf(sc[nj][2], sc[nj][3]));
            }
            mx0 = fmaxf(mx0, __shfl_xor_sync(0xffffffffu, mx0, 1));
            mx0 = fmaxf(mx0, __shfl_xor_sync(0xffffffffu, mx0, 2));
            mx1 = fmaxf(mx1, __shfl_xor_sync(0xffffffffu, mx1, 1));
            mx1 = fmaxf(mx1, __shfl_xor_sync(0xffffffffu, mx1, 2));
            const float mn0 = fmaxf(m0, mx0), mn1 = fmaxf(m1, mx1);
            const float al0 = ex2_(m0 - mn0), al1 = ex2_(m1 - mn1);
            m0 = mn0; m1 = mn1;

            float s0 = 0.f, s1 = 0.f;
            float sn[8][4];
            if (doS) {
#pragma unroll
                for (int nj = 0; nj < 8; nj += 2) {
#pragma unroll
                    for (int k = 0; k < 4; k++) { sn[nj][k] = 0.f; sn[nj + 1][k] = 0.f; }
#pragma unroll
                    for (int ks = 0; ks < 4; ks++) {
                        const uint32_t boff = SWZ((uint32_t)(nj * 8 + bRow4) * 128 + ks * 32 + bSeg);
                        uint32_t k0, k1, k2, k3;
                        ldsm_x4(k0, k1, k2, k3, stS + boff);
                        mma_f16(sn[nj],     qh[ks], k0, k1);
                        mma_f16(sn[nj],     ql[ks], k0, k1);
                        mma_f16(sn[nj + 1], qh[ks], k2, k3);
                        mma_f16(sn[nj + 1], ql[ks], k2, k3);
                    }
#pragma unroll
                    for (int u = 0; u < 2; u++) {
                        sc[nj + u][0] = ex2_(sc[nj + u][0] - mn0);
                        sc[nj + u][1] = ex2_(sc[nj + u][1] - mn0);
                        sc[nj + u][2] = ex2_(sc[nj + u][2] - mn1);
                        sc[nj + u][3] = ex2_(sc[nj + u][3] - mn1);
                        s0 += sc[nj + u][0] + sc[nj + u][1];
                        s1 += sc[nj + u][2] + sc[nj + u][3];
                    }
                }
            } else {
#pragma unroll
                for (int nj = 0; nj < 8; nj++) {
                    sc[nj][0] = ex2_(sc[nj][0] - mn0);
                    sc[nj][1] = ex2_(sc[nj][1] - mn0);
                    sc[nj][2] = ex2_(sc[nj][2] - mn1);
                    sc[nj][3] = ex2_(sc[nj][3] - mn1);
                    s0 += sc[nj][0] + sc[nj][1];
                    s1 += sc[nj][2] + sc[nj][3];
                }
            }
            s0 += __shfl_xor_sync(0xffffffffu, s0, 1);
            s0 += __shfl_xor_sync(0xffffffffu, s0, 2);
            s1 += __shfl_xor_sync(0xffffffffu, s1, 1);
            s1 += __shfl_xor_sync(0xffffffffu, s1, 2);
            l0s = l0s * al0 + s0;
            l1s = l1s * al1 + s1;

            // ---- P fragments (single fp16) ----
            uint32_t ph[4][4];
#pragma unroll
            for (int ks = 0; ks < 4; ks++) {
                ph[ks][0] = packh2(sc[2 * ks][0],     sc[2 * ks][1]);
                ph[ks][1] = packh2(sc[2 * ks][2],     sc[2 * ks][3]);
                ph[ks][2] = packh2(sc[2 * ks + 1][0], sc[2 * ks + 1][1]);
                ph[ks][3] = packh2(sc[2 * ks + 1][2], sc[2 * ks + 1][3]);
            }

            // ---- PV(kt) 1-pass + O rescale ----
#pragma unroll
            for (int dj = 0; dj < 8; dj += 2) {
#pragma unroll
                for (int u = 0; u < 2; u++) {
                    o[dj + u][0] *= al0; o[dj + u][1] *= al0;
                    o[dj + u][2] *= al1; o[dj + u][3] *= al1;
                }
#pragma unroll
                for (int ks = 0; ks < 4; ks++) {
                    const uint32_t voff = SWZ((uint32_t)(ks * 16 + vRowL) * 128 + dj * 16 + vSeg);
                    uint32_t v0, v1, v2, v3;
                    ldsm_x4t(v0, v1, v2, v3, stP + 8192 + voff);
                    mma_f16(o[dj],     ph[ks], v0, v1);
                    mma_f16(o[dj + 1], ph[ks], v2, v3);
                }
            }

            if (doS) {
#pragma unroll
                for (int nj = 0; nj < 8; nj++)
#pragma unroll
                    for (int k = 0; k < 4; k++) sc[nj][k] = sn[nj][k];
            }
        }
    }

    const float inv0 = 1.0f / l0s, inv1 = 1.0f / l1s;
#pragma unroll
    for (int dj = 0; dj < 8; dj++) {
        uint32_t h0, l0, h1, l1;
        split2h(o[dj][0] * inv0, o[dj][1] * inv0, h0, l0);
        split2h(o[dj][2] * inv1, o[dj][3] * inv1, h1, l1);
        const size_t r0 = ((size_t)b * T_ + row0) * C_ + h * 64 + dj * 8 + q2;
        const size_t r1 = r0 + 8 * C_;
        *(uint32_t*)(yhi + r0) = h0;
        *(uint32_t*)(ylo + r0) = l0;
        *(uint32_t*)(yhi + r1) = h1;
        *(uint32_t*)(ylo + r1) = l1;
    }
}

// ---------------------------------------------------------------------------
extern "C" void kernel_launch(void* const* d_in, const int* in_sizes, int n_in,
                              void* d_out, int out_size)
{
    const float* x      = (const float*)d_in[0];
    const float* w_attn = (const float*)d_in[1];
    const float* b_attn = (const float*)d_in[2];
    const float* w_proj = (const float*)d_in[3];
    const float* b_proj = (const float*)d_in[4];
    float* out = (float*)d_out;

    __half *qkvhi, *qkvlo, *xhi, *xlo, *yhi, *ylo, *wa, *wp;
    cudaGetSymbolAddress((void**)&qkvhi, g_qkvhi);
    cudaGetSymbolAddress((void**)&qkvlo, g_qkvlo);
    cudaGetSymbolAddress((void**)&xhi, g_xhi);
    cudaGetSymbolAddress((void**)&xlo, g_xlo);
    cudaGetSymbolAddress((void**)&yhi, g_yhi);
    cudaGetSymbolAddress((void**)&ylo, g_ylo);
    cudaGetSymbolAddress((void**)&wa, g_wa);
    cudaGetSymbolAddress((void**)&wp, g_wp);

    cudaFuncSetAttribute(gemm_qkv_kernel,
                         cudaFuncAttributeMaxDynamicSharedMemorySize, W_SMEM);
    cudaFuncSetAttribute(gemm_proj_kernel,
                         cudaFuncAttributeMaxDynamicSharedMemorySize, P_SMEM);
    cudaFuncSetAttribute(attn_mma_kernel,
                         cudaFuncAttributeMaxDynamicSharedMemorySize, A_SMEM);

    // conversions
    {
        int n4 = ROWS_ * C_ / 4;
        split_rows_h_kernel<<<(n4 + 255) / 256, 256>>>(x, xhi, xlo, n4);
        dim3 bt(32, 8);
        transpose_h_kernel<<<dim3(QKVC_ / 32, C_ / 32), bt>>>(w_attn, wa, C_, QKVC_);
        transpose_h_kernel<<<dim3(C_ / 32,    C_ / 32), bt>>>(w_proj, wp, C_, C_);
    }
    // Stage 1: qkv GEMM (128x256 tiles)
    {
        dim3 grid(QKVC_ / 256, ROWS_ / 128);
        gemm_qkv_kernel<<<grid, 256, W_SMEM>>>(xhi, xlo, wa, b_attn,
                                               qkvhi, qkvlo, ROWS_, QKVC_, C_);
    }
    // Stage 2: attention -> y fp16 hi/lo
    {
        dim3 grid(T_ / 128, B_ * H_);
        attn_mma_kernel<<<grid, 256, A_SMEM>>>(qkvhi, qkvlo, yhi, ylo);
    }
    // Stage 3: out = y @ w_proj + b_proj
    {
        dim3 grid(C_ / 128, ROWS_ / 128);
        gemm_proj_kernel<<<grid, 256, P_SMEM>>>(yhi, ylo, wp, b_proj, out,
                                                ROWS_, C_, C_);
    }
}

// round 14
// speedup vs baseline: 3.0192x; 1.2938x over previous
#include <cuda_runtime.h>
#include <cuda_bf16.h>
#include <cuda_fp16.h>
#include <cstdint>

// ---------------------------------------------------------------------------
// CausalSelfAttention on GB300 (sm_103 family target — no 'a' features).
// fp16 mma.sync scheme:
//   gemm1 (qkv):  1-pass single x * single w -> Q(scaled)/K/V fp16 single
//   attention:    S = Q x K 1-pass; PV = P x V 1-pass
//   gemm3 (proj): y fp16 hi/lo 2-pass x w_proj single -> fp32 out
// ---------------------------------------------------------------------------

#define B_ 4
#define T_ 2048
#define C_ 768
#define H_ 12
#define ROWS_ 8192
#define QKVC_ 2304

// ---------------- scratch ---------------------------------------------------
__device__ __align__(256) __half  g_qkv[ROWS_ * QKVC_];     // Q(scaled),K,V fp16
__device__ __align__(256) __half  g_x[ROWS_ * C_];          // x fp16
__device__ __align__(256) __half  g_yhi[ROWS_ * C_];
__device__ __align__(256) __half  g_ylo[ROWS_ * C_];
__device__ __align__(256) __half  g_wa[QKVC_ * C_];         // w_attn^T fp16
__device__ __align__(256) __half  g_wp[C_ * C_];            // w_proj^T fp16

// ---------------- helpers ---------------------------------------------------
__device__ __forceinline__ uint32_t smem_u32(const void* p) {
    uint32_t a;
    asm("{ .reg .u64 t; cvta.to.shared.u64 t, %1; cvt.u32.u64 %0, t; }"
        : "=r"(a) : "l"(p));
    return a;
}
#define SWZ(x) ((x) ^ (((x) >> 3) & 0x70))

__device__ __forceinline__ void cpa16(uint32_t dst, const void* src) {
    asm volatile("cp.async.cg.shared.global [%0], [%1], 16;" :: "r"(dst), "l"(src));
}
__device__ __forceinline__ void cpa_commit() { asm volatile("cp.async.commit_group;"); }

__device__ __forceinline__ void ldsm_x4(uint32_t& r0, uint32_t& r1, uint32_t& r2,
                                        uint32_t& r3, uint32_t addr) {
    asm volatile("ldmatrix.sync.aligned.m8n8.x4.shared.b16 {%0,%1,%2,%3}, [%4];"
                 : "=r"(r0), "=r"(r1), "=r"(r2), "=r"(r3) : "r"(addr));
}
__device__ __forceinline__ void ldsm_x4t(uint32_t& r0, uint32_t& r1, uint32_t& r2,
                                         uint32_t& r3, uint32_t addr) {
    asm volatile("ldmatrix.sync.aligned.m8n8.x4.trans.shared.b16 {%0,%1,%2,%3}, [%4];"
                 : "=r"(r0), "=r"(r1), "=r"(r2), "=r"(r3) : "r"(addr));
}
__device__ __forceinline__ void mma_f16(float* c, const uint32_t* a,
                                        uint32_t b0, uint32_t b1) {
    asm volatile("mma.sync.aligned.m16n8k16.row.col.f32.f16.f16.f32 "
                 "{%0,%1,%2,%3}, {%4,%5,%6,%7}, {%8,%9}, {%0,%1,%2,%3};"
                 : "+f"(c[0]), "+f"(c[1]), "+f"(c[2]), "+f"(c[3])
                 : "r"(a[0]), "r"(a[1]), "r"(a[2]), "r"(a[3]), "r"(b0), "r"(b1));
}
__device__ __forceinline__ float ex2_(float x) {
    float r; asm("ex2.approx.f32 %0, %1;" : "=f"(r) : "f"(x)); return r;
}
__device__ __forceinline__ void split2h(float a, float b, uint32_t& h, uint32_t& l) {
    __half2 hh = __floats2half2_rn(a, b);
    float2 hf = __half22float2(hh);
    __half2 ll = __floats2half2_rn(a - hf.x, b - hf.y);
    h = *(uint32_t*)&hh;
    l = *(uint32_t*)&ll;
}
__device__ __forceinline__ uint32_t packh2(float a, float b) {
    __half2 hh = __floats2half2_rn(a, b);
    return *(uint32_t*)&hh;
}

// ---------------------------------------------------------------------------
// Conversion kernels
// ---------------------------------------------------------------------------
__global__ void convert_rows_h_kernel(const float* __restrict__ in,
                                      __half* __restrict__ outh, int n4)
{
    int i = blockIdx.x * blockDim.x + threadIdx.x;
    if (i >= n4) return;
    float4 v = ((const float4*)in)[i];
    uint32_t* hp = (uint32_t*)(outh + 4 * (size_t)i);
    hp[0] = packh2(v.x, v.y);
    hp[1] = packh2(v.z, v.w);
}

__global__ void transpose_h_kernel(const float* __restrict__ w,
                                   __half* __restrict__ wT, int K, int N)
{
    __shared__ float t[32][33];
    const int n0 = blockIdx.x * 32, k0 = blockIdx.y * 32;
    const int tx = threadIdx.x, ty = threadIdx.y;
#pragma unroll
    for (int j = 0; j < 4; j++)
        t[ty + j * 8][tx] = w[(size_t)(k0 + ty + j * 8) * N + n0 + tx];
    __syncthreads();
#pragma unroll
    for (int j = 0; j < 4; j++) {
        const int n = ty + j * 8;
        wT[(size_t)(n0 + n) * K + k0 + tx] = __float2half(t[tx][n]);
    }
}

// ---------------------------------------------------------------------------
// GEMM 1 (qkv): 128x256 CTA tile, 8 warps 64x64, fp16 1-pass.
// Epilogue: fp16 single out; Q columns pre-scaled by log2e/8.
// ---------------------------------------------------------------------------
#define W_STAGE 49152          // A 16K | B 32K
#define W_SMEM  (3 * W_STAGE)

__device__ __forceinline__ void qkv_load_chunk(
    uint32_t sb, const __half* Am, const __half* Bm,
    int rowBase, int colBase, int K, int kc, int stage, int tid)
{
    const uint32_t base = sb + stage * W_STAGE;
    const int k0 = kc * 64;
#pragma unroll
    for (int i = 0; i < 4; i++) {
        const int seg = tid + i * 256;
        const int r = seg >> 3, g = seg & 7;
        cpa16(base + SWZ(r * 128 + g * 16),
              Am + (size_t)(rowBase + r) * K + k0 + g * 8);
    }
#pragma unroll
    for (int i = 0; i < 8; i++) {
        const int seg = tid + i * 256;
        const int r = seg >> 3, g = seg & 7;
        cpa16(base + 16384 + SWZ(r * 128 + g * 16),
              Bm + (size_t)(colBase + r) * K + k0 + g * 8);
    }
    cpa_commit();
}

__global__ __launch_bounds__(256, 1)
void gemm_qkv_kernel(const __half* __restrict__ Am, const __half* __restrict__ Bm,
                     const float* __restrict__ bias, __half* __restrict__ Cq,
                     int M, int N, int K)
{
    extern __shared__ char smem[];
    const uint32_t sb = smem_u32(smem);
    const int tid = threadIdx.x, wid = tid >> 5, lane = tid & 31;
    const int wm = wid >> 2, wn = wid & 3;        // 2 x 4 warps, 64x64 each
    const int rowBase = blockIdx.y * 128, colBase = blockIdx.x * 256;
    const int NK = K / 64;

    float c[4][8][4];
#pragma unroll
    for (int i = 0; i < 4; i++)
#pragma unroll
        for (int j = 0; j < 8; j++)
#pragma unroll
            for (int k = 0; k < 4; k++) c[i][j][k] = 0.f;

    qkv_load_chunk(sb, Am, Bm, rowBase, colBase, K, 0, 0, tid);
    qkv_load_chunk(sb, Am, Bm, rowBase, colBase, K, 1, 1, tid);

    const int aRow = wm * 64 + (lane & 15);
    const uint32_t aSegOff = ((lane >> 4) & 1) * 16;
    const int bRow4 = wn * 64 + ((lane >> 4) & 1) * 8 + (lane & 7);
    const uint32_t bSegOff = ((lane >> 3) & 1) * 16;

    for (int kc = 0; kc < NK; kc++) {
        if (kc + 1 < NK) asm volatile("cp.async.wait_group 1;" ::: "memory");
        else             asm volatile("cp.async.wait_group 0;" ::: "memory");
        __syncthreads();
        if (kc + 2 < NK)
            qkv_load_chunk(sb, Am, Bm, rowBase, colBase, K,
                           kc + 2, (kc + 2) % 3, tid);
        const uint32_t st = sb + (kc % 3) * W_STAGE;
#pragma unroll
        for (int ks = 0; ks < 4; ks++) {
            uint32_t bf[8][2];
#pragma unroll
            for (int nj = 0; nj < 8; nj += 2) {
                const uint32_t boff = SWZ((uint32_t)(bRow4 + nj * 8) * 128 + ks * 32 + bSegOff);
                ldsm_x4(bf[nj][0], bf[nj][1], bf[nj + 1][0], bf[nj + 1][1], st + 16384 + boff);
            }
#pragma unroll
            for (int mi = 0; mi < 4; mi++) {
                uint32_t af[4];
                const uint32_t aoff = SWZ((uint32_t)(aRow + mi * 16) * 128 + ks * 32 + aSegOff);
                ldsm_x4(af[0], af[1], af[2], af[3], st + aoff);
#pragma unroll
                for (int nj = 0; nj < 8; nj++)
                    mma_f16(c[mi][nj], af, bf[nj][0], bf[nj][1]);
            }
        }
    }

    const int g = lane >> 2, q2 = (lane & 3) * 2;
    const int sec = colBase / 768;                 // block-uniform: 0=Q 1=K 2=V
    const float scl = (sec == 0) ? 0.18033688f : 1.0f;
#pragma unroll
    for (int mi = 0; mi < 4; mi++) {
        const int row0 = rowBase + wm * 64 + mi * 16 + g;
#pragma unroll
        for (int nj = 0; nj < 8; nj++) {
            const int col = colBase + wn * 64 + nj * 8 + q2;
            const float bx = bias[col], by = bias[col + 1];
            *(uint32_t*)(Cq + (size_t)row0 * N + col) =
                packh2((c[mi][nj][0] + bx) * scl, (c[mi][nj][1] + by) * scl);
            *(uint32_t*)(Cq + (size_t)(row0 + 8) * N + col) =
                packh2((c[mi][nj][2] + bx) * scl, (c[mi][nj][3] + by) * scl);
        }
    }
}

// ---------------------------------------------------------------------------
// GEMM 3 (proj): 128x128 tile, fp16 2-pass (y hi/lo), fp32 out.
// ---------------------------------------------------------------------------
#define P_STAGE 49152
#define P_SMEM  (3 * P_STAGE)

__device__ __forceinline__ void proj_load_chunk(
    uint32_t sb, const __half* Ahi, const __half* Alo, const __half* Bm,
    int rowBase, int colBase, int K, int kc, int stage, int tid)
{
    const uint32_t base = sb + stage * P_STAGE;
    const int k0 = kc * 64;
#pragma unroll
    for (int i = 0; i < 4; i++) {
        const int seg = tid + i * 256;
        const int r = seg >> 3, g = seg & 7;
        const uint32_t soff = SWZ(r * 128 + g * 16);
        cpa16(base + soff,         Ahi + (size_t)(rowBase + r) * K + k0 + g * 8);
        cpa16(base + 16384 + soff, Alo + (size_t)(rowBase + r) * K + k0 + g * 8);
        cpa16(base + 32768 + soff, Bm  + (size_t)(colBase + r) * K + k0 + g * 8);
    }
    cpa_commit();
}

__global__ __launch_bounds__(256, 1)
void gemm_proj_kernel(const __half* __restrict__ Ahi, const __half* __restrict__ Alo,
                      const __half* __restrict__ Bm,
                      const float* __restrict__ bias, float* __restrict__ Cm,
                      int M, int N, int K)
{
    extern __shared__ char smem[];
    const uint32_t sb = smem_u32(smem);
    const int tid = threadIdx.x, wid = tid >> 5, lane = tid & 31;
    const int wm = wid >> 2, wn = wid & 3;
    const int rowBase = blockIdx.y * 128, colBase = blockIdx.x * 128;
    const int NK = K / 64;

    float c[4][4][4];
#pragma unroll
    for (int i = 0; i < 4; i++)
#pragma unroll
        for (int j = 0; j < 4; j++)
#pragma unroll
            for (int k = 0; k < 4; k++) c[i][j][k] = 0.f;

    proj_load_chunk(sb, Ahi, Alo, Bm, rowBase, colBase, K, 0, 0, tid);
    proj_load_chunk(sb, Ahi, Alo, Bm, rowBase, colBase, K, 1, 1, tid);

    const int aRow = wm * 64 + (lane & 15);
    const uint32_t aSegOff = ((lane >> 4) & 1) * 16;
    const int bRow4 = wn * 32 + ((lane >> 4) & 1) * 8 + (lane & 7);
    const uint32_t bSegOff = ((lane >> 3) & 1) * 16;

    for (int kc = 0; kc < NK; kc++) {
        if (kc + 1 < NK) asm volatile("cp.async.wait_group 1;" ::: "memory");
        else             asm volatile("cp.async.wait_group 0;" ::: "memory");
        __syncthreads();
        if (kc + 2 < NK)
            proj_load_chunk(sb, Ahi, Alo, Bm, rowBase, colBase, K,
                            kc + 2, (kc + 2) % 3, tid);
        const uint32_t st = sb + (kc % 3) * P_STAGE;
#pragma unroll
        for (int ks = 0; ks < 4; ks++) {
            uint32_t bf[4][2];
#pragma unroll
            for (int nj = 0; nj < 4; nj += 2) {
                const uint32_t boff = SWZ((uint32_t)(bRow4 + nj * 8) * 128 + ks * 32 + bSegOff);
                ldsm_x4(bf[nj][0], bf[nj][1], bf[nj + 1][0], bf[nj + 1][1], st + 32768 + boff);
            }
#pragma unroll
            for (int mi = 0; mi < 4; mi++) {
                uint32_t ah[4], al[4];
                const uint32_t aoff = SWZ((uint32_t)(aRow + mi * 16) * 128 + ks * 32 + aSegOff);
                ldsm_x4(ah[0], ah[1], ah[2], ah[3], st + aoff);
                ldsm_x4(al[0], al[1], al[2], al[3], st + 16384 + aoff);
#pragma unroll
                for (int nj = 0; nj < 4; nj++) {
                    mma_f16(c[mi][nj], ah, bf[nj][0], bf[nj][1]);
                    mma_f16(c[mi][nj], al, bf[nj][0], bf[nj][1]);
                }
            }
        }
    }

    const int g = lane >> 2, q2 = (lane & 3) * 2;
#pragma unroll
    for (int mi = 0; mi < 4; mi++) {
        const int row0 = rowBase + wm * 64 + mi * 16 + g;
#pragma unroll
        for (int nj = 0; nj < 4; nj++) {
            const int col = colBase + wn * 32 + nj * 8 + q2;
            const float bx = bias[col], by = bias[col + 1];
            float2 v0 = make_float2(c[mi][nj][0] + bx, c[mi][nj][1] + by);
            float2 v1 = make_float2(c[mi][nj][2] + bx, c[mi][nj][3] + by);
            *(float2*)(Cm + (size_t)row0 * N + col) = v0;
            *(float2*)(Cm + (size_t)(row0 + 8) * N + col) = v1;
        }
    }
}

// ---------------------------------------------------------------------------
// Flash attention: S fp16 1-pass (Q single x K single), PV fp16 1-pass.
// Single-sync 3-stage ring, stage = K 8K | V 8K = 16K. smem: Q 16K + 48K.
// S(kt+1) interleaved with softmax(kt).
// ---------------------------------------------------------------------------
#define SM_Q  0
#define SM_ST 16384
#define A_STAGE 16384
#define A_SMEM (SM_ST + 3 * A_STAGE)

__device__ __forceinline__ void attn_load_kv(
    uint32_t sb, const __half* qkv, size_t base0, int kBase, int stage, int tid)
{
    const uint32_t st = sb + SM_ST + stage * A_STAGE;
#pragma unroll
    for (int i = 0; i < 2; i++) {
        const int seg = tid + i * 256;
        const int r = seg >> 3, gsg = seg & 7;
        const size_t goff = base0 + (size_t)(kBase + r) * QKVC_ + gsg * 8;
        const uint32_t soff = SWZ((uint32_t)r * 128 + gsg * 16);
        cpa16(st + soff,        qkv + goff + 768);    // K
        cpa16(st + 8192 + soff, qkv + goff + 1536);   // V
    }
    cpa_commit();
}

__global__ __launch_bounds__(256, 1)
void attn_mma_kernel(const __half* __restrict__ qkv,
                     __half* __restrict__ yhi, __half* __restrict__ ylo)
{
    extern __shared__ char smem[];
    const uint32_t sb = smem_u32(smem);
    const int qt = (int)gridDim.x - 1 - (int)blockIdx.x;
    const int bh = blockIdx.y;
    const int b = bh / H_, h = bh % H_;
    const int tid = threadIdx.x, wid = tid >> 5, lane = tid & 31;
    const int qBase = qt * 128;
    const size_t base0 = (size_t)b * T_ * QKVC_ + h * 64;
    const int ktMax = 2 * qt + 1;

#pragma unroll
    for (int i = 0; i < 2; i++) {
        const int seg = tid + i * 256;
        const int r = seg >> 3, gsg = seg & 7;
        const size_t goff = base0 + (size_t)(qBase + r * 2 + (gsg >= 4)) * QKVC_;
        // simple layout: 2 rows per 8-group span handled below instead
    }
    // Q tile: 128 rows x 128 bytes = 16K -> 1024 cpa16, 4 iters
#pragma unroll
    for (int i = 0; i < 4; i++) {
        const int seg = tid + i * 256;
        const int r = seg >> 3, gsg = seg & 7;
        if (gsg < 8) {
            const size_t goff = base0 + (size_t)(qBase + r) * QKVC_ + gsg * 8;
            cpa16(sb + SM_Q + SWZ((uint32_t)r * 128 + gsg * 16), qkv + goff);
        }
    }
    cpa_commit();
    attn_load_kv(sb, qkv, base0, 0,  0, tid);
    attn_load_kv(sb, qkv, base0, 64, 1, tid);
    asm volatile("cp.async.wait_group 1;" ::: "memory");
    __syncthreads();

    uint32_t qf[4][4];
    {
        const int aRow = wid * 16 + (lane & 15);
        const uint32_t aSeg = ((lane >> 4) & 1) * 16;
#pragma unroll
        for (int ks = 0; ks < 4; ks++) {
            const uint32_t aoff = SWZ((uint32_t)aRow * 128 + ks * 32 + aSeg);
            ldsm_x4(qf[ks][0], qf[ks][1], qf[ks][2], qf[ks][3], sb + SM_Q + aoff);
        }
    }

    float o[8][4];
#pragma unroll
    for (int d = 0; d < 8; d++)
#pragma unroll
        for (int k = 0; k < 4; k++) o[d][k] = 0.f;
    float m0 = -1e30f, m1 = -1e30f, l0s = 0.f, l1s = 0.f;

    const int g = lane >> 2, q2 = (lane & 3) * 2;
    const int qRowMin = qBase + wid * 16;
    const int row0 = qRowMin + g;
    const int wktMax = (qRowMin + 15) >> 6;

    const int bRow4 = ((lane >> 4) & 1) * 8 + (lane & 7);
    const uint32_t bSeg = ((lane >> 3) & 1) * 16;
    const int vRowL = lane & 15;
    const uint32_t vSeg = ((lane >> 4) & 1) * 16;

    // ---- S(0): 1-pass ----
    float sc[8][4];
    {
        const uint32_t st0 = sb + SM_ST;
#pragma unroll
        for (int nj = 0; nj < 8; nj += 2) {
#pragma unroll
            for (int k = 0; k < 4; k++) { sc[nj][k] = 0.f; sc[nj + 1][k] = 0.f; }
#pragma unroll
            for (int ks = 0; ks < 4; ks++) {
                const uint32_t boff = SWZ((uint32_t)(nj * 8 + bRow4) * 128 + ks * 32 + bSeg);
                uint32_t k0, k1, k2, k3;
                ldsm_x4(k0, k1, k2, k3, st0 + boff);
                mma_f16(sc[nj],     qf[ks], k0, k1);
                mma_f16(sc[nj + 1], qf[ks], k2, k3);
            }
        }
    }

    for (int kt = 0; kt <= ktMax; kt++) {
        const int kBase = kt * 64;
        asm volatile("cp.async.wait_group 0;" ::: "memory");
        __syncthreads();
        if (kt + 2 <= ktMax)
            attn_load_kv(sb, qkv, base0, (kt + 2) * 64, (kt + 2) % 3, tid);

        const bool doP = (kt <= wktMax);
        const bool doS = (kt + 1 <= ktMax) && (kt + 1 <= wktMax);

        if (doP) {
            const uint32_t stP = sb + SM_ST + (kt % 3) * A_STAGE;
            const uint32_t stS = sb + SM_ST + ((kt + 1) % 3) * A_STAGE;

            if (kBase + 63 > qRowMin) {
#pragma unroll
                for (int nj = 0; nj < 8; nj++) {
                    const int col = kBase + nj * 8 + q2;
                    if (col > row0)         sc[nj][0] = -1e30f;
                    if (col + 1 > row0)     sc[nj][1] = -1e30f;
                    if (col > row0 + 8)     sc[nj][2] = -1e30f;
                    if (col + 1 > row0 + 8) sc[nj][3] = -1e30f;
                }
            }

            float mx0 = -1e30f, mx1 = -1e30f;
#pragma unroll
            for (int nj = 0; nj < 8; nj++) {
                mx0 = fmaxf(mx0, fmaxf(sc[nj][0], sc[nj][1]));
                mx1 = fmaxf(mx1, fmaxf(sc[nj][2], sc[nj][3]));
            }
            mx0 = fmaxf(mx0, __shfl_xor_sync(0xffffffffu, mx0, 1));
            mx0 = fmaxf(mx0, __shfl_xor_sync(0xffffffffu, mx0, 2));
            mx1 = fmaxf(mx1, __shfl_xor_sync(0xffffffffu, mx1, 1));
            mx1 = fmaxf(mx1, __shfl_xor_sync(0xffffffffu, mx1, 2));
            const float mn0 = fmaxf(m0, mx0), mn1 = fmaxf(m1, mx1);
            const float al0 = ex2_(m0 - mn0), al1 = ex2_(m1 - mn1);
            m0 = mn0; m1 = mn1;

            float s0 = 0.f, s1 = 0.f;
            float sn[8][4];
            if (doS) {
                // ---- S(kt+1) interleaved with exp2(kt) ----
#pragma unroll
                for (int nj = 0; nj < 8; nj += 2) {
#pragma unroll
                    for (int k = 0; k < 4; k++) { sn[nj][k] = 0.f; sn[nj + 1][k] = 0.f; }
#pragma unroll
                    for (int ks = 0; ks < 4; ks++) {
                        const uint32_t boff = SWZ((uint32_t)(nj * 8 + bRow4) * 128 + ks * 32 + bSeg);
                        uint32_t k0, k1, k2, k3;
                        ldsm_x4(k0, k1, k2, k3, stS + boff);
                        mma_f16(sn[nj],     qf[ks], k0, k1);
                        mma_f16(sn[nj + 1], qf[ks], k2, k3);
                    }
#pragma unroll
                    for (int u = 0; u < 2; u++) {
                        sc[nj + u][0] = ex2_(sc[nj + u][0] - mn0);
                        sc[nj + u][1] = ex2_(sc[nj + u][1] - mn0);
                        sc[nj + u][2] = ex2_(sc[nj + u][2] - mn1);
                        sc[nj + u][3] = ex2_(sc[nj + u][3] - mn1);
                        s0 += sc[nj + u][0] + sc[nj + u][1];
                        s1 += sc[nj + u][2] + sc[nj + u][3];
                    }
                }
            } else {
#pragma unroll
                for (int nj = 0; nj < 8; nj++) {
                    sc[nj][0] = ex2_(sc[nj][0] - mn0);
                    sc[nj][1] = ex2_(sc[nj][1] - mn0);
                    sc[nj][2] = ex2_(sc[nj][2] - mn1);
                    sc[nj][3] = ex2_(sc[nj][3] - mn1);
                    s0 += sc[nj][0] + sc[nj][1];
                    s1 += sc[nj][2] + sc[nj][3];
                }
            }
            s0 += __shfl_xor_sync(0xffffffffu, s0, 1);
            s0 += __shfl_xor_sync(0xffffffffu, s0, 2);
            s1 += __shfl_xor_sync(0xffffffffu, s1, 1);
            s1 += __shfl_xor_sync(0xffffffffu, s1, 2);
            l0s = l0s * al0 + s0;
            l1s = l1s * al1 + s1;

            // ---- P fragments (single fp16) ----
            uint32_t ph[4][4];
#pragma unroll
            for (int ks = 0; ks < 4; ks++) {
                ph[ks][0] = packh2(sc[2 * ks][0],     sc[2 * ks][1]);
                ph[ks][1] = packh2(sc[2 * ks][2],     sc[2 * ks][3]);
                ph[ks][2] = packh2(sc[2 * ks + 1][0], sc[2 * ks + 1][1]);
                ph[ks][3] = packh2(sc[2 * ks + 1][2], sc[2 * ks + 1][3]);
            }

            // ---- PV(kt) 1-pass + O rescale ----
#pragma unroll
            for (int dj = 0; dj < 8; dj += 2) {
#pragma unroll
                for (int u = 0; u < 2; u++) {
                    o[dj + u][0] *= al0; o[dj + u][1] *= al0;
                    o[dj + u][2] *= al1; o[dj + u][3] *= al1;
                }
#pragma unroll
                for (int ks = 0; ks < 4; ks++) {
                    const uint32_t voff = SWZ((uint32_t)(ks * 16 + vRowL) * 128 + dj * 16 + vSeg);
                    uint32_t v0, v1, v2, v3;
                    ldsm_x4t(v0, v1, v2, v3, stP + 8192 + voff);
                    mma_f16(o[dj],     ph[ks], v0, v1);
                    mma_f16(o[dj + 1], ph[ks], v2, v3);
                }
            }

            if (doS) {
#pragma unroll
                for (int nj = 0; nj < 8; nj++)
#pragma unroll
                    for (int k = 0; k < 4; k++) sc[nj][k] = sn[nj][k];
            }
        }
    }

    const float inv0 = 1.0f / l0s, inv1 = 1.0f / l1s;
#pragma unroll
    for (int dj = 0; dj < 8; dj++) {
        uint32_t h0, l0, h1, l1;
        split2h(o[dj][0] * inv0, o[dj][1] * inv0, h0, l0);
        split2h(o[dj][2] * inv1, o[dj][3] * inv1, h1, l1);
        const size_t r0 = ((size_t)b * T_ + row0) * C_ + h * 64 + dj * 8 + q2;
        const size_t r1 = r0 + 8 * C_;
        *(uint32_t*)(yhi + r0) = h0;
        *(uint32_t*)(ylo + r0) = l0;
        *(uint32_t*)(yhi + r1) = h1;
        *(uint32_t*)(ylo + r1) = l1;
    }
}

// ---------------------------------------------------------------------------
extern "C" void kernel_launch(void* const* d_in, const int* in_sizes, int n_in,
                              void* d_out, int out_size)
{
    const float* x      = (const float*)d_in[0];
    const float* w_attn = (const float*)d_in[1];
    const float* b_attn = (const float*)d_in[2];
    const float* w_proj = (const float*)d_in[3];
    const float* b_proj = (const float*)d_in[4];
    float* out = (float*)d_out;

    __half *qkv, *xh, *yhi, *ylo, *wa, *wp;
    cudaGetSymbolAddress((void**)&qkv, g_qkv);
    cudaGetSymbolAddress((void**)&xh, g_x);
    cudaGetSymbolAddress((void**)&yhi, g_yhi);
    cudaGetSymbolAddress((void**)&ylo, g_ylo);
    cudaGetSymbolAddress((void**)&wa, g_wa);
    cudaGetSymbolAddress((void**)&wp, g_wp);

    cudaFuncSetAttribute(gemm_qkv_kernel,
                         cudaFuncAttributeMaxDynamicSharedMemorySize, W_SMEM);
    cudaFuncSetAttribute(gemm_proj_kernel,
                         cudaFuncAttributeMaxDynamicSharedMemorySize, P_SMEM);
    cudaFuncSetAttribute(attn_mma_kernel,
                         cudaFuncAttributeMaxDynamicSharedMemorySize, A_SMEM);

    // conversions
    {
        int n4 = ROWS_ * C_ / 4;
        convert_rows_h_kernel<<<(n4 + 255) / 256, 256>>>(x, xh, n4);
        dim3 bt(32, 8);
        transpose_h_kernel<<<dim3(QKVC_ / 32, C_ / 32), bt>>>(w_attn, wa, C_, QKVC_);
        transpose_h_kernel<<<dim3(C_ / 32,    C_ / 32), bt>>>(w_proj, wp, C_, C_);
    }
    // Stage 1: qkv GEMM (128x256 tiles, 1-pass fp16)
    {
        dim3 grid(QKVC_ / 256, ROWS_ / 128);
        gemm_qkv_kernel<<<grid, 256, W_SMEM>>>(xh, wa, b_attn, qkv,
                                               ROWS_, QKVC_, C_);
    }
    // Stage 2: attention -> y fp16 hi/lo
    {
        dim3 grid(T_ / 128, B_ * H_);
        attn_mma_kernel<<<grid, 256, A_SMEM>>>(qkv, yhi, ylo);
    }
    // Stage 3: out = y @ w_proj + b_proj (fp16 2-pass)
    {
        dim3 grid(C_ / 128, ROWS_ / 128);
        gemm_proj_kernel<<<grid, 256, P_SMEM>>>(yhi, ylo, wp, b_proj, out,
                                                ROWS_, C_, C_);
    }
}

// round 15
// speedup vs baseline: 3.5973x; 1.1915x over previous
#include <cuda_runtime.h>
#include <cuda_bf16.h>
#include <cuda_fp16.h>
#include <cstdint>

// ---------------------------------------------------------------------------
// CausalSelfAttention on GB300 (sm_103 family target — no 'a' features).
// fp16 mma.sync scheme:
//   gemm1 (qkv):  1-pass; 128x256 tile -> Q(scaled)/K/V fp16 single
//   attention:    64 q-rows/CTA, 128 thr, 2 CTAs/SM; S,PV 1-pass fp16
//   gemm3 (proj): 1-pass; y fp16 single x w_proj single -> fp32 out
// ---------------------------------------------------------------------------

#define B_ 4
#define T_ 2048
#define C_ 768
#define H_ 12
#define ROWS_ 8192
#define QKVC_ 2304

// ---------------- scratch ---------------------------------------------------
__device__ __align__(256) __half  g_qkv[ROWS_ * QKVC_];     // Q(scaled),K,V fp16
__device__ __align__(256) __half  g_x[ROWS_ * C_];          // x fp16
__device__ __align__(256) __half  g_y[ROWS_ * C_];          // y fp16
__device__ __align__(256) __half  g_wa[QKVC_ * C_];         // w_attn^T fp16
__device__ __align__(256) __half  g_wp[C_ * C_];            // w_proj^T fp16

// ---------------- helpers ---------------------------------------------------
__device__ __forceinline__ uint32_t smem_u32(const void* p) {
    uint32_t a;
    asm("{ .reg .u64 t; cvta.to.shared.u64 t, %1; cvt.u32.u64 %0, t; }"
        : "=r"(a) : "l"(p));
    return a;
}
#define SWZ(x) ((x) ^ (((x) >> 3) & 0x70))

__device__ __forceinline__ void cpa16(uint32_t dst, const void* src) {
    asm volatile("cp.async.cg.shared.global [%0], [%1], 16;" :: "r"(dst), "l"(src));
}
__device__ __forceinline__ void cpa_commit() { asm volatile("cp.async.commit_group;"); }

__device__ __forceinline__ void ldsm_x4(uint32_t& r0, uint32_t& r1, uint32_t& r2,
                                        uint32_t& r3, uint32_t addr) {
    asm volatile("ldmatrix.sync.aligned.m8n8.x4.shared.b16 {%0,%1,%2,%3}, [%4];"
                 : "=r"(r0), "=r"(r1), "=r"(r2), "=r"(r3) : "r"(addr));
}
__device__ __forceinline__ void ldsm_x4t(uint32_t& r0, uint32_t& r1, uint32_t& r2,
                                         uint32_t& r3, uint32_t addr) {
    asm volatile("ldmatrix.sync.aligned.m8n8.x4.trans.shared.b16 {%0,%1,%2,%3}, [%4];"
                 : "=r"(r0), "=r"(r1), "=r"(r2), "=r"(r3) : "r"(addr));
}
__device__ __forceinline__ void mma_f16(float* c, const uint32_t* a,
                                        uint32_t b0, uint32_t b1) {
    asm volatile("mma.sync.aligned.m16n8k16.row.col.f32.f16.f16.f32 "
                 "{%0,%1,%2,%3}, {%4,%5,%6,%7}, {%8,%9}, {%0,%1,%2,%3};"
                 : "+f"(c[0]), "+f"(c[1]), "+f"(c[2]), "+f"(c[3])
                 : "r"(a[0]), "r"(a[1]), "r"(a[2]), "r"(a[3]), "r"(b0), "r"(b1));
}
__device__ __forceinline__ float ex2_(float x) {
    float r; asm("ex2.approx.f32 %0, %1;" : "=f"(r) : "f"(x)); return r;
}
__device__ __forceinline__ uint32_t packh2(float a, float b) {
    __half2 hh = __floats2half2_rn(a, b);
    return *(uint32_t*)&hh;
}

// ---------------------------------------------------------------------------
// Conversion kernels
// ---------------------------------------------------------------------------
__global__ void convert_rows_h_kernel(const float* __restrict__ in,
                                      __half* __restrict__ outh, int n4)
{
    int i = blockIdx.x * blockDim.x + threadIdx.x;
    if (i >= n4) return;
    float4 v = ((const float4*)in)[i];
    uint32_t* hp = (uint32_t*)(outh + 4 * (size_t)i);
    hp[0] = packh2(v.x, v.y);
    hp[1] = packh2(v.z, v.w);
}

__global__ void transpose_h_kernel(const float* __restrict__ w,
                                   __half* __restrict__ wT, int K, int N)
{
    __shared__ float t[32][33];
    const int n0 = blockIdx.x * 32, k0 = blockIdx.y * 32;
    const int tx = threadIdx.x, ty = threadIdx.y;
#pragma unroll
    for (int j = 0; j < 4; j++)
        t[ty + j * 8][tx] = w[(size_t)(k0 + ty + j * 8) * N + n0 + tx];
    __syncthreads();
#pragma unroll
    for (int j = 0; j < 4; j++) {
        const int n = ty + j * 8;
        wT[(size_t)(n0 + n) * K + k0 + tx] = __float2half(t[tx][n]);
    }
}

// ---------------------------------------------------------------------------
// GEMM 1 (qkv): 128x256 CTA tile, 8 warps 64x64, fp16 1-pass.
// Epilogue: fp16 single out; Q columns pre-scaled by log2e/8.
// ---------------------------------------------------------------------------
#define W_STAGE 49152          // A 16K | B 32K
#define W_SMEM  (3 * W_STAGE)

__device__ __forceinline__ void qkv_load_chunk(
    uint32_t sb, const __half* Am, const __half* Bm,
    int rowBase, int colBase, int K, int kc, int stage, int tid)
{
    const uint32_t base = sb + stage * W_STAGE;
    const int k0 = kc * 64;
#pragma unroll
    for (int i = 0; i < 4; i++) {
        const int seg = tid + i * 256;
        const int r = seg >> 3, g = seg & 7;
        cpa16(base + SWZ(r * 128 + g * 16),
              Am + (size_t)(rowBase + r) * K + k0 + g * 8);
    }
#pragma unroll
    for (int i = 0; i < 8; i++) {
        const int seg = tid + i * 256;
        const int r = seg >> 3, g = seg & 7;
        cpa16(base + 16384 + SWZ(r * 128 + g * 16),
              Bm + (size_t)(colBase + r) * K + k0 + g * 8);
    }
    cpa_commit();
}

__global__ __launch_bounds__(256, 1)
void gemm_qkv_kernel(const __half* __restrict__ Am, const __half* __restrict__ Bm,
                     const float* __restrict__ bias, __half* __restrict__ Cq,
                     int M, int N, int K)
{
    extern __shared__ char smem[];
    const uint32_t sb = smem_u32(smem);
    const int tid = threadIdx.x, wid = tid >> 5, lane = tid & 31;
    const int wm = wid >> 2, wn = wid & 3;
    const int rowBase = blockIdx.y * 128, colBase = blockIdx.x * 256;
    const int NK = K / 64;

    float c[4][8][4];
#pragma unroll
    for (int i = 0; i < 4; i++)
#pragma unroll
        for (int j = 0; j < 8; j++)
#pragma unroll
            for (int k = 0; k < 4; k++) c[i][j][k] = 0.f;

    qkv_load_chunk(sb, Am, Bm, rowBase, colBase, K, 0, 0, tid);
    qkv_load_chunk(sb, Am, Bm, rowBase, colBase, K, 1, 1, tid);

    const int aRow = wm * 64 + (lane & 15);
    const uint32_t aSegOff = ((lane >> 4) & 1) * 16;
    const int bRow4 = wn * 64 + ((lane >> 4) & 1) * 8 + (lane & 7);
    const uint32_t bSegOff = ((lane >> 3) & 1) * 16;

    for (int kc = 0; kc < NK; kc++) {
        if (kc + 1 < NK) asm volatile("cp.async.wait_group 1;" ::: "memory");
        else             asm volatile("cp.async.wait_group 0;" ::: "memory");
        __syncthreads();
        if (kc + 2 < NK)
            qkv_load_chunk(sb, Am, Bm, rowBase, colBase, K,
                           kc + 2, (kc + 2) % 3, tid);
        const uint32_t st = sb + (kc % 3) * W_STAGE;
#pragma unroll
        for (int ks = 0; ks < 4; ks++) {
            uint32_t bf[8][2];
#pragma unroll
            for (int nj = 0; nj < 8; nj += 2) {
                const uint32_t boff = SWZ((uint32_t)(bRow4 + nj * 8) * 128 + ks * 32 + bSegOff);
                ldsm_x4(bf[nj][0], bf[nj][1], bf[nj + 1][0], bf[nj + 1][1], st + 16384 + boff);
            }
#pragma unroll
            for (int mi = 0; mi < 4; mi++) {
                uint32_t af[4];
                const uint32_t aoff = SWZ((uint32_t)(aRow + mi * 16) * 128 + ks * 32 + aSegOff);
                ldsm_x4(af[0], af[1], af[2], af[3], st + aoff);
#pragma unroll
                for (int nj = 0; nj < 8; nj++)
                    mma_f16(c[mi][nj], af, bf[nj][0], bf[nj][1]);
            }
        }
    }

    const int g = lane >> 2, q2 = (lane & 3) * 2;
    const int sec = colBase / 768;
    const float scl = (sec == 0) ? 0.18033688f : 1.0f;
#pragma unroll
    for (int mi = 0; mi < 4; mi++) {
        const int row0 = rowBase + wm * 64 + mi * 16 + g;
#pragma unroll
        for (int nj = 0; nj < 8; nj++) {
            const int col = colBase + wn * 64 + nj * 8 + q2;
            const float bx = bias[col], by = bias[col + 1];
            *(uint32_t*)(Cq + (size_t)row0 * N + col) =
                packh2((c[mi][nj][0] + bx) * scl, (c[mi][nj][1] + by) * scl);
            *(uint32_t*)(Cq + (size_t)(row0 + 8) * N + col) =
                packh2((c[mi][nj][2] + bx) * scl, (c[mi][nj][3] + by) * scl);
        }
    }
}

// ---------------------------------------------------------------------------
// GEMM 3 (proj): 128x128 tile, fp16 1-pass (y single), fp32 out.
// ---------------------------------------------------------------------------
#define P_STAGE 32768          // A 16K | B 16K
#define P_SMEM  (3 * P_STAGE)

__device__ __forceinline__ void proj_load_chunk(
    uint32_t sb, const __half* Am, const __half* Bm,
    int rowBase, int colBase, int K, int kc, int stage, int tid)
{
    const uint32_t base = sb + stage * P_STAGE;
    const int k0 = kc * 64;
#pragma unroll
    for (int i = 0; i < 4; i++) {
        const int seg = tid + i * 256;
        const int r = seg >> 3, g = seg & 7;
        const uint32_t soff = SWZ(r * 128 + g * 16);
        cpa16(base + soff,         Am + (size_t)(rowBase + r) * K + k0 + g * 8);
        cpa16(base + 16384 + soff, Bm + (size_t)(colBase + r) * K + k0 + g * 8);
    }
    cpa_commit();
}

__global__ __launch_bounds__(256, 1)
void gemm_proj_kernel(const __half* __restrict__ Am, const __half* __restrict__ Bm,
                      const float* __restrict__ bias, float* __restrict__ Cm,
                      int M, int N, int K)
{
    extern __shared__ char smem[];
    const uint32_t sb = smem_u32(smem);
    const int tid = threadIdx.x, wid = tid >> 5, lane = tid & 31;
    const int wm = wid >> 2, wn = wid & 3;
    const int rowBase = blockIdx.y * 128, colBase = blockIdx.x * 128;
    const int NK = K / 64;

    float c[4][4][4];
#pragma unroll
    for (int i = 0; i < 4; i++)
#pragma unroll
        for (int j = 0; j < 4; j++)
#pragma unroll
            for (int k = 0; k < 4; k++) c[i][j][k] = 0.f;

    proj_load_chunk(sb, Am, Bm, rowBase, colBase, K, 0, 0, tid);
    proj_load_chunk(sb, Am, Bm, rowBase, colBase, K, 1, 1, tid);

    const int aRow = wm * 64 + (lane & 15);
    const uint32_t aSegOff = ((lane >> 4) & 1) * 16;
    const int bRow4 = wn * 32 + ((lane >> 4) & 1) * 8 + (lane & 7);
    const uint32_t bSegOff = ((lane >> 3) & 1) * 16;

    for (int kc = 0; kc < NK; kc++) {
        if (kc + 1 < NK) asm volatile("cp.async.wait_group 1;" ::: "memory");
        else             asm volatile("cp.async.wait_group 0;" ::: "memory");
        __syncthreads();
        if (kc + 2 < NK)
            proj_load_chunk(sb, Am, Bm, rowBase, colBase, K,
                            kc + 2, (kc + 2) % 3, tid);
        const uint32_t st = sb + (kc % 3) * P_STAGE;
#pragma unroll
        for (int ks = 0; ks < 4; ks++) {
            uint32_t bf[4][2];
#pragma unroll
            for (int nj = 0; nj < 4; nj += 2) {
                const uint32_t boff = SWZ((uint32_t)(bRow4 + nj * 8) * 128 + ks * 32 + bSegOff);
                ldsm_x4(bf[nj][0], bf[nj][1], bf[nj + 1][0], bf[nj + 1][1], st + 16384 + boff);
            }
#pragma unroll
            for (int mi = 0; mi < 4; mi++) {
                uint32_t af[4];
                const uint32_t aoff = SWZ((uint32_t)(aRow + mi * 16) * 128 + ks * 32 + aSegOff);
                ldsm_x4(af[0], af[1], af[2], af[3], st + aoff);
#pragma unroll
                for (int nj = 0; nj < 4; nj++)
                    mma_f16(c[mi][nj], af, bf[nj][0], bf[nj][1]);
            }
        }
    }

    const int g = lane >> 2, q2 = (lane & 3) * 2;
#pragma unroll
    for (int mi = 0; mi < 4; mi++) {
        const int row0 = rowBase + wm * 64 + mi * 16 + g;
#pragma unroll
        for (int nj = 0; nj < 4; nj++) {
            const int col = colBase + wn * 32 + nj * 8 + q2;
            const float bx = bias[col], by = bias[col + 1];
            float2 v0 = make_float2(c[mi][nj][0] + bx, c[mi][nj][1] + by);
            float2 v1 = make_float2(c[mi][nj][2] + bx, c[mi][nj][3] + by);
            *(float2*)(Cm + (size_t)row0 * N + col) = v0;
            *(float2*)(Cm + (size_t)(row0 + 8) * N + col) = v1;
        }
    }
}

// ---------------------------------------------------------------------------
// Flash attention: 64 q-rows/CTA, 128 threads (4 warps x 16 rows),
// 2 CTAs/SM co-residency. S fp16 1-pass, PV fp16 1-pass.
// Single-sync 3-stage ring, stage = K 8K | V 8K = 16K. smem: Q 8K + 48K = 56K.
// S(kt+1) interleaved with softmax(kt).
// ---------------------------------------------------------------------------
#define SM_Q  0
#define SM_ST 8192
#define A_STAGE 16384
#define A_SMEM (SM_ST + 3 * A_STAGE)

__device__ __forceinline__ void attn_load_kv(
    uint32_t sb, const __half* qkv, size_t base0, int kBase, int stage, int tid)
{
    const uint32_t st = sb + SM_ST + stage * A_STAGE;
#pragma unroll
    for (int i = 0; i < 4; i++) {
        const int seg = tid + i * 128;
        const int r = seg >> 3, gsg = seg & 7;
        const size_t goff = base0 + (size_t)(kBase + r) * QKVC_ + gsg * 8;
        const uint32_t soff = SWZ((uint32_t)r * 128 + gsg * 16);
        cpa16(st + soff,        qkv + goff + 768);    // K
        cpa16(st + 8192 + soff, qkv + goff + 1536);   // V
    }
    cpa_commit();
}

__global__ __launch_bounds__(128, 2)
void attn_mma_kernel(const __half* __restrict__ qkv, __half* __restrict__ y)
{
    extern __shared__ char smem[];
    const uint32_t sb = smem_u32(smem);
    const int qt = (int)gridDim.x - 1 - (int)blockIdx.x;   // longest first
    const int bh = blockIdx.y;
    const int b = bh / H_, h = bh % H_;
    const int tid = threadIdx.x, wid = tid >> 5, lane = tid & 31;
    const int qBase = qt * 64;
    const size_t base0 = (size_t)b * T_ * QKVC_ + h * 64;
    const int ktMax = qt;

    // ---- prologue: Q (g0), KV0 (g1), KV1 (g2) ----
#pragma unroll
    for (int i = 0; i < 4; i++) {
        const int seg = tid + i * 128;
        const int r = seg >> 3, gsg = seg & 7;
        const size_t goff = base0 + (size_t)(qBase + r) * QKVC_ + gsg * 8;
        cpa16(sb + SM_Q + SWZ((uint32_t)r * 128 + gsg * 16), qkv + goff);
    }
    cpa_commit();
    attn_load_kv(sb, qkv, base0, 0, 0, tid);
    attn_load_kv(sb, qkv, base0, (ktMax >= 1) ? 64 : 0, 1, tid);
    asm volatile("cp.async.wait_group 1;" ::: "memory");
    __syncthreads();

    // ---- Q fragments ----
    uint32_t qf[4][4];
    {
        const int aRow = wid * 16 + (lane & 15);
        const uint32_t aSeg = ((lane >> 4) & 1) * 16;
#pragma unroll
        for (int ks = 0; ks < 4; ks++) {
            const uint32_t aoff = SWZ((uint32_t)aRow * 128 + ks * 32 + aSeg);
            ldsm_x4(qf[ks][0], qf[ks][1], qf[ks][2], qf[ks][3], sb + SM_Q + aoff);
        }
    }

    float o[8][4];
#pragma unroll
    for (int d = 0; d < 8; d++)
#pragma unroll
        for (int k = 0; k < 4; k++) o[d][k] = 0.f;
    float m0 = -1e30f, m1 = -1e30f, l0s = 0.f, l1s = 0.f;

    const int g = lane >> 2, q2 = (lane & 3) * 2;
    const int qRowMin = qBase + wid * 16;
    const int row0 = qRowMin + g;

    const int bRow4 = ((lane >> 4) & 1) * 8 + (lane & 7);
    const uint32_t bSeg = ((lane >> 3) & 1) * 16;
    const int vRowL = lane & 15;
    const uint32_t vSeg = ((lane >> 4) & 1) * 16;

    // ---- S(0) ----
    float sc[8][4];
    {
        const uint32_t st0 = sb + SM_ST;
#pragma unroll
        for (int nj = 0; nj < 8; nj += 2) {
#pragma unroll
            for (int k = 0; k < 4; k++) { sc[nj][k] = 0.f; sc[nj + 1][k] = 0.f; }
#pragma unroll
            for (int ks = 0; ks < 4; ks++) {
                const uint32_t boff = SWZ((uint32_t)(nj * 8 + bRow4) * 128 + ks * 32 + bSeg);
                uint32_t k0, k1, k2, k3;
                ldsm_x4(k0, k1, k2, k3, st0 + boff);
                mma_f16(sc[nj],     qf[ks], k0, k1);
                mma_f16(sc[nj + 1], qf[ks], k2, k3);
            }
        }
    }

    for (int kt = 0; kt <= ktMax; kt++) {
        const int kBase = kt * 64;
        asm volatile("cp.async.wait_group 0;" ::: "memory");
        __syncthreads();
        if (kt + 2 <= ktMax)
            attn_load_kv(sb, qkv, base0, (kt + 2) * 64, (kt + 2) % 3, tid);

        const bool doS = (kt + 1 <= ktMax);
        const uint32_t stP = sb + SM_ST + (kt % 3) * A_STAGE;
        const uint32_t stS = sb + SM_ST + ((kt + 1) % 3) * A_STAGE;

        // ---- causal mask (diagonal tile only: kt == qt) ----
        if (kt == ktMax) {
#pragma unroll
            for (int nj = 0; nj < 8; nj++) {
                const int col = kBase + nj * 8 + q2;
                if (col > row0)         sc[nj][0] = -1e30f;
                if (col + 1 > row0)     sc[nj][1] = -1e30f;
                if (col > row0 + 8)     sc[nj][2] = -1e30f;
                if (col + 1 > row0 + 8) sc[nj][3] = -1e30f;
            }
        }

        // ---- online softmax (base 2) ----
        float mx0 = -1e30f, mx1 = -1e30f;
#pragma unroll
        for (int nj = 0; nj < 8; nj++) {
            mx0 = fmaxf(mx0, fmaxf(sc[nj][0], sc[nj][1]));
            mx1 = fmaxf(mx1, fmaxf(sc[nj][2], sc[nj][3]));
        }
        mx0 = fmaxf(mx0, __shfl_xor_sync(0xffffffffu, mx0, 1));
        mx0 = fmaxf(mx0, __shfl_xor_sync(0xffffffffu, mx0, 2));
        mx1 = fmaxf(mx1, __shfl_xor_sync(0xffffffffu, mx1, 1));
        mx1 = fmaxf(mx1, __shfl_xor_sync(0xffffffffu, mx1, 2));
        const float mn0 = fmaxf(m0, mx0), mn1 = fmaxf(m1, mx1);
        const float al0 = ex2_(m0 - mn0), al1 = ex2_(m1 - mn1);
        m0 = mn0; m1 = mn1;

        float s0 = 0.f, s1 = 0.f;
        float sn[8][4];
        if (doS) {
            // ---- S(kt+1) interleaved with exp2(kt) ----
#pragma unroll
            for (int nj = 0; nj < 8; nj += 2) {
#pragma unroll
                for (int k = 0; k < 4; k++) { sn[nj][k] = 0.f; sn[nj + 1][k] = 0.f; }
#pragma unroll
                for (int ks = 0; ks < 4; ks++) {
                    const uint32_t boff = SWZ((uint32_t)(nj * 8 + bRow4) * 128 + ks * 32 + bSeg);
                    uint32_t k0, k1, k2, k3;
                    ldsm_x4(k0, k1, k2, k3, stS + boff);
                    mma_f16(sn[nj],     qf[ks], k0, k1);
                    mma_f16(sn[nj + 1], qf[ks], k2, k3);
                }
#pragma unroll
                for (int u = 0; u < 2; u++) {
                    sc[nj + u][0] = ex2_(sc[nj + u][0] - mn0);
                    sc[nj + u][1] = ex2_(sc[nj + u][1] - mn0);
                    sc[nj + u][2] = ex2_(sc[nj + u][2] - mn1);
                    sc[nj + u][3] = ex2_(sc[nj + u][3] - mn1);
                    s0 += sc[nj + u][0] + sc[nj + u][1];
                    s1 += sc[nj + u][2] + sc[nj + u][3];
                }
            }
        } else {
#pragma unroll
            for (int nj = 0; nj < 8; nj++) {
                sc[nj][0] = ex2_(sc[nj][0] - mn0);
                sc[nj][1] = ex2_(sc[nj][1] - mn0);
                sc[nj][2] = ex2_(sc[nj][2] - mn1);
                sc[nj][3] = ex2_(sc[nj][3] - mn1);
                s0 += sc[nj][0] + sc[nj][1];
                s1 += sc[nj][2] + sc[nj][3];
            }
        }
        s0 += __shfl_xor_sync(0xffffffffu, s0, 1);
        s0 += __shfl_xor_sync(0xffffffffu, s0, 2);
        s1 += __shfl_xor_sync(0xffffffffu, s1, 1);
        s1 += __shfl_xor_sync(0xffffffffu, s1, 2);
        l0s = l0s * al0 + s0;
        l1s = l1s * al1 + s1;

        // ---- P fragments (single fp16) ----
        uint32_t ph[4][4];
#pragma unroll
        for (int ks = 0; ks < 4; ks++) {
            ph[ks][0] = packh2(sc[2 * ks][0],     sc[2 * ks][1]);
            ph[ks][1] = packh2(sc[2 * ks][2],     sc[2 * ks][3]);
            ph[ks][2] = packh2(sc[2 * ks + 1][0], sc[2 * ks + 1][1]);
            ph[ks][3] = packh2(sc[2 * ks + 1][2], sc[2 * ks + 1][3]);
        }

        // ---- PV(kt) 1-pass + O rescale ----
#pragma unroll
        for (int dj = 0; dj < 8; dj += 2) {
#pragma unroll
            for (int u = 0; u < 2; u++) {
                o[dj + u][0] *= al0; o[dj + u][1] *= al0;
                o[dj + u][2] *= al1; o[dj + u][3] *= al1;
            }
#pragma unroll
            for (int ks = 0; ks < 4; ks++) {
                const uint32_t voff = SWZ((uint32_t)(ks * 16 + vRowL) * 128 + dj * 16 + vSeg);
                uint32_t v0, v1, v2, v3;
                ldsm_x4t(v0, v1, v2, v3, stP + 8192 + voff);
                mma_f16(o[dj],     ph[ks], v0, v1);
                mma_f16(o[dj + 1], ph[ks], v2, v3);
            }
        }

        if (doS) {
#pragma unroll
            for (int nj = 0; nj < 8; nj++)
#pragma unroll
                for (int k = 0; k < 4; k++) sc[nj][k] = sn[nj][k];
        }
    }

    // ---- epilogue: O/l -> fp16 single for proj GEMM ----
    const float inv0 = 1.0f / l0s, inv1 = 1.0f / l1s;
#pragma unroll
    for (int dj = 0; dj < 8; dj++) {
        const size_t r0 = ((size_t)b * T_ + row0) * C_ + h * 64 + dj * 8 + q2;
        const size_t r1 = r0 + 8 * C_;
        *(uint32_t*)(y + r0) = packh2(o[dj][0] * inv0, o[dj][1] * inv0);
        *(uint32_t*)(y + r1) = packh2(o[dj][2] * inv1, o[dj][3] * inv1);
    }
}

// ---------------------------------------------------------------------------
extern "C" void kernel_launch(void* const* d_in, const int* in_sizes, int n_in,
                              void* d_out, int out_size)
{
    const float* x      = (const float*)d_in[0];
    const float* w_attn = (const float*)d_in[1];
    const float* b_attn = (const float*)d_in[2];
    const float* w_proj = (const float*)d_in[3];
    const float* b_proj = (const float*)d_in[4];
    float* out = (float*)d_out;

    __half *qkv, *xh, *yh, *wa, *wp;
    cudaGetSymbolAddress((void**)&qkv, g_qkv);
    cudaGetSymbolAddress((void**)&xh, g_x);
    cudaGetSymbolAddress((void**)&yh, g_y);
    cudaGetSymbolAddress((void**)&wa, g_wa);
    cudaGetSymbolAddress((void**)&wp, g_wp);

    cudaFuncSetAttribute(gemm_qkv_kernel,
                         cudaFuncAttributeMaxDynamicSharedMemorySize, W_SMEM);
    cudaFuncSetAttribute(gemm_proj_kernel,
                         cudaFuncAttributeMaxDynamicSharedMemorySize, P_SMEM);
    cudaFuncSetAttribute(attn_mma_kernel,
                         cudaFuncAttributeMaxDynamicSharedMemorySize, A_SMEM);

    // conversions
    {
        int n4 = ROWS_ * C_ / 4;
        convert_rows_h_kernel<<<(n4 + 255) / 256, 256>>>(x, xh, n4);
        dim3 bt(32, 8);
        transpose_h_kernel<<<dim3(QKVC_ / 32, C_ / 32), bt>>>(w_attn, wa, C_, QKVC_);
        transpose_h_kernel<<<dim3(C_ / 32,    C_ / 32), bt>>>(w_proj, wp, C_, C_);
    }
    // Stage 1: qkv GEMM (1-pass fp16)
    {
        dim3 grid(QKVC_ / 256, ROWS_ / 128);
        gemm_qkv_kernel<<<grid, 256, W_SMEM>>>(xh, wa, b_attn, qkv,
                                               ROWS_, QKVC_, C_);
    }
    // Stage 2: attention (64-row CTAs, 2/SM) -> y fp16
    {
        dim3 grid(T_ / 64, B_ * H_);
        attn_mma_kernel<<<grid, 128, A_SMEM>>>(qkv, yh);
    }
    // Stage 3: out = y @ w_proj + b_proj (1-pass fp16)
    {
        dim3 grid(C_ / 128, ROWS_ / 128);
        gemm_proj_kernel<<<grid, 256, P_SMEM>>>(yh, wp, b_proj, out,
                                                ROWS_, C_, C_);
    }
}